// round 7
// baseline (speedup 1.0000x reference)
#include <cuda_runtime.h>
#include <cstdint>
#include <math.h>

// Problem constants
#define DMODEL 1024
#define TLEN   2048
#define BATCH  4
#define NHEAD  16
#define HDIM   64
#define MTOT   (BATCH*TLEN)      // 8192
#define KBLKS  (DMODEL/8)        // 128

// Scratch (static device globals; allocation-free rules)
__device__ float g_q [BATCH*NHEAD*TLEN*HDIM];  // [B,H,T,Hd], tf32-rounded, row-major
__device__ float g_k [BATCH*NHEAD*TLEN*HDIM];
__device__ float g_v [BATCH*NHEAD*TLEN*HDIM];
__device__ float g_ao[MTOT*DMODEL];            // A-fragment order, tf32-rounded
__device__ float g_xr  [MTOT*DMODEL];          // A-fragment order, tf32-rounded x
__device__ float g_wqkv[DMODEL*3*DMODEL];      // B-pair order, tf32-rounded
__device__ float g_wout[DMODEL*DMODEL];        // B-pair order, tf32-rounded

// A-fragment order: element (m,k) ->
//   f4 = (m>>4)*4096 + (k>>3)*32 + (m&7)*4 + (k&3);  slot = ((m>>3)&1) + 2*((k>>2)&1)
//   float index = f4*4 + slot
// B-pair order: element (k,n) ->
//   float index = (((n>>3)*128 + (k>>3))*32 + (n&7)*4 + (k&3))*2 + ((k>>2)&1)

// ---------------------------------------------------------------------------
// Helpers
// ---------------------------------------------------------------------------
__device__ __forceinline__ uint32_t smem_u32(const void* p) {
    uint32_t a;
    asm("{ .reg .u64 t; cvta.to.shared.u64 t, %1; cvt.u32.u64 %0, t; }"
        : "=r"(a) : "l"(p));
    return a;
}

__device__ __forceinline__ float to_tf32(float x) {
    float r;
    asm("cvt.rna.tf32.f32 %0, %1;" : "=f"(r) : "f"(x));
    return r;
}

__device__ __forceinline__ void cp16(uint32_t dst, const void* src) {
    asm volatile("cp.async.cg.shared.global [%0], [%1], 16;"
                 :: "r"(dst), "l"(src) : "memory");
}
#define CP_COMMIT() asm volatile("cp.async.commit_group;" ::: "memory")
#define CP_WAIT1()  asm volatile("cp.async.wait_group 1;" ::: "memory")
#define CP_WAIT0()  asm volatile("cp.async.wait_group 0;" ::: "memory")

// m16n8k8 row.col tf32 MMA, fp32 accumulate
__device__ __forceinline__ void mma_tf32(float* c, const float* a, const float* b) {
    const uint32_t* A = reinterpret_cast<const uint32_t*>(a);
    const uint32_t* B = reinterpret_cast<const uint32_t*>(b);
    asm volatile(
        "mma.sync.aligned.m16n8k8.row.col.f32.tf32.tf32.f32 "
        "{%0,%1,%2,%3}, {%4,%5,%6,%7}, {%8,%9}, {%0,%1,%2,%3};"
        : "+f"(c[0]), "+f"(c[1]), "+f"(c[2]), "+f"(c[3])
        : "r"(A[0]), "r"(A[1]), "r"(A[2]), "r"(A[3]), "r"(B[0]), "r"(B[1]));
}

// ---------------------------------------------------------------------------
// Prepass: x (row-major [M,1024]) -> A-fragment order, tf32-rounded.
// ---------------------------------------------------------------------------
__global__ __launch_bounds__(256) void perm_a(const float4* __restrict__ src,
                                              float4* __restrict__ dst) {
    int t = blockIdx.x * 256 + threadIdx.x;       // (M/16)*128*8 threads
    int g = t & 7, Kblk = (t >> 3) & 127, Mtile = t >> 10;
    int m0 = Mtile * 16 + g;
    float4 r00 = src[m0 * 256 + Kblk * 2];
    float4 r01 = src[m0 * 256 + Kblk * 2 + 1];
    float4 r10 = src[(m0 + 8) * 256 + Kblk * 2];
    float4 r11 = src[(m0 + 8) * 256 + Kblk * 2 + 1];
    float a0[4] = {r00.x, r00.y, r00.z, r00.w};
    float a1[4] = {r10.x, r10.y, r10.z, r10.w};
    float a2[4] = {r01.x, r01.y, r01.z, r01.w};
    float a3[4] = {r11.x, r11.y, r11.z, r11.w};
    int base = Mtile * 4096 + Kblk * 32 + g * 4;
#pragma unroll
    for (int tig = 0; tig < 4; tig++) {
        float4 o;
        o.x = to_tf32(a0[tig]); o.y = to_tf32(a1[tig]);
        o.z = to_tf32(a2[tig]); o.w = to_tf32(a3[tig]);
        dst[base + tig] = o;
    }
}

// ---------------------------------------------------------------------------
// Prepass: W (row-major [1024,N]) -> B-pair order, tf32-rounded.
// ---------------------------------------------------------------------------
__global__ __launch_bounds__(256) void perm_b(const float4* __restrict__ src,
                                              float4* __restrict__ dst, int N) {
    int t = blockIdx.x * 256 + threadIdx.x;       // (N/8)*128 threads
    int Kblk = t & 127, Ntile = t >> 7;
    float w[8][8];
#pragma unroll
    for (int kk = 0; kk < 8; kk++) {
        int k = Kblk * 8 + kk;
        float4 wa = src[(size_t)k * (N / 4) + Ntile * 2];
        float4 wb = src[(size_t)k * (N / 4) + Ntile * 2 + 1];
        w[kk][0] = wa.x; w[kk][1] = wa.y; w[kk][2] = wa.z; w[kk][3] = wa.w;
        w[kk][4] = wb.x; w[kk][5] = wb.y; w[kk][6] = wb.z; w[kk][7] = wb.w;
    }
    int base = (Ntile * 128 + Kblk) * 16;
#pragma unroll
    for (int f = 0; f < 16; f++) {
        float o[4];
#pragma unroll
        for (int e = 0; e < 4; e++) {
            int l = f * 4 + e;
            int gb = l >> 3, tig = (l >> 1) & 3, jb = l & 1;
            o[e] = to_tf32(w[tig + 4 * jb][gb]);
        }
        dst[base + f] = make_float4(o[0], o[1], o[2], o[3]);
    }
}

// ---------------------------------------------------------------------------
// Tensor-core GEMM on fragment-order operands. CTA 128x128, BK=32 (4 Kblks),
// 8 warps 2(M)x4(N). Inner loop: 4 LDS.128 + 4 LDS.64 per 16 MMAs.
// ---------------------------------------------------------------------------
#define STAGE_BYTES 32768          // 16KB A + 16KB B
#define GEMM_SMEM   (2 * STAGE_BYTES)

template<int MODE>
__global__ __launch_bounds__(256) void gemm_mma(const float* __restrict__ bias,
                                                float* __restrict__ out) {
    extern __shared__ char smem[];
    const uint32_t sb = smem_u32(smem);
    const int tid  = threadIdx.x;
    const int lane = tid & 31;
    const int warp = tid >> 5;
    const int mw = warp & 1;
    const int nw = warp >> 1;
    const int g   = lane >> 2;
    const int tig = lane & 3;
    const int brow = blockIdx.y * 128;
    const int bcol = blockIdx.x * 128;
    const int Mtile0 = blockIdx.y * 8;
    const int Ntile0 = blockIdx.x * 16;

    const float4* __restrict__ A4 = (const float4*)(MODE ? g_ao : g_xr);
    const float4* __restrict__ B4 = (const float4*)(MODE ? g_wout : g_wqkv);

    float acc[4][4][4];
#pragma unroll
    for (int i = 0; i < 4; i++)
#pragma unroll
        for (int j = 0; j < 4; j++)
#pragma unroll
            for (int q = 0; q < 4; q++) acc[i][j][q] = 0.f;

    auto issue = [&](int ic, int s) {
        const int Kb0 = ic * 4;
        const uint32_t As = sb + (uint32_t)s * STAGE_BYTES;
        const uint32_t Bs = As + 16384u;
#pragma unroll
        for (int r = 0; r < 4; r++) {
            int idx = tid + r * 256;
            int ml = idx >> 7, kl = (idx >> 5) & 3, l = idx & 31;
            cp16(As + (uint32_t)idx * 16,
                 &A4[(size_t)(Mtile0 + ml) * 4096 + (Kb0 + kl) * 32 + l]);
        }
#pragma unroll
        for (int r = 0; r < 4; r++) {
            int idx = tid + r * 256;
            int nl = idx >> 6, kl = (idx >> 4) & 3, l = idx & 15;
            cp16(Bs + (uint32_t)idx * 16,
                 &B4[(size_t)(Ntile0 + nl) * 2048 + (Kb0 + kl) * 16 + l]);
        }
    };

    issue(0, 0);
    CP_COMMIT();

    for (int ic = 0; ic < 32; ic++) {
        const int s = ic & 1;
        if (ic + 1 < 32) {
            issue(ic + 1, s ^ 1);
            CP_COMMIT();
            CP_WAIT1();
        } else {
            CP_WAIT0();
        }
        __syncthreads();

        const float4* As4 = (const float4*)(smem + (size_t)s * STAGE_BYTES);
        const float2* Bs2 = (const float2*)(smem + (size_t)s * STAGE_BYTES + 16384);

#pragma unroll
        for (int ks = 0; ks < 4; ks++) {
            float4 af[4];
            float2 bf[4];
#pragma unroll
            for (int mt = 0; mt < 4; mt++)
                af[mt] = As4[(mw * 4 + mt) * 128 + ks * 32 + g * 4 + tig];
#pragma unroll
            for (int nt = 0; nt < 4; nt++)
                bf[nt] = Bs2[((nw * 4 + nt) * 4 + ks) * 32 + g * 4 + tig];
#pragma unroll
            for (int mt = 0; mt < 4; mt++)
#pragma unroll
                for (int nt = 0; nt < 4; nt++)
                    mma_tf32(acc[mt][nt], (const float*)&af[mt], (const float*)&bf[nt]);
        }
        __syncthreads();
    }

#pragma unroll
    for (int mt = 0; mt < 4; mt++) {
#pragma unroll
        for (int half = 0; half < 2; half++) {
            const int m = brow + mw * 64 + mt * 16 + g + half * 8;
            const int b = m >> 11, t = m & 2047;
#pragma unroll
            for (int nt = 0; nt < 4; nt++) {
                const int col = bcol + nw * 32 + nt * 8 + 2 * tig;
                float2 o;
                o.x = acc[mt][nt][half * 2 + 0] + bias[col];
                o.y = acc[mt][nt][half * 2 + 1] + bias[col + 1];
                if (MODE == 0) {
                    o.x = to_tf32(o.x); o.y = to_tf32(o.y);
                    const int seg = col >> 10;
                    const int dc  = col & 1023;
                    const int h = dc >> 6, hd = dc & 63;
                    float* dst = (seg == 0) ? g_q : (seg == 1 ? g_k : g_v);
                    *(float2*)&dst[((size_t)((b * NHEAD + h) * TLEN + t)) * HDIM + hd] = o;
                } else {
                    *(float2*)&out[(size_t)m * DMODEL + col] = o;
                }
            }
        }
    }
}

// ---------------------------------------------------------------------------
// Flash attention, causal, tensor-core, wide fragment loads.
// ---------------------------------------------------------------------------
#define QS_OFF 0
#define KS_OFF (128*68)                 // Qs: [128][68]
#define VS_OFF (KS_OFF + 64*72)         // Ks: pair layout, stride 72
#define PS_OFF (VS_OFF + 64*72)         // Vs: [n][k-pair], stride 72
#define FLASH_SMEM ((PS_OFF + 8*1024) * 4)   // + Ps 8 warps x 1024 fl = 104448 B

__global__ __launch_bounds__(256, 2) void flash_attn_mma() {
    extern __shared__ float sm[];
    float* Qs = sm + QS_OFF;
    float* Ks = sm + KS_OFF;
    float* Vs = sm + VS_OFF;
    float* Ps = sm + PS_OFF;

    const int tid  = threadIdx.x;
    const int lane = tid & 31;
    const int warp = tid >> 5;
    const int g    = lane >> 2;
    const int tig  = lane & 3;
    const int xorb = (g >> 1) & 1;
    const int qt = (int)gridDim.x - 1 - (int)blockIdx.x;
    const int bh = blockIdx.y;
    const int q0 = qt * 128;

    const float4* Qg4 = (const float4*)(g_q + (size_t)bh * TLEN * HDIM);
    const float4* Kg4 = (const float4*)(g_k + (size_t)bh * TLEN * HDIM);
    const float4* Vg4 = (const float4*)(g_v + (size_t)bh * TLEN * HDIM);

    // Load Q once: fold 1/8 * log2(e), re-round to tf32
    const float QSCALE = 0.125f * 1.44269504089f;
#pragma unroll
    for (int r = 0; r < 8; r++) {
        int idx = tid + r * 256;
        int row = idx >> 4, c4 = idx & 15;
        float4 v = Qg4[(size_t)(q0 + row) * 16 + c4];
        v.x = to_tf32(v.x * QSCALE); v.y = to_tf32(v.y * QSCALE);
        v.z = to_tf32(v.z * QSCALE); v.w = to_tf32(v.w * QSCALE);
        *(float4*)&Qs[row * 68 + c4 * 4] = v;
    }
    __syncthreads();

    const int qrow_w = q0 + warp * 16;
    const int prow   = warp * 16 + g;

    // Hoist Q a-fragments
    float aq[8][4];
#pragma unroll
    for (int ks = 0; ks < 8; ks++) {
        aq[ks][0] = Qs[prow * 68 + ks * 8 + tig];
        aq[ks][1] = Qs[(prow + 8) * 68 + ks * 8 + tig];
        aq[ks][2] = Qs[prow * 68 + ks * 8 + tig + 4];
        aq[ks][3] = Qs[(prow + 8) * 68 + ks * 8 + tig + 4];
    }

    float m0 = -1e30f, m1 = -1e30f, l0 = 0.f, l1 = 0.f;
    float o[8][4];
#pragma unroll
    for (int nt = 0; nt < 8; nt++)
#pragma unroll
        for (int q = 0; q < 4; q++) o[nt][q] = 0.f;

    const int njt = 2 * qt + 2;

    for (int jt = 0; jt < njt; jt++) {
        __syncthreads();
        const int k0 = jt * 64;
#pragma unroll
        for (int r = 0; r < 4; r++) {
            int idx = tid + r * 256;
            int row = idx >> 4, c4 = idx & 15;
            // K: pair layout addr(row,hd) = row*72 + (hd>>3)*8 + (hd&3)*2 + ((hd>>2)&1)
            float4 kv4 = Kg4[(size_t)(k0 + row) * 16 + c4];
            int kb = row * 72 + (c4 >> 1) * 8 + (c4 & 1);
            Ks[kb + 0] = kv4.x; Ks[kb + 2] = kv4.y;
            Ks[kb + 4] = kv4.z; Ks[kb + 6] = kv4.w;
            // V: addr(k,n) = n*72 + (k>>3)*8 + (k&3)*2 + ((k>>2)&1)
            float4 vv4 = Vg4[(size_t)(k0 + row) * 16 + c4];
            int vb = (row >> 3) * 8 + (row & 3) * 2 + ((row >> 2) & 1);
            Vs[(c4 * 4 + 0) * 72 + vb] = vv4.x;
            Vs[(c4 * 4 + 1) * 72 + vb] = vv4.y;
            Vs[(c4 * 4 + 2) * 72 + vb] = vv4.z;
            Vs[(c4 * 4 + 3) * 72 + vb] = vv4.w;
        }
        __syncthreads();

        if (qrow_w + 15 < k0) continue;

        // ----- S = Q @ K^T (b-frag = one LDS.64) -----
        float s[8][4];
#pragma unroll
        for (int nt = 0; nt < 8; nt++)
#pragma unroll
            for (int q = 0; q < 4; q++) s[nt][q] = 0.f;
#pragma unroll
        for (int ks = 0; ks < 8; ks++) {
#pragma unroll
            for (int nt = 0; nt < 8; nt++) {
                float2 bf = *(const float2*)&Ks[(nt * 8 + g) * 72 + ks * 8 + tig * 2];
                mma_tf32(s[nt], aq[ks], (const float*)&bf);
            }
        }

        // ----- causal mask -----
        if (k0 + 63 > qrow_w) {
            const int row0 = qrow_w + g, row1 = row0 + 8;
#pragma unroll
            for (int nt = 0; nt < 8; nt++) {
                const int col = k0 + nt * 8 + 2 * tig;
                if (col     > row0) s[nt][0] = -1e30f;
                if (col + 1 > row0) s[nt][1] = -1e30f;
                if (col     > row1) s[nt][2] = -1e30f;
                if (col + 1 > row1) s[nt][3] = -1e30f;
            }
        }

        // ----- online softmax (log2 domain) -----
        float rm0 = -1e30f, rm1 = -1e30f;
#pragma unroll
        for (int nt = 0; nt < 8; nt++) {
            rm0 = fmaxf(rm0, fmaxf(s[nt][0], s[nt][1]));
            rm1 = fmaxf(rm1, fmaxf(s[nt][2], s[nt][3]));
        }
        rm0 = fmaxf(rm0, __shfl_xor_sync(0xffffffffu, rm0, 1));
        rm0 = fmaxf(rm0, __shfl_xor_sync(0xffffffffu, rm0, 2));
        rm1 = fmaxf(rm1, __shfl_xor_sync(0xffffffffu, rm1, 1));
        rm1 = fmaxf(rm1, __shfl_xor_sync(0xffffffffu, rm1, 2));
        const float mn0 = fmaxf(m0, rm0), mn1 = fmaxf(m1, rm1);
        const float c0 = exp2f(m0 - mn0), c1 = exp2f(m1 - mn1);
        float rs0 = 0.f, rs1 = 0.f;
        const int psl0 = ((2 * tig) & 3) ^ xorb;
        const int psl1 = ((2 * tig + 1) & 3) ^ xorb;
        const int jj = tig >> 1;
        const int pbase = warp * 1024 + g * 16 + jj * 2;
#pragma unroll
        for (int nt = 0; nt < 8; nt++) {
            float p00 = exp2f(s[nt][0] - mn0);
            float p01 = exp2f(s[nt][1] - mn0);
            float p10 = exp2f(s[nt][2] - mn1);
            float p11 = exp2f(s[nt][3] - mn1);
            rs0 += p00 + p01;
            rs1 += p10 + p11;
            *(float2*)&Ps[pbase + nt * 128 + psl0 * 4] =
                make_float2(to_tf32(p00), to_tf32(p10));
            *(float2*)&Ps[pbase + nt * 128 + psl1 * 4] =
                make_float2(to_tf32(p01), to_tf32(p11));
            o[nt][0] *= c0; o[nt][1] *= c0;
            o[nt][2] *= c1; o[nt][3] *= c1;
        }
        rs0 += __shfl_xor_sync(0xffffffffu, rs0, 1);
        rs0 += __shfl_xor_sync(0xffffffffu, rs0, 2);
        rs1 += __shfl_xor_sync(0xffffffffu, rs1, 1);
        rs1 += __shfl_xor_sync(0xffffffffu, rs1, 2);
        l0 = l0 * c0 + rs0; m0 = mn0;
        l1 = l1 * c1 + rs1; m1 = mn1;

        __syncwarp();

        // ----- O += P @ V (a-frag = one LDS.128, b-frag = one LDS.64) -----
#pragma unroll
        for (int ks = 0; ks < 8; ks++) {
            float4 af = *(const float4*)&Ps[warp * 1024 + ks * 128 + g * 16
                                            + (tig ^ xorb) * 4];
#pragma unroll
            for (int nt = 0; nt < 8; nt++) {
                float2 bf = *(const float2*)&Vs[(nt * 8 + g) * 72 + ks * 8 + tig * 2];
                mma_tf32(o[nt], (const float*)&af, (const float*)&bf);
            }
        }
    }

    // ----- normalize + write g_ao in A-fragment order (tf32-rounded) -----
    // float index(m,k) = (Mtile*4096 + Kblk*32 + g*4 + (k&3))*4 + slot,
    // slot = ((m>>3)&1) + 2*((k>>2)&1). Pair (row g, row g+8) => float2 at
    // f4*4 + 2*((k>>2)&1).  [R6 bug: used (k&3)*16; correct is (k&3)*4]
    const int b = bh >> 4;
    const int h = bh & 15;
    const float inv0 = 1.0f / l0, inv1 = 1.0f / l1;
    const int Mtile = b * 128 + (q0 >> 4) + warp;
    const int t0 = (2 * tig) & 3, t1 = (2 * tig + 1) & 3;
    const int jj = tig >> 1;
#pragma unroll
    for (int nt = 0; nt < 8; nt++) {
        const int Kblk = h * 8 + nt;
        const int fb = (Mtile * 4096 + Kblk * 32 + g * 4) * 4 + jj * 2;
        *(float2*)&g_ao[fb + t0 * 4] =
            make_float2(to_tf32(o[nt][0] * inv0), to_tf32(o[nt][2] * inv1));
        *(float2*)&g_ao[fb + t1 * 4] =
            make_float2(to_tf32(o[nt][1] * inv0), to_tf32(o[nt][3] * inv1));
    }
}

// ---------------------------------------------------------------------------
extern "C" void kernel_launch(void* const* d_in, const int* in_sizes, int n_in,
                              void* d_out, int out_size) {
    const float* x     = (const float*)d_in[0];
    const float* W_qkv = (const float*)d_in[1];
    const float* b_qkv = (const float*)d_in[2];
    const float* W_out = (const float*)d_in[3];
    const float* b_out = (const float*)d_in[4];
    float* out = (float*)d_out;

    cudaFuncSetAttribute(gemm_mma<0>, cudaFuncAttributeMaxDynamicSharedMemorySize, GEMM_SMEM);
    cudaFuncSetAttribute(gemm_mma<1>, cudaFuncAttributeMaxDynamicSharedMemorySize, GEMM_SMEM);
    cudaFuncSetAttribute(flash_attn_mma, cudaFuncAttributeMaxDynamicSharedMemorySize, FLASH_SMEM);

    float* xr; cudaGetSymbolAddress((void**)&xr, g_xr);
    float* wq; cudaGetSymbolAddress((void**)&wq, g_wqkv);
    float* wo; cudaGetSymbolAddress((void**)&wo, g_wout);

    // Permute+round prepasses
    perm_a<<<(MTOT / 16) * 128 * 8 / 256, 256>>>((const float4*)x, (float4*)xr);
    perm_b<<<(3 * DMODEL / 8) * 128 / 256, 256>>>((const float4*)W_qkv, (float4*)wq, 3 * DMODEL);
    perm_b<<<(DMODEL / 8) * 128 / 256, 256>>>((const float4*)W_out, (float4*)wo, DMODEL);

    gemm_mma<0><<<dim3(3 * DMODEL / 128, MTOT / 128), 256, GEMM_SMEM>>>(b_qkv, nullptr);
    flash_attn_mma<<<dim3(TLEN / 128, BATCH * NHEAD), 256, FLASH_SMEM>>>();
    gemm_mma<1><<<dim3(DMODEL / 128, MTOT / 128), 256, GEMM_SMEM>>>(b_out, out);
}

// round 8
// speedup vs baseline: 1.0936x; 1.0936x over previous
#include <cuda_runtime.h>
#include <cstdint>
#include <math.h>

// Problem constants
#define DMODEL 1024
#define TLEN   2048
#define BATCH  4
#define NHEAD  16
#define HDIM   64
#define MTOT   (BATCH*TLEN)      // 8192

// Scratch (static device globals; allocation-free rules)
__device__ float g_q [BATCH*NHEAD*TLEN*HDIM];  // [B,H,T,Hd], tf32-rounded, row-major
__device__ float g_k [BATCH*NHEAD*TLEN*HDIM];
__device__ float g_v [BATCH*NHEAD*TLEN*HDIM];
__device__ float g_ao[MTOT*DMODEL];            // A-fragment order, tf32-rounded
__device__ float g_xr  [MTOT*DMODEL];          // A-fragment order, tf32-rounded x
__device__ float g_wqkv[DMODEL*3*DMODEL];      // B-pair order, tf32-rounded
__device__ float g_wout[DMODEL*DMODEL];        // B-pair order, tf32-rounded

// ---------------------------------------------------------------------------
// Helpers
// ---------------------------------------------------------------------------
__device__ __forceinline__ uint32_t smem_u32(const void* p) {
    uint32_t a;
    asm("{ .reg .u64 t; cvta.to.shared.u64 t, %1; cvt.u32.u64 %0, t; }"
        : "=r"(a) : "l"(p));
    return a;
}

__device__ __forceinline__ float to_tf32(float x) {
    float r;
    asm("cvt.rna.tf32.f32 %0, %1;" : "=f"(r) : "f"(x));
    return r;
}

__device__ __forceinline__ void cp16(uint32_t dst, const void* src) {
    asm volatile("cp.async.cg.shared.global [%0], [%1], 16;"
                 :: "r"(dst), "l"(src) : "memory");
}
#define CP_COMMIT() asm volatile("cp.async.commit_group;" ::: "memory")
#define CP_WAIT1()  asm volatile("cp.async.wait_group 1;" ::: "memory")
#define CP_WAIT0()  asm volatile("cp.async.wait_group 0;" ::: "memory")

// m16n8k8 row.col tf32 MMA, fp32 accumulate
__device__ __forceinline__ void mma_tf32(float* c, const float* a, const float* b) {
    const uint32_t* A = reinterpret_cast<const uint32_t*>(a);
    const uint32_t* B = reinterpret_cast<const uint32_t*>(b);
    asm volatile(
        "mma.sync.aligned.m16n8k8.row.col.f32.tf32.tf32.f32 "
        "{%0,%1,%2,%3}, {%4,%5,%6,%7}, {%8,%9}, {%0,%1,%2,%3};"
        : "+f"(c[0]), "+f"(c[1]), "+f"(c[2]), "+f"(c[3])
        : "r"(A[0]), "r"(A[1]), "r"(A[2]), "r"(A[3]), "r"(B[0]), "r"(B[1]));
}

// ---------------------------------------------------------------------------
// Prepass: x (row-major [M,1024]) -> A-fragment order, tf32-rounded.
// ---------------------------------------------------------------------------
__global__ __launch_bounds__(256) void perm_a(const float4* __restrict__ src,
                                              float4* __restrict__ dst) {
    int t = blockIdx.x * 256 + threadIdx.x;       // (M/16)*128*8 threads
    int g = t & 7, Kblk = (t >> 3) & 127, Mtile = t >> 10;
    int m0 = Mtile * 16 + g;
    float4 r00 = src[m0 * 256 + Kblk * 2];
    float4 r01 = src[m0 * 256 + Kblk * 2 + 1];
    float4 r10 = src[(m0 + 8) * 256 + Kblk * 2];
    float4 r11 = src[(m0 + 8) * 256 + Kblk * 2 + 1];
    float a0[4] = {r00.x, r00.y, r00.z, r00.w};
    float a1[4] = {r10.x, r10.y, r10.z, r10.w};
    float a2[4] = {r01.x, r01.y, r01.z, r01.w};
    float a3[4] = {r11.x, r11.y, r11.z, r11.w};
    int base = Mtile * 4096 + Kblk * 32 + g * 4;
#pragma unroll
    for (int tig = 0; tig < 4; tig++) {
        float4 o;
        o.x = to_tf32(a0[tig]); o.y = to_tf32(a1[tig]);
        o.z = to_tf32(a2[tig]); o.w = to_tf32(a3[tig]);
        dst[base + tig] = o;
    }
}

// ---------------------------------------------------------------------------
// Prepass: W (row-major [1024,N]) -> B-pair order, tf32-rounded.
// ---------------------------------------------------------------------------
__global__ __launch_bounds__(256) void perm_b(const float4* __restrict__ src,
                                              float4* __restrict__ dst, int N) {
    int t = blockIdx.x * 256 + threadIdx.x;       // (N/8)*128 threads
    int Kblk = t & 127, Ntile = t >> 7;
    float w[8][8];
#pragma unroll
    for (int kk = 0; kk < 8; kk++) {
        int k = Kblk * 8 + kk;
        float4 wa = src[(size_t)k * (N / 4) + Ntile * 2];
        float4 wb = src[(size_t)k * (N / 4) + Ntile * 2 + 1];
        w[kk][0] = wa.x; w[kk][1] = wa.y; w[kk][2] = wa.z; w[kk][3] = wa.w;
        w[kk][4] = wb.x; w[kk][5] = wb.y; w[kk][6] = wb.z; w[kk][7] = wb.w;
    }
    int base = (Ntile * 128 + Kblk) * 16;
#pragma unroll
    for (int f = 0; f < 16; f++) {
        float o[4];
#pragma unroll
        for (int e = 0; e < 4; e++) {
            int l = f * 4 + e;
            int gb = l >> 3, tig = (l >> 1) & 3, jb = l & 1;
            o[e] = to_tf32(w[tig + 4 * jb][gb]);
        }
        dst[base + f] = make_float4(o[0], o[1], o[2], o[3]);
    }
}

// ---------------------------------------------------------------------------
// Tensor-core GEMM on fragment-order operands (unchanged from R7 — 260us).
// ---------------------------------------------------------------------------
#define STAGE_BYTES 32768          // 16KB A + 16KB B
#define GEMM_SMEM   (2 * STAGE_BYTES)

template<int MODE>
__global__ __launch_bounds__(256) void gemm_mma(const float* __restrict__ bias,
                                                float* __restrict__ out) {
    extern __shared__ char smem[];
    const uint32_t sb = smem_u32(smem);
    const int tid  = threadIdx.x;
    const int lane = tid & 31;
    const int warp = tid >> 5;
    const int mw = warp & 1;
    const int nw = warp >> 1;
    const int g   = lane >> 2;
    const int tig = lane & 3;
    const int brow = blockIdx.y * 128;
    const int bcol = blockIdx.x * 128;
    const int Mtile0 = blockIdx.y * 8;
    const int Ntile0 = blockIdx.x * 16;

    const float4* __restrict__ A4 = (const float4*)(MODE ? g_ao : g_xr);
    const float4* __restrict__ B4 = (const float4*)(MODE ? g_wout : g_wqkv);

    float acc[4][4][4];
#pragma unroll
    for (int i = 0; i < 4; i++)
#pragma unroll
        for (int j = 0; j < 4; j++)
#pragma unroll
            for (int q = 0; q < 4; q++) acc[i][j][q] = 0.f;

    auto issue = [&](int ic, int s) {
        const int Kb0 = ic * 4;
        const uint32_t As = sb + (uint32_t)s * STAGE_BYTES;
        const uint32_t Bs = As + 16384u;
#pragma unroll
        for (int r = 0; r < 4; r++) {
            int idx = tid + r * 256;
            int ml = idx >> 7, kl = (idx >> 5) & 3, l = idx & 31;
            cp16(As + (uint32_t)idx * 16,
                 &A4[(size_t)(Mtile0 + ml) * 4096 + (Kb0 + kl) * 32 + l]);
        }
#pragma unroll
        for (int r = 0; r < 4; r++) {
            int idx = tid + r * 256;
            int nl = idx >> 6, kl = (idx >> 4) & 3, l = idx & 15;
            cp16(Bs + (uint32_t)idx * 16,
                 &B4[(size_t)(Ntile0 + nl) * 2048 + (Kb0 + kl) * 16 + l]);
        }
    };

    issue(0, 0);
    CP_COMMIT();

    for (int ic = 0; ic < 32; ic++) {
        const int s = ic & 1;
        if (ic + 1 < 32) {
            issue(ic + 1, s ^ 1);
            CP_COMMIT();
            CP_WAIT1();
        } else {
            CP_WAIT0();
        }
        __syncthreads();

        const float4* As4 = (const float4*)(smem + (size_t)s * STAGE_BYTES);
        const float2* Bs2 = (const float2*)(smem + (size_t)s * STAGE_BYTES + 16384);

#pragma unroll
        for (int ks = 0; ks < 4; ks++) {
            float4 af[4];
            float2 bf[4];
#pragma unroll
            for (int mt = 0; mt < 4; mt++)
                af[mt] = As4[(mw * 4 + mt) * 128 + ks * 32 + g * 4 + tig];
#pragma unroll
            for (int nt = 0; nt < 4; nt++)
                bf[nt] = Bs2[((nw * 4 + nt) * 4 + ks) * 32 + g * 4 + tig];
#pragma unroll
            for (int mt = 0; mt < 4; mt++)
#pragma unroll
                for (int nt = 0; nt < 4; nt++)
                    mma_tf32(acc[mt][nt], (const float*)&af[mt], (const float*)&bf[nt]);
        }
        __syncthreads();
    }

#pragma unroll
    for (int mt = 0; mt < 4; mt++) {
#pragma unroll
        for (int half = 0; half < 2; half++) {
            const int m = brow + mw * 64 + mt * 16 + g + half * 8;
            const int b = m >> 11, t = m & 2047;
#pragma unroll
            for (int nt = 0; nt < 4; nt++) {
                const int col = bcol + nw * 32 + nt * 8 + 2 * tig;
                float2 o;
                o.x = acc[mt][nt][half * 2 + 0] + bias[col];
                o.y = acc[mt][nt][half * 2 + 1] + bias[col + 1];
                if (MODE == 0) {
                    o.x = to_tf32(o.x); o.y = to_tf32(o.y);
                    const int seg = col >> 10;
                    const int dc  = col & 1023;
                    const int h = dc >> 6, hd = dc & 63;
                    float* dst = (seg == 0) ? g_q : (seg == 1 ? g_k : g_v);
                    *(float2*)&dst[((size_t)((b * NHEAD + h) * TLEN + t)) * HDIM + hd] = o;
                } else {
                    *(float2*)&out[(size_t)m * DMODEL + col] = o;
                }
            }
        }
    }
}

// ---------------------------------------------------------------------------
// Flash attention, causal, tensor-core.
// K: pair layout (b-frag = LDS.64, stores 2-way).  V: ROW-MAJOR [kv][68]
// (float4 stores conflict-free; b-frag = 2 scalar LDS, conflict-free).
// P: swizzled fragment order (a-frag = LDS.128, stores 2-way).
// ---------------------------------------------------------------------------
#define QS_OFF 0
#define KS_OFF (128*68)                 // Qs: [128][68]
#define VS_OFF (KS_OFF + 64*72)         // Ks: pair layout, stride 72
#define PS_OFF (VS_OFF + 64*68)         // Vs: row-major [kv][68]
#define FLASH_SMEM ((PS_OFF + 8*1024) * 4)   // 103424 B

__global__ __launch_bounds__(256, 2) void flash_attn_mma() {
    extern __shared__ float sm[];
    float* Qs = sm + QS_OFF;
    float* Ks = sm + KS_OFF;
    float* Vs = sm + VS_OFF;
    float* Ps = sm + PS_OFF;

    const int tid  = threadIdx.x;
    const int lane = tid & 31;
    const int warp = tid >> 5;
    const int g    = lane >> 2;
    const int tig  = lane & 3;
    const int xorb = (g >> 1) & 1;
    const int qt = (int)gridDim.x - 1 - (int)blockIdx.x;
    const int bh = blockIdx.y;
    const int q0 = qt * 128;

    const float4* Qg4 = (const float4*)(g_q + (size_t)bh * TLEN * HDIM);
    const float4* Kg4 = (const float4*)(g_k + (size_t)bh * TLEN * HDIM);
    const float4* Vg4 = (const float4*)(g_v + (size_t)bh * TLEN * HDIM);

    // Load Q once: fold 1/8 * log2(e), re-round to tf32
    const float QSCALE = 0.125f * 1.44269504089f;
#pragma unroll
    for (int r = 0; r < 8; r++) {
        int idx = tid + r * 256;
        int row = idx >> 4, c4 = idx & 15;
        float4 v = Qg4[(size_t)(q0 + row) * 16 + c4];
        v.x = to_tf32(v.x * QSCALE); v.y = to_tf32(v.y * QSCALE);
        v.z = to_tf32(v.z * QSCALE); v.w = to_tf32(v.w * QSCALE);
        *(float4*)&Qs[row * 68 + c4 * 4] = v;
    }
    __syncthreads();

    const int qrow_w = q0 + warp * 16;
    const int prow   = warp * 16 + g;

    // Hoist Q a-fragments
    float aq[8][4];
#pragma unroll
    for (int ks = 0; ks < 8; ks++) {
        aq[ks][0] = Qs[prow * 68 + ks * 8 + tig];
        aq[ks][1] = Qs[(prow + 8) * 68 + ks * 8 + tig];
        aq[ks][2] = Qs[prow * 68 + ks * 8 + tig + 4];
        aq[ks][3] = Qs[(prow + 8) * 68 + ks * 8 + tig + 4];
    }

    float m0 = -1e30f, m1 = -1e30f, l0 = 0.f, l1 = 0.f;
    float o[8][4];
#pragma unroll
    for (int nt = 0; nt < 8; nt++)
#pragma unroll
        for (int q = 0; q < 4; q++) o[nt][q] = 0.f;

    const int njt = 2 * qt + 2;

    for (int jt = 0; jt < njt; jt++) {
        __syncthreads();
        const int k0 = jt * 64;
#pragma unroll
        for (int r = 0; r < 4; r++) {
            int idx = tid + r * 256;
            int row = idx >> 4, c4 = idx & 15;
            // K: pair layout addr(row,hd) = row*72 + (hd>>3)*8 + (hd&3)*2 + ((hd>>2)&1)
            float4 kv4 = Kg4[(size_t)(k0 + row) * 16 + c4];
            int kb = row * 72 + (c4 >> 1) * 8 + (c4 & 1);
            Ks[kb + 0] = kv4.x; Ks[kb + 2] = kv4.y;
            Ks[kb + 4] = kv4.z; Ks[kb + 6] = kv4.w;
            // V: row-major, conflict-free float4 store
            float4 vv4 = Vg4[(size_t)(k0 + row) * 16 + c4];
            *(float4*)&Vs[row * 68 + c4 * 4] = vv4;
        }
        __syncthreads();

        if (qrow_w + 15 < k0) continue;

        // ----- S = Q @ K^T (b-frag = one LDS.64) -----
        float s[8][4];
#pragma unroll
        for (int nt = 0; nt < 8; nt++)
#pragma unroll
            for (int q = 0; q < 4; q++) s[nt][q] = 0.f;
#pragma unroll
        for (int ks = 0; ks < 8; ks++) {
#pragma unroll
            for (int nt = 0; nt < 8; nt++) {
                float2 bf = *(const float2*)&Ks[(nt * 8 + g) * 72 + ks * 8 + tig * 2];
                mma_tf32(s[nt], aq[ks], (const float*)&bf);
            }
        }

        // ----- causal mask -----
        if (k0 + 63 > qrow_w) {
            const int row0 = qrow_w + g, row1 = row0 + 8;
#pragma unroll
            for (int nt = 0; nt < 8; nt++) {
                const int col = k0 + nt * 8 + 2 * tig;
                if (col     > row0) s[nt][0] = -1e30f;
                if (col + 1 > row0) s[nt][1] = -1e30f;
                if (col     > row1) s[nt][2] = -1e30f;
                if (col + 1 > row1) s[nt][3] = -1e30f;
            }
        }

        // ----- online softmax (log2 domain) -----
        float rm0 = -1e30f, rm1 = -1e30f;
#pragma unroll
        for (int nt = 0; nt < 8; nt++) {
            rm0 = fmaxf(rm0, fmaxf(s[nt][0], s[nt][1]));
            rm1 = fmaxf(rm1, fmaxf(s[nt][2], s[nt][3]));
        }
        rm0 = fmaxf(rm0, __shfl_xor_sync(0xffffffffu, rm0, 1));
        rm0 = fmaxf(rm0, __shfl_xor_sync(0xffffffffu, rm0, 2));
        rm1 = fmaxf(rm1, __shfl_xor_sync(0xffffffffu, rm1, 1));
        rm1 = fmaxf(rm1, __shfl_xor_sync(0xffffffffu, rm1, 2));
        const float mn0 = fmaxf(m0, rm0), mn1 = fmaxf(m1, rm1);
        const float c0 = exp2f(m0 - mn0), c1 = exp2f(m1 - mn1);
        float rs0 = 0.f, rs1 = 0.f;
        const int psl0 = ((2 * tig) & 3) ^ xorb;
        const int psl1 = ((2 * tig + 1) & 3) ^ xorb;
        const int jj = tig >> 1;
        const int pbase = warp * 1024 + g * 16 + jj * 2;
#pragma unroll
        for (int nt = 0; nt < 8; nt++) {
            float p00 = exp2f(s[nt][0] - mn0);
            float p01 = exp2f(s[nt][1] - mn0);
            float p10 = exp2f(s[nt][2] - mn1);
            float p11 = exp2f(s[nt][3] - mn1);
            rs0 += p00 + p01;
            rs1 += p10 + p11;
            *(float2*)&Ps[pbase + nt * 128 + psl0 * 4] =
                make_float2(to_tf32(p00), to_tf32(p10));
            *(float2*)&Ps[pbase + nt * 128 + psl1 * 4] =
                make_float2(to_tf32(p01), to_tf32(p11));
            o[nt][0] *= c0; o[nt][1] *= c0;
            o[nt][2] *= c1; o[nt][3] *= c1;
        }
        rs0 += __shfl_xor_sync(0xffffffffu, rs0, 1);
        rs0 += __shfl_xor_sync(0xffffffffu, rs0, 2);
        rs1 += __shfl_xor_sync(0xffffffffu, rs1, 1);
        rs1 += __shfl_xor_sync(0xffffffffu, rs1, 2);
        l0 = l0 * c0 + rs0; m0 = mn0;
        l1 = l1 * c1 + rs1; m1 = mn1;

        __syncwarp();

        // ----- O += P @ V (a-frag = LDS.128; b-frag = 2 scalar LDS, no conflict) -----
#pragma unroll
        for (int ks = 0; ks < 8; ks++) {
            float4 af = *(const float4*)&Ps[warp * 1024 + ks * 128 + g * 16
                                            + (tig ^ xorb) * 4];
#pragma unroll
            for (int nt = 0; nt < 8; nt++) {
                float bf[2];
                bf[0] = Vs[(ks * 8 + tig) * 68 + nt * 8 + g];
                bf[1] = Vs[(ks * 8 + tig + 4) * 68 + nt * 8 + g];
                mma_tf32(o[nt], (const float*)&af, bf);
            }
        }
    }

    // ----- normalize + write g_ao in A-fragment order (tf32-rounded) -----
    const int b = bh >> 4;
    const int h = bh & 15;
    const float inv0 = 1.0f / l0, inv1 = 1.0f / l1;
    const int Mtile = b * 128 + (q0 >> 4) + warp;
    const int t0 = (2 * tig) & 3, t1 = (2 * tig + 1) & 3;
    const int jj = tig >> 1;
#pragma unroll
    for (int nt = 0; nt < 8; nt++) {
        const int Kblk = h * 8 + nt;
        const int fb = (Mtile * 4096 + Kblk * 32 + g * 4) * 4 + jj * 2;
        *(float2*)&g_ao[fb + t0 * 4] =
            make_float2(to_tf32(o[nt][0] * inv0), to_tf32(o[nt][2] * inv1));
        *(float2*)&g_ao[fb + t1 * 4] =
            make_float2(to_tf32(o[nt][1] * inv0), to_tf32(o[nt][3] * inv1));
    }
}

// ---------------------------------------------------------------------------
extern "C" void kernel_launch(void* const* d_in, const int* in_sizes, int n_in,
                              void* d_out, int out_size) {
    const float* x     = (const float*)d_in[0];
    const float* W_qkv = (const float*)d_in[1];
    const float* b_qkv = (const float*)d_in[2];
    const float* W_out = (const float*)d_in[3];
    const float* b_out = (const float*)d_in[4];
    float* out = (float*)d_out;

    cudaFuncSetAttribute(gemm_mma<0>, cudaFuncAttributeMaxDynamicSharedMemorySize, GEMM_SMEM);
    cudaFuncSetAttribute(gemm_mma<1>, cudaFuncAttributeMaxDynamicSharedMemorySize, GEMM_SMEM);
    cudaFuncSetAttribute(flash_attn_mma, cudaFuncAttributeMaxDynamicSharedMemorySize, FLASH_SMEM);

    float* xr; cudaGetSymbolAddress((void**)&xr, g_xr);
    float* wq; cudaGetSymbolAddress((void**)&wq, g_wqkv);
    float* wo; cudaGetSymbolAddress((void**)&wo, g_wout);

    perm_a<<<(MTOT / 16) * 128 * 8 / 256, 256>>>((const float4*)x, (float4*)xr);
    perm_b<<<(3 * DMODEL / 8) * 128 / 256, 256>>>((const float4*)W_qkv, (float4*)wq, 3 * DMODEL);
    perm_b<<<(DMODEL / 8) * 128 / 256, 256>>>((const float4*)W_out, (float4*)wo, DMODEL);

    gemm_mma<0><<<dim3(3 * DMODEL / 128, MTOT / 128), 256, GEMM_SMEM>>>(b_qkv, nullptr);
    flash_attn_mma<<<dim3(TLEN / 128, BATCH * NHEAD), 256, FLASH_SMEM>>>();
    gemm_mma<1><<<dim3(DMODEL / 128, MTOT / 128), 256, GEMM_SMEM>>>(b_out, out);
}

// round 9
// speedup vs baseline: 1.1831x; 1.0818x over previous
#include <cuda_runtime.h>
#include <cuda_fp16.h>
#include <cstdint>
#include <math.h>

// Problem constants
#define DMODEL 1024
#define TLEN   2048
#define BATCH  4
#define NHEAD  16
#define HDIM   64
#define MTOT   (BATCH*TLEN)      // 8192

// Scratch (static device globals; allocation-free rules)
__device__ float g_q [BATCH*NHEAD*TLEN*HDIM];  // [B,H,T,Hd], tf32-rounded, row-major
__device__ float g_k [BATCH*NHEAD*TLEN*HDIM];
__device__ float g_v [BATCH*NHEAD*TLEN*HDIM];
__device__ float g_ao[MTOT*DMODEL];            // A-fragment order, tf32-rounded
__device__ float g_xr  [MTOT*DMODEL];          // A-fragment order, tf32-rounded x
__device__ float g_wqkv[DMODEL*3*DMODEL];      // B-pair order, tf32-rounded
__device__ float g_wout[DMODEL*DMODEL];        // B-pair order, tf32-rounded

// ---------------------------------------------------------------------------
// Helpers
// ---------------------------------------------------------------------------
__device__ __forceinline__ uint32_t smem_u32(const void* p) {
    uint32_t a;
    asm("{ .reg .u64 t; cvta.to.shared.u64 t, %1; cvt.u32.u64 %0, t; }"
        : "=r"(a) : "l"(p));
    return a;
}

__device__ __forceinline__ float to_tf32(float x) {
    float r;
    asm("cvt.rna.tf32.f32 %0, %1;" : "=f"(r) : "f"(x));
    return r;
}

__device__ __forceinline__ uint32_t f2h2(float lo, float hi) {
    __half2 h = __floats2half2_rn(lo, hi);
    return *reinterpret_cast<uint32_t*>(&h);
}

__device__ __forceinline__ void cp16(uint32_t dst, const void* src) {
    asm volatile("cp.async.cg.shared.global [%0], [%1], 16;"
                 :: "r"(dst), "l"(src) : "memory");
}
#define CP_COMMIT() asm volatile("cp.async.commit_group;" ::: "memory")
#define CP_WAIT1()  asm volatile("cp.async.wait_group 1;" ::: "memory")
#define CP_WAIT0()  asm volatile("cp.async.wait_group 0;" ::: "memory")

// m16n8k8 row.col tf32 MMA, fp32 accumulate (projection GEMMs)
__device__ __forceinline__ void mma_tf32(float* c, const float* a, const float* b) {
    const uint32_t* A = reinterpret_cast<const uint32_t*>(a);
    const uint32_t* B = reinterpret_cast<const uint32_t*>(b);
    asm volatile(
        "mma.sync.aligned.m16n8k8.row.col.f32.tf32.tf32.f32 "
        "{%0,%1,%2,%3}, {%4,%5,%6,%7}, {%8,%9}, {%0,%1,%2,%3};"
        : "+f"(c[0]), "+f"(c[1]), "+f"(c[2]), "+f"(c[3])
        : "r"(A[0]), "r"(A[1]), "r"(A[2]), "r"(A[3]), "r"(B[0]), "r"(B[1]));
}

// m16n8k16 row.col fp16 MMA, fp32 accumulate (flash attention)
__device__ __forceinline__ void mma_f16(float* c, const uint32_t* a,
                                        uint32_t b0, uint32_t b1) {
    asm volatile(
        "mma.sync.aligned.m16n8k16.row.col.f32.f16.f16.f32 "
        "{%0,%1,%2,%3}, {%4,%5,%6,%7}, {%8,%9}, {%0,%1,%2,%3};"
        : "+f"(c[0]), "+f"(c[1]), "+f"(c[2]), "+f"(c[3])
        : "r"(a[0]), "r"(a[1]), "r"(a[2]), "r"(a[3]), "r"(b0), "r"(b1));
}

// ---------------------------------------------------------------------------
// Prepass: x (row-major [M,1024]) -> A-fragment order, tf32-rounded.
// ---------------------------------------------------------------------------
__global__ __launch_bounds__(256) void perm_a(const float4* __restrict__ src,
                                              float4* __restrict__ dst) {
    int t = blockIdx.x * 256 + threadIdx.x;
    int g = t & 7, Kblk = (t >> 3) & 127, Mtile = t >> 10;
    int m0 = Mtile * 16 + g;
    float4 r00 = src[m0 * 256 + Kblk * 2];
    float4 r01 = src[m0 * 256 + Kblk * 2 + 1];
    float4 r10 = src[(m0 + 8) * 256 + Kblk * 2];
    float4 r11 = src[(m0 + 8) * 256 + Kblk * 2 + 1];
    float a0[4] = {r00.x, r00.y, r00.z, r00.w};
    float a1[4] = {r10.x, r10.y, r10.z, r10.w};
    float a2[4] = {r01.x, r01.y, r01.z, r01.w};
    float a3[4] = {r11.x, r11.y, r11.z, r11.w};
    int base = Mtile * 4096 + Kblk * 32 + g * 4;
#pragma unroll
    for (int tig = 0; tig < 4; tig++) {
        float4 o;
        o.x = to_tf32(a0[tig]); o.y = to_tf32(a1[tig]);
        o.z = to_tf32(a2[tig]); o.w = to_tf32(a3[tig]);
        dst[base + tig] = o;
    }
}

// ---------------------------------------------------------------------------
// Prepass: W (row-major [1024,N]) -> B-pair order, tf32-rounded.
// ---------------------------------------------------------------------------
__global__ __launch_bounds__(256) void perm_b(const float4* __restrict__ src,
                                              float4* __restrict__ dst, int N) {
    int t = blockIdx.x * 256 + threadIdx.x;
    int Kblk = t & 127, Ntile = t >> 7;
    float w[8][8];
#pragma unroll
    for (int kk = 0; kk < 8; kk++) {
        int k = Kblk * 8 + kk;
        float4 wa = src[(size_t)k * (N / 4) + Ntile * 2];
        float4 wb = src[(size_t)k * (N / 4) + Ntile * 2 + 1];
        w[kk][0] = wa.x; w[kk][1] = wa.y; w[kk][2] = wa.z; w[kk][3] = wa.w;
        w[kk][4] = wb.x; w[kk][5] = wb.y; w[kk][6] = wb.z; w[kk][7] = wb.w;
    }
    int base = (Ntile * 128 + Kblk) * 16;
#pragma unroll
    for (int f = 0; f < 16; f++) {
        float o[4];
#pragma unroll
        for (int e = 0; e < 4; e++) {
            int l = f * 4 + e;
            int gb = l >> 3, tig = (l >> 1) & 3, jb = l & 1;
            o[e] = to_tf32(w[tig + 4 * jb][gb]);
        }
        dst[base + f] = make_float4(o[0], o[1], o[2], o[3]);
    }
}

// ---------------------------------------------------------------------------
// Tensor-core GEMM on fragment-order operands (unchanged from R8 — 260us).
// ---------------------------------------------------------------------------
#define STAGE_BYTES 32768
#define GEMM_SMEM   (2 * STAGE_BYTES)

template<int MODE>
__global__ __launch_bounds__(256) void gemm_mma(const float* __restrict__ bias,
                                                float* __restrict__ out) {
    extern __shared__ char smem[];
    const uint32_t sb = smem_u32(smem);
    const int tid  = threadIdx.x;
    const int lane = tid & 31;
    const int warp = tid >> 5;
    const int mw = warp & 1;
    const int nw = warp >> 1;
    const int g   = lane >> 2;
    const int tig = lane & 3;
    const int brow = blockIdx.y * 128;
    const int bcol = blockIdx.x * 128;
    const int Mtile0 = blockIdx.y * 8;
    const int Ntile0 = blockIdx.x * 16;

    const float4* __restrict__ A4 = (const float4*)(MODE ? g_ao : g_xr);
    const float4* __restrict__ B4 = (const float4*)(MODE ? g_wout : g_wqkv);

    float acc[4][4][4];
#pragma unroll
    for (int i = 0; i < 4; i++)
#pragma unroll
        for (int j = 0; j < 4; j++)
#pragma unroll
            for (int q = 0; q < 4; q++) acc[i][j][q] = 0.f;

    auto issue = [&](int ic, int s) {
        const int Kb0 = ic * 4;
        const uint32_t As = sb + (uint32_t)s * STAGE_BYTES;
        const uint32_t Bs = As + 16384u;
#pragma unroll
        for (int r = 0; r < 4; r++) {
            int idx = tid + r * 256;
            int ml = idx >> 7, kl = (idx >> 5) & 3, l = idx & 31;
            cp16(As + (uint32_t)idx * 16,
                 &A4[(size_t)(Mtile0 + ml) * 4096 + (Kb0 + kl) * 32 + l]);
        }
#pragma unroll
        for (int r = 0; r < 4; r++) {
            int idx = tid + r * 256;
            int nl = idx >> 6, kl = (idx >> 4) & 3, l = idx & 15;
            cp16(Bs + (uint32_t)idx * 16,
                 &B4[(size_t)(Ntile0 + nl) * 2048 + (Kb0 + kl) * 16 + l]);
        }
    };

    issue(0, 0);
    CP_COMMIT();

    for (int ic = 0; ic < 32; ic++) {
        const int s = ic & 1;
        if (ic + 1 < 32) {
            issue(ic + 1, s ^ 1);
            CP_COMMIT();
            CP_WAIT1();
        } else {
            CP_WAIT0();
        }
        __syncthreads();

        const float4* As4 = (const float4*)(smem + (size_t)s * STAGE_BYTES);
        const float2* Bs2 = (const float2*)(smem + (size_t)s * STAGE_BYTES + 16384);

#pragma unroll
        for (int ks = 0; ks < 4; ks++) {
            float4 af[4];
            float2 bf[4];
#pragma unroll
            for (int mt = 0; mt < 4; mt++)
                af[mt] = As4[(mw * 4 + mt) * 128 + ks * 32 + g * 4 + tig];
#pragma unroll
            for (int nt = 0; nt < 4; nt++)
                bf[nt] = Bs2[((nw * 4 + nt) * 4 + ks) * 32 + g * 4 + tig];
#pragma unroll
            for (int mt = 0; mt < 4; mt++)
#pragma unroll
                for (int nt = 0; nt < 4; nt++)
                    mma_tf32(acc[mt][nt], (const float*)&af[mt], (const float*)&bf[nt]);
        }
        __syncthreads();
    }

#pragma unroll
    for (int mt = 0; mt < 4; mt++) {
#pragma unroll
        for (int half = 0; half < 2; half++) {
            const int m = brow + mw * 64 + mt * 16 + g + half * 8;
            const int b = m >> 11, t = m & 2047;
#pragma unroll
            for (int nt = 0; nt < 4; nt++) {
                const int col = bcol + nw * 32 + nt * 8 + 2 * tig;
                float2 o;
                o.x = acc[mt][nt][half * 2 + 0] + bias[col];
                o.y = acc[mt][nt][half * 2 + 1] + bias[col + 1];
                if (MODE == 0) {
                    o.x = to_tf32(o.x); o.y = to_tf32(o.y);
                    const int seg = col >> 10;
                    const int dc  = col & 1023;
                    const int h = dc >> 6, hd = dc & 63;
                    float* dst = (seg == 0) ? g_q : (seg == 1 ? g_k : g_v);
                    *(float2*)&dst[((size_t)((b * NHEAD + h) * TLEN + t)) * HDIM + hd] = o;
                } else {
                    *(float2*)&out[(size_t)m * DMODEL + col] = o;
                }
            }
        }
    }
}

// ---------------------------------------------------------------------------
// Flash attention, causal, fp16 tensor-core (m16n8k16).
// Qs: fp16 row-major [128 rows][66 halfs] (33 words/row) — read once (aq hoist).
// Ks: fp16 [kv n][k-paired], 34 words/row: word = n*34 + (k>>4)*8+((k>>1)&3)*2+((k>>3)&1).
//     b-frag = ONE LDS.64. Fill stores conflict-free.
// Vp: fp16 [k2][n], 66 words/row: half2 = (V[2k2][n], V[2k2+1][n]).
//     b-frag = 2 LDS.32. Fill conflict-free (thread owns a k2 pair).
// P:  never touches SMEM — k16 S c-fragment IS the PV a-fragment (same lanes).
// ---------------------------------------------------------------------------
#define QW 33
#define KW 34
#define VW 66
#define KS_W (128*QW)            // 4224
#define VP_W (KS_W + 64*KW)      // 6400
#define FLASH_SMEM ((VP_W + 32*VW) * 4)   // 34048 B

__global__ __launch_bounds__(256, 2) void flash_attn_f16() {
    extern __shared__ uint32_t smw[];
    uint32_t* Qw = smw;
    uint32_t* Kw = smw + KS_W;
    uint32_t* Vw = smw + VP_W;

    const int tid  = threadIdx.x;
    const int lane = tid & 31;
    const int warp = tid >> 5;
    const int g    = lane >> 2;
    const int tig  = lane & 3;
    const int qt = (int)gridDim.x - 1 - (int)blockIdx.x;
    const int bh = blockIdx.y;
    const int q0 = qt * 128;

    const float4* Qg4 = (const float4*)(g_q + (size_t)bh * TLEN * HDIM);
    const float4* Kg4 = (const float4*)(g_k + (size_t)bh * TLEN * HDIM);
    const float4* Vg4 = (const float4*)(g_v + (size_t)bh * TLEN * HDIM);

    // ---- Q fill: fold 1/8*log2(e), cvt fp16 (exact on tf32 values' mantissa) ----
    const float QSCALE = 0.125f * 1.44269504089f;
#pragma unroll
    for (int r = 0; r < 4; r++) {
        int t = tid + r * 256;          // 128 rows x 8 col-groups
        int row = t >> 3, c8 = t & 7;
        float4 v0 = Qg4[(size_t)(q0 + row) * 16 + c8 * 2];
        float4 v1 = Qg4[(size_t)(q0 + row) * 16 + c8 * 2 + 1];
        int wb = row * QW + c8 * 4;
        Qw[wb + 0] = f2h2(v0.x * QSCALE, v0.y * QSCALE);
        Qw[wb + 1] = f2h2(v0.z * QSCALE, v0.w * QSCALE);
        Qw[wb + 2] = f2h2(v1.x * QSCALE, v1.y * QSCALE);
        Qw[wb + 3] = f2h2(v1.z * QSCALE, v1.w * QSCALE);
    }
    __syncthreads();

    const int qrow_w = q0 + warp * 16;
    const int prow   = warp * 16 + g;

    // Hoist Q a-fragments (4 k-chunks of 16)
    uint32_t aq[4][4];
#pragma unroll
    for (int ksc = 0; ksc < 4; ksc++) {
        aq[ksc][0] = Qw[prow * QW + ksc * 8 + tig];
        aq[ksc][1] = Qw[(prow + 8) * QW + ksc * 8 + tig];
        aq[ksc][2] = Qw[prow * QW + ksc * 8 + tig + 4];
        aq[ksc][3] = Qw[(prow + 8) * QW + ksc * 8 + tig + 4];
    }

    float m0 = -1e30f, m1 = -1e30f, l0 = 0.f, l1 = 0.f;
    float o[8][4];
#pragma unroll
    for (int nt = 0; nt < 8; nt++)
#pragma unroll
        for (int q = 0; q < 4; q++) o[nt][q] = 0.f;

    const int njt = 2 * qt + 2;

    for (int jt = 0; jt < njt; jt++) {
        __syncthreads();
        const int k0 = jt * 64;
        // ---- K fill: [n][k-paired], conflict-free ----
#pragma unroll
        for (int r = 0; r < 4; r++) {
            int t = tid + r * 256;      // 64 rows x 16 c4
            int n = t >> 4, c4 = t & 15;
            float4 kv4 = Kg4[(size_t)(k0 + n) * 16 + c4];
            int k1 = 4 * c4, k2i = 4 * c4 + 2;
            int w1 = n * KW + ((k1 >> 4) << 3) + (((k1 >> 1) & 3) << 1) + ((k1 >> 3) & 1);
            int w2 = n * KW + ((k2i >> 4) << 3) + (((k2i >> 1) & 3) << 1) + ((k2i >> 3) & 1);
            Kw[w1] = f2h2(kv4.x, kv4.y);
            Kw[w2] = f2h2(kv4.z, kv4.w);
        }
        // ---- V fill: [k2][n] half2 transpose-pack, conflict-free ----
#pragma unroll
        for (int r = 0; r < 2; r++) {
            int t = tid + r * 256;      // 32 k2 x 16 c4
            int k2 = t >> 4, c4 = t & 15;
            float4 v0 = Vg4[(size_t)(k0 + 2 * k2) * 16 + c4];
            float4 v1 = Vg4[(size_t)(k0 + 2 * k2 + 1) * 16 + c4];
            int wb = k2 * VW + 4 * c4;
            Vw[wb + 0] = f2h2(v0.x, v1.x);
            Vw[wb + 1] = f2h2(v0.y, v1.y);
            Vw[wb + 2] = f2h2(v0.z, v1.z);
            Vw[wb + 3] = f2h2(v0.w, v1.w);
        }
        __syncthreads();

        if (qrow_w + 15 < k0) continue;

        // ----- S = Q @ K^T (b-frag = one LDS.64) -----
        float s[8][4];
#pragma unroll
        for (int nt = 0; nt < 8; nt++)
#pragma unroll
            for (int q = 0; q < 4; q++) s[nt][q] = 0.f;
#pragma unroll
        for (int ksc = 0; ksc < 4; ksc++) {
#pragma unroll
            for (int nt = 0; nt < 8; nt++) {
                uint2 bb = *(const uint2*)&Kw[(nt * 8 + g) * KW + ksc * 8 + 2 * tig];
                mma_f16(s[nt], aq[ksc], bb.x, bb.y);
            }
        }

        // ----- causal mask (same c-layout as k8) -----
        if (k0 + 63 > qrow_w) {
            const int row0 = qrow_w + g, row1 = row0 + 8;
#pragma unroll
            for (int nt = 0; nt < 8; nt++) {
                const int col = k0 + nt * 8 + 2 * tig;
                if (col     > row0) s[nt][0] = -1e30f;
                if (col + 1 > row0) s[nt][1] = -1e30f;
                if (col     > row1) s[nt][2] = -1e30f;
                if (col + 1 > row1) s[nt][3] = -1e30f;
            }
        }

        // ----- online softmax (log2 domain); P a-frags built in registers -----
        float rm0 = -1e30f, rm1 = -1e30f;
#pragma unroll
        for (int nt = 0; nt < 8; nt++) {
            rm0 = fmaxf(rm0, fmaxf(s[nt][0], s[nt][1]));
            rm1 = fmaxf(rm1, fmaxf(s[nt][2], s[nt][3]));
        }
        rm0 = fmaxf(rm0, __shfl_xor_sync(0xffffffffu, rm0, 1));
        rm0 = fmaxf(rm0, __shfl_xor_sync(0xffffffffu, rm0, 2));
        rm1 = fmaxf(rm1, __shfl_xor_sync(0xffffffffu, rm1, 1));
        rm1 = fmaxf(rm1, __shfl_xor_sync(0xffffffffu, rm1, 2));
        const float mn0 = fmaxf(m0, rm0), mn1 = fmaxf(m1, rm1);
        const float c0 = exp2f(m0 - mn0), c1 = exp2f(m1 - mn1);
        float rs0 = 0.f, rs1 = 0.f;
        uint32_t pa[4][4];
#pragma unroll
        for (int nt = 0; nt < 8; nt++) {
            float p00 = exp2f(s[nt][0] - mn0);
            float p01 = exp2f(s[nt][1] - mn0);
            float p10 = exp2f(s[nt][2] - mn1);
            float p11 = exp2f(s[nt][3] - mn1);
            rs0 += p00 + p01;
            rs1 += p10 + p11;
            pa[nt >> 1][(nt & 1) * 2 + 0] = f2h2(p00, p01);   // rows g
            pa[nt >> 1][(nt & 1) * 2 + 1] = f2h2(p10, p11);   // rows g+8
            o[nt][0] *= c0; o[nt][1] *= c0;
            o[nt][2] *= c1; o[nt][3] *= c1;
        }
        rs0 += __shfl_xor_sync(0xffffffffu, rs0, 1);
        rs0 += __shfl_xor_sync(0xffffffffu, rs0, 2);
        rs1 += __shfl_xor_sync(0xffffffffu, rs1, 1);
        rs1 += __shfl_xor_sync(0xffffffffu, rs1, 2);
        l0 = l0 * c0 + rs0; m0 = mn0;
        l1 = l1 * c1 + rs1; m1 = mn1;

        // a-frag reg order check: reg0=(g,2tig@16ksc), reg1=(g+8,..), reg2=(g,+8), reg3=(g+8,+8)
        // pa[ksc] = { h2(s[2ksc][0,1]), h2(s[2ksc][2,3]), h2(s[2ksc+1][0,1]), h2(s[2ksc+1][2,3]) } ✓

        // ----- O += P @ V (no SMEM for P; b-frag = 2 LDS.32) -----
#pragma unroll
        for (int ksc = 0; ksc < 4; ksc++) {
#pragma unroll
            for (int nt = 0; nt < 8; nt++) {
                uint32_t b0 = Vw[(8 * ksc + tig) * VW + nt * 8 + g];
                uint32_t b1 = Vw[(8 * ksc + tig + 4) * VW + nt * 8 + g];
                mma_f16(o[nt], pa[ksc], b0, b1);
            }
        }
    }

    // ----- normalize + write g_ao in A-fragment order (tf32-rounded) -----
    const int b = bh >> 4;
    const int h = bh & 15;
    const float inv0 = 1.0f / l0, inv1 = 1.0f / l1;
    const int Mtile = b * 128 + (q0 >> 4) + warp;
    const int t0 = (2 * tig) & 3, t1 = (2 * tig + 1) & 3;
    const int jj = tig >> 1;
#pragma unroll
    for (int nt = 0; nt < 8; nt++) {
        const int Kblk = h * 8 + nt;
        const int fb = (Mtile * 4096 + Kblk * 32 + g * 4) * 4 + jj * 2;
        *(float2*)&g_ao[fb + t0 * 4] =
            make_float2(to_tf32(o[nt][0] * inv0), to_tf32(o[nt][2] * inv1));
        *(float2*)&g_ao[fb + t1 * 4] =
            make_float2(to_tf32(o[nt][1] * inv0), to_tf32(o[nt][3] * inv1));
    }
}

// ---------------------------------------------------------------------------
extern "C" void kernel_launch(void* const* d_in, const int* in_sizes, int n_in,
                              void* d_out, int out_size) {
    const float* x     = (const float*)d_in[0];
    const float* W_qkv = (const float*)d_in[1];
    const float* b_qkv = (const float*)d_in[2];
    const float* W_out = (const float*)d_in[3];
    const float* b_out = (const float*)d_in[4];
    float* out = (float*)d_out;

    cudaFuncSetAttribute(gemm_mma<0>, cudaFuncAttributeMaxDynamicSharedMemorySize, GEMM_SMEM);
    cudaFuncSetAttribute(gemm_mma<1>, cudaFuncAttributeMaxDynamicSharedMemorySize, GEMM_SMEM);
    cudaFuncSetAttribute(flash_attn_f16, cudaFuncAttributeMaxDynamicSharedMemorySize, FLASH_SMEM);

    float* xr; cudaGetSymbolAddress((void**)&xr, g_xr);
    float* wq; cudaGetSymbolAddress((void**)&wq, g_wqkv);
    float* wo; cudaGetSymbolAddress((void**)&wo, g_wout);

    perm_a<<<(MTOT / 16) * 128 * 8 / 256, 256>>>((const float4*)x, (float4*)xr);
    perm_b<<<(3 * DMODEL / 8) * 128 / 256, 256>>>((const float4*)W_qkv, (float4*)wq, 3 * DMODEL);
    perm_b<<<(DMODEL / 8) * 128 / 256, 256>>>((const float4*)W_out, (float4*)wo, DMODEL);

    gemm_mma<0><<<dim3(3 * DMODEL / 128, MTOT / 128), 256, GEMM_SMEM>>>(b_qkv, nullptr);
    flash_attn_f16<<<dim3(TLEN / 128, BATCH * NHEAD), 256, FLASH_SMEM>>>();
    gemm_mma<1><<<dim3(DMODEL / 128, MTOT / 128), 256, GEMM_SMEM>>>(b_out, out);
}

// round 10
// speedup vs baseline: 2.2730x; 1.9212x over previous
#include <cuda_runtime.h>
#include <cuda_fp16.h>
#include <cstdint>
#include <math.h>

// Problem constants
#define DMODEL 1024
#define TLEN   2048
#define BATCH  4
#define NHEAD  16
#define HDIM   64
#define MTOT   (BATCH*TLEN)      // 8192

#define QSCALE (0.125f * 1.44269504089f)   // 1/sqrt(64) * log2(e), folded into q

// ---------------------------------------------------------------------------
// Global scratch, all fp16 stored as uint32 half2-words.
// g_qw : flash A-frag order  [bh][t>>4][hd>>4][lane][4 words]
// g_kw : flash B-frag order  [bh][t>>3][hd>>4][lane][2 words]
// g_vw : row-major           [bh][t][hd>>1]
// g_xrw, g_aow : GEMM A-frag order  [m>>4][k>>4][lane][4 words]
// g_wqkvw, g_woutw : GEMM B-frag order [n>>3][k>>4][lane][2 words]
// ---------------------------------------------------------------------------
__device__ uint32_t g_qw  [4194304];
__device__ uint32_t g_kw  [4194304];
__device__ uint32_t g_vw  [4194304];
__device__ uint32_t g_aow [4194304];
__device__ uint32_t g_xrw [4194304];
__device__ uint32_t g_wqkvw[1572864];
__device__ uint32_t g_woutw[524288];

// ---------------------------------------------------------------------------
// Helpers
// ---------------------------------------------------------------------------
__device__ __forceinline__ uint32_t smem_u32(const void* p) {
    uint32_t a;
    asm("{ .reg .u64 t; cvta.to.shared.u64 t, %1; cvt.u32.u64 %0, t; }"
        : "=r"(a) : "l"(p));
    return a;
}

__device__ __forceinline__ uint32_t f2h2(float lo, float hi) {
    __half2 h = __floats2half2_rn(lo, hi);
    return *reinterpret_cast<uint32_t*>(&h);
}

__device__ __forceinline__ void cp16(uint32_t dst, const void* src) {
    asm volatile("cp.async.cg.shared.global [%0], [%1], 16;"
                 :: "r"(dst), "l"(src) : "memory");
}
#define CP_COMMIT() asm volatile("cp.async.commit_group;" ::: "memory")
#define CP_WAIT1()  asm volatile("cp.async.wait_group 1;" ::: "memory")
#define CP_WAIT0()  asm volatile("cp.async.wait_group 0;" ::: "memory")

// m16n8k16 row.col fp16 MMA, fp32 accumulate
__device__ __forceinline__ void mma_f16(float* c, const uint32_t* a,
                                        uint32_t b0, uint32_t b1) {
    asm volatile(
        "mma.sync.aligned.m16n8k16.row.col.f32.f16.f16.f32 "
        "{%0,%1,%2,%3}, {%4,%5,%6,%7}, {%8,%9}, {%0,%1,%2,%3};"
        : "+f"(c[0]), "+f"(c[1]), "+f"(c[2]), "+f"(c[3])
        : "r"(a[0]), "r"(a[1]), "r"(a[2]), "r"(a[3]), "r"(b0), "r"(b1));
}

// ---------------------------------------------------------------------------
// Prepass: x (fp32 row-major [M,1024]) -> fp16 A-frag order.
// Thread owns (Mtile, chunk16 c, g): 8 LDG.128 -> 4 STG.128.
// ---------------------------------------------------------------------------
__global__ __launch_bounds__(256) void perm_a_f16(const float4* __restrict__ src,
                                                  uint4* __restrict__ dst) {
    int t = blockIdx.x * 256 + threadIdx.x;   // 512*64*8 = 262144 threads
    int g = t & 7, c = (t >> 3) & 63, Mtile = t >> 9;
    int m0 = Mtile * 16 + g;
    float f0[16], f1[16];
#pragma unroll
    for (int j = 0; j < 4; j++) {
        float4 v0 = src[m0 * 256 + c * 4 + j];
        float4 v1 = src[(m0 + 8) * 256 + c * 4 + j];
        f0[4*j+0]=v0.x; f0[4*j+1]=v0.y; f0[4*j+2]=v0.z; f0[4*j+3]=v0.w;
        f1[4*j+0]=v1.x; f1[4*j+1]=v1.y; f1[4*j+2]=v1.z; f1[4*j+3]=v1.w;
    }
    int base = (Mtile * 64 + c) * 32 + g * 4;
#pragma unroll
    for (int tig = 0; tig < 4; tig++) {
        uint4 w;
        w.x = f2h2(f0[2*tig],   f0[2*tig+1]);
        w.y = f2h2(f1[2*tig],   f1[2*tig+1]);
        w.z = f2h2(f0[2*tig+8], f0[2*tig+9]);
        w.w = f2h2(f1[2*tig+8], f1[2*tig+9]);
        dst[base + tig] = w;
    }
}

// ---------------------------------------------------------------------------
// Prepass: W (fp32 row-major [1024,N]) -> fp16 B-frag order.
// Thread owns (Ntile, Kblk8): 16 LDG.128 -> 32 STG.32.
// ---------------------------------------------------------------------------
__global__ __launch_bounds__(256) void perm_b_f16(const float4* __restrict__ src,
                                                  uint32_t* __restrict__ dst, int N) {
    int t = blockIdx.x * 256 + threadIdx.x;   // (N/8)*128 threads
    int Kblk = t & 127, Ntile = t >> 7;
    float w[8][8];
#pragma unroll
    for (int kk = 0; kk < 8; kk++) {
        int k = Kblk * 8 + kk;
        float4 wa = src[(size_t)k * (N / 4) + Ntile * 2];
        float4 wb = src[(size_t)k * (N / 4) + Ntile * 2 + 1];
        w[kk][0]=wa.x; w[kk][1]=wa.y; w[kk][2]=wa.z; w[kk][3]=wa.w;
        w[kk][4]=wb.x; w[kk][5]=wb.y; w[kk][6]=wb.z; w[kk][7]=wb.w;
    }
    int c = Kblk >> 1, kb = Kblk & 1;
    int base = (Ntile * 64 + c) * 64 + kb;    // uint index: lane*2 + kb
#pragma unroll
    for (int l = 0; l < 32; l++) {
        int g = l >> 2, tig = l & 3;
        dst[base + l * 2] = f2h2(w[2*tig][g], w[2*tig+1][g]);
    }
}

// ---------------------------------------------------------------------------
// fp16 m16n8k16 GEMM on fragment-order operands. CTA 128x128, BK=64 (4 chunks),
// 8 warps 2(M)x4(N). Inner: 4 LDS.128 + 4 LDS.64 per 16 MMAs (k16).
// MODE 0: A=g_xrw, B=g_wqkvw -> scatter fp16 q(frag,scaled)/k(bfrag)/v(rowmaj)
// MODE 1: A=g_aow, B=g_woutw -> fp32 out + bias
// ---------------------------------------------------------------------------
#define STAGE_BYTES 32768          // 16KB A + 16KB B
#define GEMM_SMEM   (2 * STAGE_BYTES)

template<int MODE>
__global__ __launch_bounds__(256) void gemm_f16(const float* __restrict__ bias,
                                                float* __restrict__ out, int Ntot) {
    extern __shared__ char smem[];
    const uint32_t sb = smem_u32(smem);
    const int tid  = threadIdx.x;
    const int lane = tid & 31;
    const int warp = tid >> 5;
    const int mw = warp & 1;
    const int nw = warp >> 1;
    const int g   = lane >> 2;
    const int tig = lane & 3;
    const int brow = blockIdx.y * 128;
    const int bcol = blockIdx.x * 128;
    const int Mtile0 = blockIdx.y * 8;
    const int Ntile0 = blockIdx.x * 16;

    const uint4* __restrict__ A4 = (const uint4*)(MODE ? g_aow : g_xrw);
    const uint4* __restrict__ B4 = (const uint4*)(MODE ? g_woutw : g_wqkvw);

    float acc[4][4][4];
#pragma unroll
    for (int i = 0; i < 4; i++)
#pragma unroll
        for (int j = 0; j < 4; j++)
#pragma unroll
            for (int q = 0; q < 4; q++) acc[i][j][q] = 0.f;

    auto issue = [&](int ic, int s) {
        const int Kc0 = ic * 4;                 // chunk16 index
        const uint32_t As = sb + (uint32_t)s * STAGE_BYTES;
        const uint32_t Bs = As + 16384u;
#pragma unroll
        for (int r = 0; r < 4; r++) {
            int idx = tid + r * 256;
            int ml = idx >> 7, c = (idx >> 5) & 3, l = idx & 31;
            cp16(As + (uint32_t)idx * 16,
                 &A4[(size_t)((Mtile0 + ml) * 64 + Kc0 + c) * 32 + l]);
        }
#pragma unroll
        for (int r = 0; r < 4; r++) {
            int idx = tid + r * 256;
            int nl = idx >> 6, c = (idx >> 4) & 3, l = idx & 15;
            cp16(Bs + (uint32_t)idx * 16,
                 &B4[(size_t)((Ntile0 + nl) * 64 + Kc0 + c) * 16 + l]);
        }
    };

    issue(0, 0);
    CP_COMMIT();

    for (int ic = 0; ic < 16; ic++) {
        const int s = ic & 1;
        if (ic + 1 < 16) {
            issue(ic + 1, s ^ 1);
            CP_COMMIT();
            CP_WAIT1();
        } else {
            CP_WAIT0();
        }
        __syncthreads();

        const uint4* As4 = (const uint4*)(smem + (size_t)s * STAGE_BYTES);
        const uint2* Bs2 = (const uint2*)(smem + (size_t)s * STAGE_BYTES + 16384);

#pragma unroll
        for (int c = 0; c < 4; c++) {
            uint4 af[4];
            uint2 bf[4];
#pragma unroll
            for (int mt = 0; mt < 4; mt++)
                af[mt] = As4[((mw * 4 + mt) * 4 + c) * 32 + lane];
#pragma unroll
            for (int nt = 0; nt < 4; nt++)
                bf[nt] = Bs2[((nw * 4 + nt) * 4 + c) * 32 + lane];
#pragma unroll
            for (int mt = 0; mt < 4; mt++)
#pragma unroll
                for (int nt = 0; nt < 4; nt++)
                    mma_f16(acc[mt][nt], (const uint32_t*)&af[mt], bf[nt].x, bf[nt].y);
        }
        __syncthreads();
    }

#pragma unroll
    for (int mt = 0; mt < 4; mt++) {
#pragma unroll
        for (int half = 0; half < 2; half++) {
            const int m = brow + mw * 64 + mt * 16 + g + half * 8;
            const int b = m >> 11, t = m & 2047;
#pragma unroll
            for (int nt = 0; nt < 4; nt++) {
                const int col = bcol + nw * 32 + nt * 8 + 2 * tig;
                float vx = acc[mt][nt][half * 2 + 0] + bias[col];
                float vy = acc[mt][nt][half * 2 + 1] + bias[col + 1];
                if (MODE == 0) {
                    const int seg = col >> 10;
                    const int dc  = col & 1023;
                    const int h = dc >> 6, hd = dc & 63;
                    const int bh = b * NHEAD + h;
                    if (seg == 0) {            // q: flash A-frag order, pre-scaled
                        uint32_t w = f2h2(vx * QSCALE, vy * QSCALE);
                        int idx = (((bh * 128 + (t >> 4)) * 4 + (hd >> 4)) * 32
                                   + g * 4 + tig) * 4 + half + 2 * ((hd >> 3) & 1);
                        g_qw[idx] = w;
                    } else if (seg == 1) {     // k: flash B-frag order
                        uint32_t w = f2h2(vx, vy);
                        int idx = (((bh * 256 + (t >> 3)) * 4 + (hd >> 4)) * 32
                                   + g * 4 + tig) * 2 + ((hd >> 3) & 1);
                        g_kw[idx] = w;
                    } else {                   // v: row-major fp16
                        g_vw[(size_t)(bh * TLEN + t) * 32 + (hd >> 1)] = f2h2(vx, vy);
                    }
                } else {
                    *(float2*)&out[(size_t)m * DMODEL + col] = make_float2(vx, vy);
                }
            }
        }
    }
}

// ---------------------------------------------------------------------------
// Flash attention, causal, fp16 m16n8k16.
// Q: NO SMEM — aq fragments loaded directly (4 LDG.128) from g_qw frag order.
// K: cp.async pure copy of B-frag-ordered window (8KB contiguous); LDS.64 b-frags.
// V: row-major fp16 LDG + byte_perm transpose-pack to Vw[k2][n] (stride 68).
// P: register-only (S c-frag == PV a-frag).
// ---------------------------------------------------------------------------
#define VW 68
#define FLASH_SMEM (8192 + 32*VW*4)   // Kb 8KB + Vw 8704B = 16896 B

__global__ __launch_bounds__(256, 2) void flash_attn_f16() {
    extern __shared__ uint32_t smw[];
    uint2*    Kb = (uint2*)smw;           // 1024 uint2
    uint32_t* Vw = smw + 2048;            // 32*68 words

    const int tid  = threadIdx.x;
    const int lane = tid & 31;
    const int warp = tid >> 5;
    const int g    = lane >> 2;
    const int tig  = lane & 3;
    const int qt = (int)gridDim.x - 1 - (int)blockIdx.x;
    const int bh = blockIdx.y;
    const int q0 = qt * 128;
    const int Mt = qt * 8 + warp;

    // Q a-fragments: direct global loads, no SMEM
    uint32_t aq[4][4];
#pragma unroll
    for (int ksc = 0; ksc < 4; ksc++) {
        uint4 w = *(const uint4*)&g_qw[(((bh * 128 + Mt) * 4 + ksc) * 32 + lane) * 4];
        aq[ksc][0] = w.x; aq[ksc][1] = w.y; aq[ksc][2] = w.z; aq[ksc][3] = w.w;
    }

    const int qrow_w = q0 + warp * 16;
    float m0 = -1e30f, m1 = -1e30f, l0 = 0.f, l1 = 0.f;
    float o[8][4];
#pragma unroll
    for (int nt = 0; nt < 8; nt++)
#pragma unroll
        for (int q = 0; q < 4; q++) o[nt][q] = 0.f;

    const uint32_t sb = smem_u32(smw);
    const int njt = 2 * qt + 2;

    for (int jt = 0; jt < njt; jt++) {
        __syncthreads();
        const int k0 = jt * 64;
        // K: contiguous 8KB copy (frag-ordered in global)
        {
            const uint4* src = (const uint4*)&g_kw[(size_t)(bh * 256 + (k0 >> 3)) * 256];
#pragma unroll
            for (int r = 0; r < 2; r++) {
                int idx = tid + r * 256;
                cp16(sb + (uint32_t)idx * 16, &src[idx]);
            }
        }
        // V: transpose-pack [k2][n] via byte_perm
        {
            int k2 = tid >> 3, c8 = tid & 7;
            const uint4* vsrc = (const uint4*)&g_vw[(size_t)(bh * TLEN + k0) * 32];
            uint4 r0 = vsrc[(2 * k2) * 8 + c8];
            uint4 r1 = vsrc[(2 * k2 + 1) * 8 + c8];
            uint4 o0, o1;
            o0.x = __byte_perm(r0.x, r1.x, 0x5410); o0.y = __byte_perm(r0.x, r1.x, 0x7632);
            o0.z = __byte_perm(r0.y, r1.y, 0x5410); o0.w = __byte_perm(r0.y, r1.y, 0x7632);
            o1.x = __byte_perm(r0.z, r1.z, 0x5410); o1.y = __byte_perm(r0.z, r1.z, 0x7632);
            o1.z = __byte_perm(r0.w, r1.w, 0x5410); o1.w = __byte_perm(r0.w, r1.w, 0x7632);
            *(uint4*)&Vw[k2 * VW + 8 * c8]     = o0;
            *(uint4*)&Vw[k2 * VW + 8 * c8 + 4] = o1;
        }
        CP_COMMIT();
        CP_WAIT0();
        __syncthreads();

        if (qrow_w + 15 < k0) continue;

        // ----- S = Q @ K^T -----
        float s[8][4];
#pragma unroll
        for (int nt = 0; nt < 8; nt++)
#pragma unroll
            for (int q = 0; q < 4; q++) s[nt][q] = 0.f;
#pragma unroll
        for (int ksc = 0; ksc < 4; ksc++) {
#pragma unroll
            for (int nt = 0; nt < 8; nt++) {
                uint2 bb = Kb[((nt * 4 + ksc) * 32) + lane];
                mma_f16(s[nt], aq[ksc], bb.x, bb.y);
            }
        }

        // ----- causal mask -----
        if (k0 + 63 > qrow_w) {
            const int row0 = qrow_w + g, row1 = row0 + 8;
#pragma unroll
            for (int nt = 0; nt < 8; nt++) {
                const int col = k0 + nt * 8 + 2 * tig;
                if (col     > row0) s[nt][0] = -1e30f;
                if (col + 1 > row0) s[nt][1] = -1e30f;
                if (col     > row1) s[nt][2] = -1e30f;
                if (col + 1 > row1) s[nt][3] = -1e30f;
            }
        }

        // ----- online softmax (log2 domain); P a-frags in registers -----
        float rm0 = -1e30f, rm1 = -1e30f;
#pragma unroll
        for (int nt = 0; nt < 8; nt++) {
            rm0 = fmaxf(rm0, fmaxf(s[nt][0], s[nt][1]));
            rm1 = fmaxf(rm1, fmaxf(s[nt][2], s[nt][3]));
        }
        rm0 = fmaxf(rm0, __shfl_xor_sync(0xffffffffu, rm0, 1));
        rm0 = fmaxf(rm0, __shfl_xor_sync(0xffffffffu, rm0, 2));
        rm1 = fmaxf(rm1, __shfl_xor_sync(0xffffffffu, rm1, 1));
        rm1 = fmaxf(rm1, __shfl_xor_sync(0xffffffffu, rm1, 2));
        const float mn0 = fmaxf(m0, rm0), mn1 = fmaxf(m1, rm1);
        const float c0 = exp2f(m0 - mn0), c1 = exp2f(m1 - mn1);
        float rs0 = 0.f, rs1 = 0.f;
        uint32_t pa[4][4];
#pragma unroll
        for (int nt = 0; nt < 8; nt++) {
            float p00 = exp2f(s[nt][0] - mn0);
            float p01 = exp2f(s[nt][1] - mn0);
            float p10 = exp2f(s[nt][2] - mn1);
            float p11 = exp2f(s[nt][3] - mn1);
            rs0 += p00 + p01;
            rs1 += p10 + p11;
            pa[nt >> 1][(nt & 1) * 2 + 0] = f2h2(p00, p01);
            pa[nt >> 1][(nt & 1) * 2 + 1] = f2h2(p10, p11);
            o[nt][0] *= c0; o[nt][1] *= c0;
            o[nt][2] *= c1; o[nt][3] *= c1;
        }
        rs0 += __shfl_xor_sync(0xffffffffu, rs0, 1);
        rs0 += __shfl_xor_sync(0xffffffffu, rs0, 2);
        rs1 += __shfl_xor_sync(0xffffffffu, rs1, 1);
        rs1 += __shfl_xor_sync(0xffffffffu, rs1, 2);
        l0 = l0 * c0 + rs0; m0 = mn0;
        l1 = l1 * c1 + rs1; m1 = mn1;

        // ----- O += P @ V -----
#pragma unroll
        for (int ksc = 0; ksc < 4; ksc++) {
#pragma unroll
            for (int nt = 0; nt < 8; nt++) {
                uint32_t b0 = Vw[(8 * ksc + tig) * VW + nt * 8 + g];
                uint32_t b1 = Vw[(8 * ksc + tig + 4) * VW + nt * 8 + g];
                mma_f16(o[nt], pa[ksc], b0, b1);
            }
        }
    }

    // ----- normalize + write g_aow in fp16 A-frag order -----
    const int b = bh >> 4;
    const int h = bh & 15;
    const float inv0 = 1.0f / l0, inv1 = 1.0f / l1;
    const int MtO = b * 128 + (q0 >> 4) + warp;
#pragma unroll
    for (int nt = 0; nt < 8; nt++) {
        const int chunk = h * 4 + (nt >> 1);
        const int base = ((MtO * 64 + chunk) * 32 + lane) * 4 + 2 * (nt & 1);
        g_aow[base]     = f2h2(o[nt][0] * inv0, o[nt][1] * inv0);
        g_aow[base + 1] = f2h2(o[nt][2] * inv1, o[nt][3] * inv1);
    }
}

// ---------------------------------------------------------------------------
extern "C" void kernel_launch(void* const* d_in, const int* in_sizes, int n_in,
                              void* d_out, int out_size) {
    const float* x     = (const float*)d_in[0];
    const float* W_qkv = (const float*)d_in[1];
    const float* b_qkv = (const float*)d_in[2];
    const float* W_out = (const float*)d_in[3];
    const float* b_out = (const float*)d_in[4];
    float* out = (float*)d_out;

    cudaFuncSetAttribute(gemm_f16<0>, cudaFuncAttributeMaxDynamicSharedMemorySize, GEMM_SMEM);
    cudaFuncSetAttribute(gemm_f16<1>, cudaFuncAttributeMaxDynamicSharedMemorySize, GEMM_SMEM);
    cudaFuncSetAttribute(flash_attn_f16, cudaFuncAttributeMaxDynamicSharedMemorySize, FLASH_SMEM);

    uint4* xr; cudaGetSymbolAddress((void**)&xr, g_xrw);
    uint32_t* wq; cudaGetSymbolAddress((void**)&wq, g_wqkvw);
    uint32_t* wo; cudaGetSymbolAddress((void**)&wo, g_woutw);

    perm_a_f16<<<1024, 256>>>((const float4*)x, xr);
    perm_b_f16<<<(3 * DMODEL / 8) * 128 / 256, 256>>>((const float4*)W_qkv, wq, 3 * DMODEL);
    perm_b_f16<<<(DMODEL / 8) * 128 / 256, 256>>>((const float4*)W_out, wo, DMODEL);

    gemm_f16<0><<<dim3(3 * DMODEL / 128, MTOT / 128), 256, GEMM_SMEM>>>(b_qkv, nullptr, 3 * DMODEL);
    flash_attn_f16<<<dim3(TLEN / 128, BATCH * NHEAD), 256, FLASH_SMEM>>>();
    gemm_f16<1><<<dim3(DMODEL / 128, MTOT / 128), 256, GEMM_SMEM>>>(b_out, out, DMODEL);
}

// round 11
// speedup vs baseline: 2.3938x; 1.0531x over previous
#include <cuda_runtime.h>
#include <cuda_fp16.h>
#include <cstdint>
#include <math.h>

// Problem constants
#define DMODEL 1024
#define TLEN   2048
#define BATCH  4
#define NHEAD  16
#define HDIM   64
#define MTOT   (BATCH*TLEN)      // 8192

#define QSCALE (0.125f * 1.44269504089f)   // 1/sqrt(64) * log2(e), folded into q

// ---------------------------------------------------------------------------
// Global scratch, all fp16 stored as uint32 half2-words.
// ---------------------------------------------------------------------------
__device__ uint32_t g_qw  [4194304];   // flash A-frag order
__device__ uint32_t g_kw  [4194304];   // flash B-frag order
__device__ uint32_t g_vw  [4194304];   // row-major [bh][t][hd>>1]
__device__ uint32_t g_vt  [4194304];   // transposed-packed [bh][k2][n]
__device__ uint32_t g_aow [4194304];   // GEMM A-frag order
__device__ uint32_t g_xrw [4194304];   // GEMM A-frag order
__device__ uint32_t g_wqkvw[1572864];  // GEMM B-frag order
__device__ uint32_t g_woutw[524288];

// ---------------------------------------------------------------------------
// Helpers
// ---------------------------------------------------------------------------
__device__ __forceinline__ uint32_t smem_u32(const void* p) {
    uint32_t a;
    asm("{ .reg .u64 t; cvta.to.shared.u64 t, %1; cvt.u32.u64 %0, t; }"
        : "=r"(a) : "l"(p));
    return a;
}

__device__ __forceinline__ uint32_t f2h2(float lo, float hi) {
    __half2 h = __floats2half2_rn(lo, hi);
    return *reinterpret_cast<uint32_t*>(&h);
}

// exp2 of two fp32 args -> half2 word (cvt.rn to f16, then ex2.approx.f16x2)
__device__ __forceinline__ uint32_t h2exp2(float a, float b) {
    uint32_t h = f2h2(a, b), r;
    asm("ex2.approx.f16x2 %0, %1;" : "=r"(r) : "r"(h));
    return r;
}

__device__ __forceinline__ void cp16(uint32_t dst, const void* src) {
    asm volatile("cp.async.cg.shared.global [%0], [%1], 16;"
                 :: "r"(dst), "l"(src) : "memory");
}
#define CP_COMMIT() asm volatile("cp.async.commit_group;" ::: "memory")
#define CP_WAIT1()  asm volatile("cp.async.wait_group 1;" ::: "memory")
#define CP_WAIT0()  asm volatile("cp.async.wait_group 0;" ::: "memory")

// m16n8k16 row.col fp16 MMA, fp32 accumulate
__device__ __forceinline__ void mma_f16(float* c, const uint32_t* a,
                                        uint32_t b0, uint32_t b1) {
    asm volatile(
        "mma.sync.aligned.m16n8k16.row.col.f32.f16.f16.f32 "
        "{%0,%1,%2,%3}, {%4,%5,%6,%7}, {%8,%9}, {%0,%1,%2,%3};"
        : "+f"(c[0]), "+f"(c[1]), "+f"(c[2]), "+f"(c[3])
        : "r"(a[0]), "r"(a[1]), "r"(a[2]), "r"(a[3]), "r"(b0), "r"(b1));
}

// ---------------------------------------------------------------------------
// Prepass: x (fp32 row-major [M,1024]) -> fp16 A-frag order.
// ---------------------------------------------------------------------------
__global__ __launch_bounds__(256) void perm_a_f16(const float4* __restrict__ src,
                                                  uint4* __restrict__ dst) {
    int t = blockIdx.x * 256 + threadIdx.x;
    int g = t & 7, c = (t >> 3) & 63, Mtile = t >> 9;
    int m0 = Mtile * 16 + g;
    float f0[16], f1[16];
#pragma unroll
    for (int j = 0; j < 4; j++) {
        float4 v0 = src[m0 * 256 + c * 4 + j];
        float4 v1 = src[(m0 + 8) * 256 + c * 4 + j];
        f0[4*j+0]=v0.x; f0[4*j+1]=v0.y; f0[4*j+2]=v0.z; f0[4*j+3]=v0.w;
        f1[4*j+0]=v1.x; f1[4*j+1]=v1.y; f1[4*j+2]=v1.z; f1[4*j+3]=v1.w;
    }
    int base = (Mtile * 64 + c) * 32 + g * 4;
#pragma unroll
    for (int tig = 0; tig < 4; tig++) {
        uint4 w;
        w.x = f2h2(f0[2*tig],   f0[2*tig+1]);
        w.y = f2h2(f1[2*tig],   f1[2*tig+1]);
        w.z = f2h2(f0[2*tig+8], f0[2*tig+9]);
        w.w = f2h2(f1[2*tig+8], f1[2*tig+9]);
        dst[base + tig] = w;
    }
}

// ---------------------------------------------------------------------------
// Prepass: W (fp32 row-major [1024,N]) -> fp16 B-frag order.
// ---------------------------------------------------------------------------
__global__ __launch_bounds__(256) void perm_b_f16(const float4* __restrict__ src,
                                                  uint32_t* __restrict__ dst, int N) {
    int t = blockIdx.x * 256 + threadIdx.x;
    int Kblk = t & 127, Ntile = t >> 7;
    float w[8][8];
#pragma unroll
    for (int kk = 0; kk < 8; kk++) {
        int k = Kblk * 8 + kk;
        float4 wa = src[(size_t)k * (N / 4) + Ntile * 2];
        float4 wb = src[(size_t)k * (N / 4) + Ntile * 2 + 1];
        w[kk][0]=wa.x; w[kk][1]=wa.y; w[kk][2]=wa.z; w[kk][3]=wa.w;
        w[kk][4]=wb.x; w[kk][5]=wb.y; w[kk][6]=wb.z; w[kk][7]=wb.w;
    }
    int c = Kblk >> 1, kb = Kblk & 1;
    int base = (Ntile * 64 + c) * 64 + kb;
#pragma unroll
    for (int l = 0; l < 32; l++) {
        int g = l >> 2, tig = l & 3;
        dst[base + l * 2] = f2h2(w[2*tig][g], w[2*tig+1][g]);
    }
}

// ---------------------------------------------------------------------------
// Prepass: g_vw (row-major fp16 [bh][t][hd]) -> g_vt transposed-packed
// [bh][k2][n]: word = (V[2k2][n], V[2k2+1][n]). Runs after qkv GEMM.
// ---------------------------------------------------------------------------
__global__ __launch_bounds__(256) void perm_v_f16() {
    int t = blockIdx.x * 256 + threadIdx.x;   // 64 bh * 1024 k2 * 8 c8 = 524288
    int c8 = t & 7, k2 = (t >> 3) & 1023, bh = t >> 13;
    const uint4* src = (const uint4*)g_vw;
    uint4 r0 = src[(size_t)(bh * 2048 + 2 * k2) * 8 + c8];
    uint4 r1 = src[(size_t)(bh * 2048 + 2 * k2 + 1) * 8 + c8];
    uint4 o0, o1;
    o0.x = __byte_perm(r0.x, r1.x, 0x5410); o0.y = __byte_perm(r0.x, r1.x, 0x7632);
    o0.z = __byte_perm(r0.y, r1.y, 0x5410); o0.w = __byte_perm(r0.y, r1.y, 0x7632);
    o1.x = __byte_perm(r0.z, r1.z, 0x5410); o1.y = __byte_perm(r0.z, r1.z, 0x7632);
    o1.z = __byte_perm(r0.w, r1.w, 0x5410); o1.w = __byte_perm(r0.w, r1.w, 0x7632);
    uint4* dst = (uint4*)g_vt;
    size_t db = (size_t)bh * 16384 + k2 * 16 + c8 * 2;
    dst[db] = o0;
    dst[db + 1] = o1;
}

// ---------------------------------------------------------------------------
// fp16 m16n8k16 GEMM on fragment-order operands (unchanged from R10).
// ---------------------------------------------------------------------------
#define STAGE_BYTES 32768
#define GEMM_SMEM   (2 * STAGE_BYTES)

template<int MODE>
__global__ __launch_bounds__(256) void gemm_f16(const float* __restrict__ bias,
                                                float* __restrict__ out, int Ntot) {
    extern __shared__ char smem[];
    const uint32_t sb = smem_u32(smem);
    const int tid  = threadIdx.x;
    const int lane = tid & 31;
    const int warp = tid >> 5;
    const int mw = warp & 1;
    const int nw = warp >> 1;
    const int g   = lane >> 2;
    const int tig = lane & 3;
    const int brow = blockIdx.y * 128;
    const int bcol = blockIdx.x * 128;
    const int Mtile0 = blockIdx.y * 8;
    const int Ntile0 = blockIdx.x * 16;

    const uint4* __restrict__ A4 = (const uint4*)(MODE ? g_aow : g_xrw);
    const uint4* __restrict__ B4 = (const uint4*)(MODE ? g_woutw : g_wqkvw);

    float acc[4][4][4];
#pragma unroll
    for (int i = 0; i < 4; i++)
#pragma unroll
        for (int j = 0; j < 4; j++)
#pragma unroll
            for (int q = 0; q < 4; q++) acc[i][j][q] = 0.f;

    auto issue = [&](int ic, int s) {
        const int Kc0 = ic * 4;
        const uint32_t As = sb + (uint32_t)s * STAGE_BYTES;
        const uint32_t Bs = As + 16384u;
#pragma unroll
        for (int r = 0; r < 4; r++) {
            int idx = tid + r * 256;
            int ml = idx >> 7, c = (idx >> 5) & 3, l = idx & 31;
            cp16(As + (uint32_t)idx * 16,
                 &A4[(size_t)((Mtile0 + ml) * 64 + Kc0 + c) * 32 + l]);
        }
#pragma unroll
        for (int r = 0; r < 4; r++) {
            int idx = tid + r * 256;
            int nl = idx >> 6, c = (idx >> 4) & 3, l = idx & 15;
            cp16(Bs + (uint32_t)idx * 16,
                 &B4[(size_t)((Ntile0 + nl) * 64 + Kc0 + c) * 16 + l]);
        }
    };

    issue(0, 0);
    CP_COMMIT();

    for (int ic = 0; ic < 16; ic++) {
        const int s = ic & 1;
        if (ic + 1 < 16) {
            issue(ic + 1, s ^ 1);
            CP_COMMIT();
            CP_WAIT1();
        } else {
            CP_WAIT0();
        }
        __syncthreads();

        const uint4* As4 = (const uint4*)(smem + (size_t)s * STAGE_BYTES);
        const uint2* Bs2 = (const uint2*)(smem + (size_t)s * STAGE_BYTES + 16384);

#pragma unroll
        for (int c = 0; c < 4; c++) {
            uint4 af[4];
            uint2 bf[4];
#pragma unroll
            for (int mt = 0; mt < 4; mt++)
                af[mt] = As4[((mw * 4 + mt) * 4 + c) * 32 + lane];
#pragma unroll
            for (int nt = 0; nt < 4; nt++)
                bf[nt] = Bs2[((nw * 4 + nt) * 4 + c) * 32 + lane];
#pragma unroll
            for (int mt = 0; mt < 4; mt++)
#pragma unroll
                for (int nt = 0; nt < 4; nt++)
                    mma_f16(acc[mt][nt], (const uint32_t*)&af[mt], bf[nt].x, bf[nt].y);
        }
        __syncthreads();
    }

#pragma unroll
    for (int mt = 0; mt < 4; mt++) {
#pragma unroll
        for (int half = 0; half < 2; half++) {
            const int m = brow + mw * 64 + mt * 16 + g + half * 8;
            const int b = m >> 11, t = m & 2047;
#pragma unroll
            for (int nt = 0; nt < 4; nt++) {
                const int col = bcol + nw * 32 + nt * 8 + 2 * tig;
                float vx = acc[mt][nt][half * 2 + 0] + bias[col];
                float vy = acc[mt][nt][half * 2 + 1] + bias[col + 1];
                if (MODE == 0) {
                    const int seg = col >> 10;
                    const int dc  = col & 1023;
                    const int h = dc >> 6, hd = dc & 63;
                    const int bh = b * NHEAD + h;
                    if (seg == 0) {
                        uint32_t w = f2h2(vx * QSCALE, vy * QSCALE);
                        int idx = (((bh * 128 + (t >> 4)) * 4 + (hd >> 4)) * 32
                                   + g * 4 + tig) * 4 + half + 2 * ((hd >> 3) & 1);
                        g_qw[idx] = w;
                    } else if (seg == 1) {
                        uint32_t w = f2h2(vx, vy);
                        int idx = (((bh * 256 + (t >> 3)) * 4 + (hd >> 4)) * 32
                                   + g * 4 + tig) * 2 + ((hd >> 3) & 1);
                        g_kw[idx] = w;
                    } else {
                        g_vw[(size_t)(bh * TLEN + t) * 32 + (hd >> 1)] = f2h2(vx, vy);
                    }
                } else {
                    *(float2*)&out[(size_t)m * DMODEL + col] = make_float2(vx, vy);
                }
            }
        }
    }
}

// ---------------------------------------------------------------------------
// Flash attention, causal, fp16 m16n8k16.
// Double-buffered KV stages (cp.async contiguous copies from frag-ordered /
// transpose-packed globals). Softmax: ex2.approx.f16x2; row sums via ones-MMA.
// ---------------------------------------------------------------------------
#define VW 68
#define STAGE_W (2048 + 32*VW)          // Kb 2048 words + Vt padded 2176 words
#define FLASH_SMEM (2 * STAGE_W * 4)    // 33792 B

__global__ __launch_bounds__(256, 2) void flash_attn_f16() {
    extern __shared__ uint32_t smw[];

    const int tid  = threadIdx.x;
    const int lane = tid & 31;
    const int warp = tid >> 5;
    const int g    = lane >> 2;
    const int tig  = lane & 3;
    const int qt = (int)gridDim.x - 1 - (int)blockIdx.x;
    const int bh = blockIdx.y;
    const int q0 = qt * 128;
    const int Mt = qt * 8 + warp;

    // Q a-fragments: direct global loads, no SMEM
    uint32_t aq[4][4];
#pragma unroll
    for (int ksc = 0; ksc < 4; ksc++) {
        uint4 w = *(const uint4*)&g_qw[(((bh * 128 + Mt) * 4 + ksc) * 32 + lane) * 4];
        aq[ksc][0] = w.x; aq[ksc][1] = w.y; aq[ksc][2] = w.z; aq[ksc][3] = w.w;
    }

    const int qrow_w = q0 + warp * 16;
    float m0 = -1e30f, m1 = -1e30f, l0 = 0.f, l1 = 0.f;
    float o[8][4];
#pragma unroll
    for (int nt = 0; nt < 8; nt++)
#pragma unroll
        for (int q = 0; q < 4; q++) o[nt][q] = 0.f;

    const uint32_t sb = smem_u32(smw);
    const int njt = 2 * qt + 2;
    const uint32_t ONES = 0x3C003C00u;

    auto issue_kv = [&](int jt, int s) {
        const uint32_t base = sb + (uint32_t)s * STAGE_W * 4;
        const uint4* srcK = (const uint4*)&g_kw[(size_t)(bh * 256 + jt * 8) * 256];
#pragma unroll
        for (int r = 0; r < 2; r++) {
            int idx = tid + r * 256;
            cp16(base + (uint32_t)idx * 16, &srcK[idx]);
        }
        const uint32_t* srcV = &g_vt[(size_t)bh * 65536 + jt * 2048];
#pragma unroll
        for (int r = 0; r < 2; r++) {
            int idx = tid + r * 256;
            int k2 = idx >> 4, c = idx & 15;
            cp16(base + (uint32_t)(2048 + k2 * VW + c * 4) * 4, &srcV[k2 * 64 + c * 4]);
        }
    };

    issue_kv(0, 0);
    CP_COMMIT();

    for (int jt = 0; jt < njt; jt++) {
        const int s = jt & 1;
        const int k0 = jt * 64;
        if (jt + 1 < njt) {
            issue_kv(jt + 1, s ^ 1);
            CP_COMMIT();
            CP_WAIT1();
        } else {
            CP_WAIT0();
        }
        __syncthreads();

        if (qrow_w + 15 >= k0) {
            const uint2*    Kb = (const uint2*)(smw + (size_t)s * STAGE_W);
            const uint32_t* Vt = smw + (size_t)s * STAGE_W + 2048;

            // ----- S = Q @ K^T -----
            float sc[8][4];
#pragma unroll
            for (int nt = 0; nt < 8; nt++)
#pragma unroll
                for (int q = 0; q < 4; q++) sc[nt][q] = 0.f;
#pragma unroll
            for (int ksc = 0; ksc < 4; ksc++) {
#pragma unroll
                for (int nt = 0; nt < 8; nt++) {
                    uint2 bb = Kb[(nt * 4 + ksc) * 32 + lane];
                    mma_f16(sc[nt], aq[ksc], bb.x, bb.y);
                }
            }

            // ----- causal mask -----
            if (k0 + 63 > qrow_w) {
                const int row0 = qrow_w + g, row1 = row0 + 8;
#pragma unroll
                for (int nt = 0; nt < 8; nt++) {
                    const int col = k0 + nt * 8 + 2 * tig;
                    if (col     > row0) sc[nt][0] = -1e30f;
                    if (col + 1 > row0) sc[nt][1] = -1e30f;
                    if (col     > row1) sc[nt][2] = -1e30f;
                    if (col + 1 > row1) sc[nt][3] = -1e30f;
                }
            }

            // ----- online softmax (log2 domain, f16x2 exp) -----
            float rm0 = -1e30f, rm1 = -1e30f;
#pragma unroll
            for (int nt = 0; nt < 8; nt++) {
                rm0 = fmaxf(rm0, fmaxf(sc[nt][0], sc[nt][1]));
                rm1 = fmaxf(rm1, fmaxf(sc[nt][2], sc[nt][3]));
            }
            rm0 = fmaxf(rm0, __shfl_xor_sync(0xffffffffu, rm0, 1));
            rm0 = fmaxf(rm0, __shfl_xor_sync(0xffffffffu, rm0, 2));
            rm1 = fmaxf(rm1, __shfl_xor_sync(0xffffffffu, rm1, 1));
            rm1 = fmaxf(rm1, __shfl_xor_sync(0xffffffffu, rm1, 2));
            const float mn0 = fmaxf(m0, rm0), mn1 = fmaxf(m1, rm1);
            const float c0 = exp2f(m0 - mn0), c1 = exp2f(m1 - mn1);
            uint32_t pa[4][4];
#pragma unroll
            for (int nt = 0; nt < 8; nt++) {
                pa[nt >> 1][(nt & 1) * 2 + 0] = h2exp2(sc[nt][0] - mn0, sc[nt][1] - mn0);
                pa[nt >> 1][(nt & 1) * 2 + 1] = h2exp2(sc[nt][2] - mn1, sc[nt][3] - mn1);
                o[nt][0] *= c0; o[nt][1] *= c0;
                o[nt][2] *= c1; o[nt][3] *= c1;
            }
            // row sums of fp16 P via ones-MMA (fp32-exact over the P used in PV)
            float rsum[4] = {0.f, 0.f, 0.f, 0.f};
#pragma unroll
            for (int ksc = 0; ksc < 4; ksc++)
                mma_f16(rsum, pa[ksc], ONES, ONES);
            l0 = l0 * c0 + rsum[0]; m0 = mn0;
            l1 = l1 * c1 + rsum[2]; m1 = mn1;

            // ----- O += P @ V -----
#pragma unroll
            for (int ksc = 0; ksc < 4; ksc++) {
#pragma unroll
                for (int nt = 0; nt < 8; nt++) {
                    uint32_t b0 = Vt[(8 * ksc + tig) * VW + nt * 8 + g];
                    uint32_t b1 = Vt[(8 * ksc + tig + 4) * VW + nt * 8 + g];
                    mma_f16(o[nt], pa[ksc], b0, b1);
                }
            }
        }
        __syncthreads();
    }

    // ----- normalize + write g_aow in fp16 A-frag order -----
    const int b = bh >> 4;
    const int h = bh & 15;
    const float inv0 = 1.0f / l0, inv1 = 1.0f / l1;
    const int MtO = b * 128 + (q0 >> 4) + warp;
#pragma unroll
    for (int nt = 0; nt < 8; nt++) {
        const int chunk = h * 4 + (nt >> 1);
        const int base = ((MtO * 64 + chunk) * 32 + lane) * 4 + 2 * (nt & 1);
        g_aow[base]     = f2h2(o[nt][0] * inv0, o[nt][1] * inv0);
        g_aow[base + 1] = f2h2(o[nt][2] * inv1, o[nt][3] * inv1);
    }
}

// ---------------------------------------------------------------------------
extern "C" void kernel_launch(void* const* d_in, const int* in_sizes, int n_in,
                              void* d_out, int out_size) {
    const float* x     = (const float*)d_in[0];
    const float* W_qkv = (const float*)d_in[1];
    const float* b_qkv = (const float*)d_in[2];
    const float* W_out = (const float*)d_in[3];
    const float* b_out = (const float*)d_in[4];
    float* out = (float*)d_out;

    cudaFuncSetAttribute(gemm_f16<0>, cudaFuncAttributeMaxDynamicSharedMemorySize, GEMM_SMEM);
    cudaFuncSetAttribute(gemm_f16<1>, cudaFuncAttributeMaxDynamicSharedMemorySize, GEMM_SMEM);
    cudaFuncSetAttribute(flash_attn_f16, cudaFuncAttributeMaxDynamicSharedMemorySize, FLASH_SMEM);

    uint4* xr; cudaGetSymbolAddress((void**)&xr, g_xrw);
    uint32_t* wq; cudaGetSymbolAddress((void**)&wq, g_wqkvw);
    uint32_t* wo; cudaGetSymbolAddress((void**)&wo, g_woutw);

    perm_a_f16<<<1024, 256>>>((const float4*)x, xr);
    perm_b_f16<<<(3 * DMODEL / 8) * 128 / 256, 256>>>((const float4*)W_qkv, wq, 3 * DMODEL);
    perm_b_f16<<<(DMODEL / 8) * 128 / 256, 256>>>((const float4*)W_out, wo, DMODEL);

    gemm_f16<0><<<dim3(3 * DMODEL / 128, MTOT / 128), 256, GEMM_SMEM>>>(b_qkv, nullptr, 3 * DMODEL);
    perm_v_f16<<<2048, 256>>>();
    flash_attn_f16<<<dim3(TLEN / 128, BATCH * NHEAD), 256, FLASH_SMEM>>>();
    gemm_f16<1><<<dim3(DMODEL / 128, MTOT / 128), 256, GEMM_SMEM>>>(b_out, out, DMODEL);
}

// round 12
// speedup vs baseline: 2.4702x; 1.0319x over previous
#include <cuda_runtime.h>
#include <cuda_fp16.h>
#include <cstdint>
#include <math.h>

// Problem constants
#define DMODEL 1024
#define TLEN   2048
#define BATCH  4
#define NHEAD  16
#define HDIM   64
#define MTOT   (BATCH*TLEN)      // 8192

#define QSCALE (0.125f * 1.44269504089f)   // 1/sqrt(64) * log2(e), folded into q

// ---------------------------------------------------------------------------
// Global scratch, all fp16 stored as uint32 half2-words.
// ---------------------------------------------------------------------------
__device__ uint32_t g_qw  [4194304];   // flash A-frag order
__device__ uint32_t g_kw  [4194304];   // flash B-frag order
__device__ uint32_t g_vw  [4194304];   // row-major [bh][t][hd>>1]
__device__ uint32_t g_vt  [4194304];   // transposed-packed [bh][k2][n]
__device__ uint32_t g_aow [4194304];   // GEMM A-frag order
__device__ uint32_t g_xrw [4194304];   // GEMM A-frag order
__device__ uint32_t g_wqkvw[1572864];  // GEMM B-frag order
__device__ uint32_t g_woutw[524288];

// ---------------------------------------------------------------------------
// Helpers
// ---------------------------------------------------------------------------
__device__ __forceinline__ uint32_t smem_u32(const void* p) {
    uint32_t a;
    asm("{ .reg .u64 t; cvta.to.shared.u64 t, %1; cvt.u32.u64 %0, t; }"
        : "=r"(a) : "l"(p));
    return a;
}

__device__ __forceinline__ uint32_t f2h2(float lo, float hi) {
    __half2 h = __floats2half2_rn(lo, hi);
    return *reinterpret_cast<uint32_t*>(&h);
}

__device__ __forceinline__ uint32_t h2exp2(float a, float b) {
    uint32_t h = f2h2(a, b), r;
    asm("ex2.approx.f16x2 %0, %1;" : "=r"(r) : "r"(h));
    return r;
}

__device__ __forceinline__ void cp16(uint32_t dst, const void* src) {
    asm volatile("cp.async.cg.shared.global [%0], [%1], 16;"
                 :: "r"(dst), "l"(src) : "memory");
}
#define CP_COMMIT() asm volatile("cp.async.commit_group;" ::: "memory")
#define CP_WAIT1()  asm volatile("cp.async.wait_group 1;" ::: "memory")
#define CP_WAIT0()  asm volatile("cp.async.wait_group 0;" ::: "memory")

// m16n8k16 row.col fp16 MMA, fp32 accumulate
__device__ __forceinline__ void mma_f16(float* c, const uint32_t* a,
                                        uint32_t b0, uint32_t b1) {
    asm volatile(
        "mma.sync.aligned.m16n8k16.row.col.f32.f16.f16.f32 "
        "{%0,%1,%2,%3}, {%4,%5,%6,%7}, {%8,%9}, {%0,%1,%2,%3};"
        : "+f"(c[0]), "+f"(c[1]), "+f"(c[2]), "+f"(c[3])
        : "r"(a[0]), "r"(a[1]), "r"(a[2]), "r"(a[3]), "r"(b0), "r"(b1));
}

// ---------------------------------------------------------------------------
// Fused prepass: x -> A-frag fp16, W_qkv/W_out -> B-frag fp16.
// Blocks [0,1024): perm_a;  [1024,1216): perm_b qkv;  [1216,1280): perm_b wout.
// ---------------------------------------------------------------------------
__device__ __forceinline__ void perm_a_body(const float4* __restrict__ src,
                                            uint4* __restrict__ dst, int t) {
    int g = t & 7, c = (t >> 3) & 63, Mtile = t >> 9;
    int m0 = Mtile * 16 + g;
    float f0[16], f1[16];
#pragma unroll
    for (int j = 0; j < 4; j++) {
        float4 v0 = src[m0 * 256 + c * 4 + j];
        float4 v1 = src[(m0 + 8) * 256 + c * 4 + j];
        f0[4*j+0]=v0.x; f0[4*j+1]=v0.y; f0[4*j+2]=v0.z; f0[4*j+3]=v0.w;
        f1[4*j+0]=v1.x; f1[4*j+1]=v1.y; f1[4*j+2]=v1.z; f1[4*j+3]=v1.w;
    }
    int base = (Mtile * 64 + c) * 32 + g * 4;
#pragma unroll
    for (int tig = 0; tig < 4; tig++) {
        uint4 w;
        w.x = f2h2(f0[2*tig],   f0[2*tig+1]);
        w.y = f2h2(f1[2*tig],   f1[2*tig+1]);
        w.z = f2h2(f0[2*tig+8], f0[2*tig+9]);
        w.w = f2h2(f1[2*tig+8], f1[2*tig+9]);
        dst[base + tig] = w;
    }
}

__device__ __forceinline__ void perm_b_body(const float4* __restrict__ src,
                                            uint32_t* __restrict__ dst, int N, int t) {
    int Kblk = t & 127, Ntile = t >> 7;
    float w[8][8];
#pragma unroll
    for (int kk = 0; kk < 8; kk++) {
        int k = Kblk * 8 + kk;
        float4 wa = src[(size_t)k * (N / 4) + Ntile * 2];
        float4 wb = src[(size_t)k * (N / 4) + Ntile * 2 + 1];
        w[kk][0]=wa.x; w[kk][1]=wa.y; w[kk][2]=wa.z; w[kk][3]=wa.w;
        w[kk][4]=wb.x; w[kk][5]=wb.y; w[kk][6]=wb.z; w[kk][7]=wb.w;
    }
    int c = Kblk >> 1, kb = Kblk & 1;
    int base = (Ntile * 64 + c) * 64 + kb;
#pragma unroll
    for (int l = 0; l < 32; l++) {
        int g = l >> 2, tig = l & 3;
        dst[base + l * 2] = f2h2(w[2*tig][g], w[2*tig+1][g]);
    }
}

__global__ __launch_bounds__(256) void perm_all(const float4* __restrict__ x,
                                                const float4* __restrict__ wqkv,
                                                const float4* __restrict__ wout) {
    int b = blockIdx.x;
    if (b < 1024) {
        perm_a_body(x, (uint4*)g_xrw, b * 256 + threadIdx.x);
    } else if (b < 1216) {
        perm_b_body(wqkv, g_wqkvw, 3 * DMODEL, (b - 1024) * 256 + threadIdx.x);
    } else {
        perm_b_body(wout, g_woutw, DMODEL, (b - 1216) * 256 + threadIdx.x);
    }
}

// ---------------------------------------------------------------------------
// Prepass: g_vw -> g_vt transposed-packed [bh][k2][n] (after qkv GEMM).
// ---------------------------------------------------------------------------
__global__ __launch_bounds__(256) void perm_v_f16() {
    int t = blockIdx.x * 256 + threadIdx.x;
    int c8 = t & 7, k2 = (t >> 3) & 1023, bh = t >> 13;
    const uint4* src = (const uint4*)g_vw;
    uint4 r0 = src[(size_t)(bh * 2048 + 2 * k2) * 8 + c8];
    uint4 r1 = src[(size_t)(bh * 2048 + 2 * k2 + 1) * 8 + c8];
    uint4 o0, o1;
    o0.x = __byte_perm(r0.x, r1.x, 0x5410); o0.y = __byte_perm(r0.x, r1.x, 0x7632);
    o0.z = __byte_perm(r0.y, r1.y, 0x5410); o0.w = __byte_perm(r0.y, r1.y, 0x7632);
    o1.x = __byte_perm(r0.z, r1.z, 0x5410); o1.y = __byte_perm(r0.z, r1.z, 0x7632);
    o1.z = __byte_perm(r0.w, r1.w, 0x5410); o1.w = __byte_perm(r0.w, r1.w, 0x7632);
    uint4* dst = (uint4*)g_vt;
    size_t db = (size_t)bh * 16384 + k2 * 16 + c8 * 2;
    dst[db] = o0;
    dst[db + 1] = o1;
}

// ---------------------------------------------------------------------------
// fp16 m16n8k16 GEMM, 3-stage cp.async pipeline, ONE barrier per K-iteration.
// ---------------------------------------------------------------------------
#define STAGE_BYTES 32768
#define GEMM_SMEM   (3 * STAGE_BYTES)      // 98304

template<int MODE>
__global__ __launch_bounds__(256) void gemm_f16(const float* __restrict__ bias,
                                                float* __restrict__ out, int Ntot) {
    extern __shared__ char smem[];
    const uint32_t sb = smem_u32(smem);
    const int tid  = threadIdx.x;
    const int lane = tid & 31;
    const int warp = tid >> 5;
    const int mw = warp & 1;
    const int nw = warp >> 1;
    const int g   = lane >> 2;
    const int tig = lane & 3;
    const int brow = blockIdx.y * 128;
    const int bcol = blockIdx.x * 128;
    const int Mtile0 = blockIdx.y * 8;
    const int Ntile0 = blockIdx.x * 16;

    const uint4* __restrict__ A4 = (const uint4*)(MODE ? g_aow : g_xrw);
    const uint4* __restrict__ B4 = (const uint4*)(MODE ? g_woutw : g_wqkvw);

    float acc[4][4][4];
#pragma unroll
    for (int i = 0; i < 4; i++)
#pragma unroll
        for (int j = 0; j < 4; j++)
#pragma unroll
            for (int q = 0; q < 4; q++) acc[i][j][q] = 0.f;

    auto issue = [&](int ic, int s) {
        const int Kc0 = ic * 4;
        const uint32_t As = sb + (uint32_t)s * STAGE_BYTES;
        const uint32_t Bs = As + 16384u;
#pragma unroll
        for (int r = 0; r < 4; r++) {
            int idx = tid + r * 256;
            int ml = idx >> 7, c = (idx >> 5) & 3, l = idx & 31;
            cp16(As + (uint32_t)idx * 16,
                 &A4[(size_t)((Mtile0 + ml) * 64 + Kc0 + c) * 32 + l]);
        }
#pragma unroll
        for (int r = 0; r < 4; r++) {
            int idx = tid + r * 256;
            int nl = idx >> 6, c = (idx >> 4) & 3, l = idx & 15;
            cp16(Bs + (uint32_t)idx * 16,
                 &B4[(size_t)((Ntile0 + nl) * 64 + Kc0 + c) * 16 + l]);
        }
    };

    issue(0, 0); CP_COMMIT();
    issue(1, 1); CP_COMMIT();

    for (int ic = 0; ic < 16; ic++) {
        if (ic + 1 < 16) { CP_WAIT1(); } else { CP_WAIT0(); }
        __syncthreads();          // single barrier per iteration

        const int s = ic % 3;
        const uint4* As4 = (const uint4*)(smem + (size_t)s * STAGE_BYTES);
        const uint2* Bs2 = (const uint2*)(smem + (size_t)s * STAGE_BYTES + 16384);

#pragma unroll
        for (int c = 0; c < 4; c++) {
            uint4 af[4];
            uint2 bf[4];
#pragma unroll
            for (int mt = 0; mt < 4; mt++)
                af[mt] = As4[((mw * 4 + mt) * 4 + c) * 32 + lane];
#pragma unroll
            for (int nt = 0; nt < 4; nt++)
                bf[nt] = Bs2[((nw * 4 + nt) * 4 + c) * 32 + lane];
#pragma unroll
            for (int mt = 0; mt < 4; mt++)
#pragma unroll
                for (int nt = 0; nt < 4; nt++)
                    mma_f16(acc[mt][nt], (const uint32_t*)&af[mt], bf[nt].x, bf[nt].y);
        }

        if (ic + 2 < 16) { issue(ic + 2, (ic + 2) % 3); CP_COMMIT(); }
    }

#pragma unroll
    for (int mt = 0; mt < 4; mt++) {
#pragma unroll
        for (int half = 0; half < 2; half++) {
            const int m = brow + mw * 64 + mt * 16 + g + half * 8;
            const int b = m >> 11, t = m & 2047;
#pragma unroll
            for (int nt = 0; nt < 4; nt++) {
                const int col = bcol + nw * 32 + nt * 8 + 2 * tig;
                float vx = acc[mt][nt][half * 2 + 0] + bias[col];
                float vy = acc[mt][nt][half * 2 + 1] + bias[col + 1];
                if (MODE == 0) {
                    const int seg = col >> 10;
                    const int dc  = col & 1023;
                    const int h = dc >> 6, hd = dc & 63;
                    const int bh = b * NHEAD + h;
                    if (seg == 0) {
                        uint32_t w = f2h2(vx * QSCALE, vy * QSCALE);
                        int idx = (((bh * 128 + (t >> 4)) * 4 + (hd >> 4)) * 32
                                   + g * 4 + tig) * 4 + half + 2 * ((hd >> 3) & 1);
                        g_qw[idx] = w;
                    } else if (seg == 1) {
                        uint32_t w = f2h2(vx, vy);
                        int idx = (((bh * 256 + (t >> 3)) * 4 + (hd >> 4)) * 32
                                   + g * 4 + tig) * 2 + ((hd >> 3) & 1);
                        g_kw[idx] = w;
                    } else {
                        g_vw[(size_t)(bh * TLEN + t) * 32 + (hd >> 1)] = f2h2(vx, vy);
                    }
                } else {
                    *(float2*)&out[(size_t)m * DMODEL + col] = make_float2(vx, vy);
                }
            }
        }
    }
}

// ---------------------------------------------------------------------------
// Flash attention, causal, fp16 m16n8k16. 3-stage KV pipeline, one barrier
// per KV tile. Softmax via ex2.approx.f16x2; row sums via ones-MMA.
// ---------------------------------------------------------------------------
#define VW 68
#define STAGE_W (2048 + 32*VW)             // 4224 words
#define FLASH_SMEM (3 * STAGE_W * 4)       // 50688 B

__global__ __launch_bounds__(256, 2) void flash_attn_f16() {
    extern __shared__ uint32_t smw[];

    const int tid  = threadIdx.x;
    const int lane = tid & 31;
    const int warp = tid >> 5;
    const int g    = lane >> 2;
    const int tig  = lane & 3;
    const int qt = (int)gridDim.x - 1 - (int)blockIdx.x;
    const int bh = blockIdx.y;
    const int q0 = qt * 128;
    const int Mt = qt * 8 + warp;

    uint32_t aq[4][4];
#pragma unroll
    for (int ksc = 0; ksc < 4; ksc++) {
        uint4 w = *(const uint4*)&g_qw[(((bh * 128 + Mt) * 4 + ksc) * 32 + lane) * 4];
        aq[ksc][0] = w.x; aq[ksc][1] = w.y; aq[ksc][2] = w.z; aq[ksc][3] = w.w;
    }

    const int qrow_w = q0 + warp * 16;
    float m0 = -1e30f, m1 = -1e30f, l0 = 0.f, l1 = 0.f;
    float o[8][4];
#pragma unroll
    for (int nt = 0; nt < 8; nt++)
#pragma unroll
        for (int q = 0; q < 4; q++) o[nt][q] = 0.f;

    const uint32_t sb = smem_u32(smw);
    const int njt = 2 * qt + 2;
    const uint32_t ONES = 0x3C003C00u;

    auto issue_kv = [&](int jt, int s) {
        const uint32_t base = sb + (uint32_t)s * STAGE_W * 4;
        const uint4* srcK = (const uint4*)&g_kw[(size_t)(bh * 256 + jt * 8) * 256];
#pragma unroll
        for (int r = 0; r < 2; r++) {
            int idx = tid + r * 256;
            cp16(base + (uint32_t)idx * 16, &srcK[idx]);
        }
        const uint32_t* srcV = &g_vt[(size_t)bh * 65536 + jt * 2048];
#pragma unroll
        for (int r = 0; r < 2; r++) {
            int idx = tid + r * 256;
            int k2 = idx >> 4, c = idx & 15;
            cp16(base + (uint32_t)(2048 + k2 * VW + c * 4) * 4, &srcV[k2 * 64 + c * 4]);
        }
    };

    issue_kv(0, 0); CP_COMMIT();
    issue_kv(1, 1); CP_COMMIT();

    for (int jt = 0; jt < njt; jt++) {
        if (jt + 1 < njt) { CP_WAIT1(); } else { CP_WAIT0(); }
        __syncthreads();          // single barrier per KV tile

        const int s = jt % 3;
        const int k0 = jt * 64;

        if (qrow_w + 15 >= k0) {
            const uint2*    Kb = (const uint2*)(smw + (size_t)s * STAGE_W);
            const uint32_t* Vt = smw + (size_t)s * STAGE_W + 2048;

            float sc[8][4];
#pragma unroll
            for (int nt = 0; nt < 8; nt++)
#pragma unroll
                for (int q = 0; q < 4; q++) sc[nt][q] = 0.f;
#pragma unroll
            for (int ksc = 0; ksc < 4; ksc++) {
#pragma unroll
                for (int nt = 0; nt < 8; nt++) {
                    uint2 bb = Kb[(nt * 4 + ksc) * 32 + lane];
                    mma_f16(sc[nt], aq[ksc], bb.x, bb.y);
                }
            }

            if (k0 + 63 > qrow_w) {
                const int row0 = qrow_w + g, row1 = row0 + 8;
#pragma unroll
                for (int nt = 0; nt < 8; nt++) {
                    const int col = k0 + nt * 8 + 2 * tig;
                    if (col     > row0) sc[nt][0] = -1e30f;
                    if (col + 1 > row0) sc[nt][1] = -1e30f;
                    if (col     > row1) sc[nt][2] = -1e30f;
                    if (col + 1 > row1) sc[nt][3] = -1e30f;
                }
            }

            float rm0 = -1e30f, rm1 = -1e30f;
#pragma unroll
            for (int nt = 0; nt < 8; nt++) {
                rm0 = fmaxf(rm0, fmaxf(sc[nt][0], sc[nt][1]));
                rm1 = fmaxf(rm1, fmaxf(sc[nt][2], sc[nt][3]));
            }
            rm0 = fmaxf(rm0, __shfl_xor_sync(0xffffffffu, rm0, 1));
            rm0 = fmaxf(rm0, __shfl_xor_sync(0xffffffffu, rm0, 2));
            rm1 = fmaxf(rm1, __shfl_xor_sync(0xffffffffu, rm1, 1));
            rm1 = fmaxf(rm1, __shfl_xor_sync(0xffffffffu, rm1, 2));
            const float mn0 = fmaxf(m0, rm0), mn1 = fmaxf(m1, rm1);
            const float c0 = exp2f(m0 - mn0), c1 = exp2f(m1 - mn1);
            uint32_t pa[4][4];
#pragma unroll
            for (int nt = 0; nt < 8; nt++) {
                pa[nt >> 1][(nt & 1) * 2 + 0] = h2exp2(sc[nt][0] - mn0, sc[nt][1] - mn0);
                pa[nt >> 1][(nt & 1) * 2 + 1] = h2exp2(sc[nt][2] - mn1, sc[nt][3] - mn1);
                o[nt][0] *= c0; o[nt][1] *= c0;
                o[nt][2] *= c1; o[nt][3] *= c1;
            }
            float rsum[4] = {0.f, 0.f, 0.f, 0.f};
#pragma unroll
            for (int ksc = 0; ksc < 4; ksc++)
                mma_f16(rsum, pa[ksc], ONES, ONES);
            l0 = l0 * c0 + rsum[0]; m0 = mn0;
            l1 = l1 * c1 + rsum[2]; m1 = mn1;

#pragma unroll
            for (int ksc = 0; ksc < 4; ksc++) {
#pragma unroll
                for (int nt = 0; nt < 8; nt++) {
                    uint32_t b0 = Vt[(8 * ksc + tig) * VW + nt * 8 + g];
                    uint32_t b1 = Vt[(8 * ksc + tig + 4) * VW + nt * 8 + g];
                    mma_f16(o[nt], pa[ksc], b0, b1);
                }
            }
        }

        if (jt + 2 < njt) { issue_kv(jt + 2, (jt + 2) % 3); CP_COMMIT(); }
    }

    // ----- normalize + write g_aow in fp16 A-frag order -----
    const int b = bh >> 4;
    const int h = bh & 15;
    const float inv0 = 1.0f / l0, inv1 = 1.0f / l1;
    const int MtO = b * 128 + (q0 >> 4) + warp;
#pragma unroll
    for (int nt = 0; nt < 8; nt++) {
        const int chunk = h * 4 + (nt >> 1);
        const int base = ((MtO * 64 + chunk) * 32 + lane) * 4 + 2 * (nt & 1);
        g_aow[base]     = f2h2(o[nt][0] * inv0, o[nt][1] * inv0);
        g_aow[base + 1] = f2h2(o[nt][2] * inv1, o[nt][3] * inv1);
    }
}

// ---------------------------------------------------------------------------
extern "C" void kernel_launch(void* const* d_in, const int* in_sizes, int n_in,
                              void* d_out, int out_size) {
    const float* x     = (const float*)d_in[0];
    const float* W_qkv = (const float*)d_in[1];
    const float* b_qkv = (const float*)d_in[2];
    const float* W_out = (const float*)d_in[3];
    const float* b_out = (const float*)d_in[4];
    float* out = (float*)d_out;

    cudaFuncSetAttribute(gemm_f16<0>, cudaFuncAttributeMaxDynamicSharedMemorySize, GEMM_SMEM);
    cudaFuncSetAttribute(gemm_f16<1>, cudaFuncAttributeMaxDynamicSharedMemorySize, GEMM_SMEM);
    cudaFuncSetAttribute(flash_attn_f16, cudaFuncAttributeMaxDynamicSharedMemorySize, FLASH_SMEM);

    perm_all<<<1280, 256>>>((const float4*)x, (const float4*)W_qkv, (const float4*)W_out);

    gemm_f16<0><<<dim3(3 * DMODEL / 128, MTOT / 128), 256, GEMM_SMEM>>>(b_qkv, nullptr, 3 * DMODEL);
    perm_v_f16<<<2048, 256>>>();
    flash_attn_f16<<<dim3(TLEN / 128, BATCH * NHEAD), 256, FLASH_SMEM>>>();
    gemm_f16<1><<<dim3(DMODEL / 128, MTOT / 128), 256, GEMM_SMEM>>>(b_out, out, DMODEL);
}

// round 13
// speedup vs baseline: 2.5507x; 1.0326x over previous
#include <cuda_runtime.h>
#include <cuda_fp16.h>
#include <cstdint>
#include <math.h>

// Problem constants
#define DMODEL 1024
#define TLEN   2048
#define BATCH  4
#define NHEAD  16
#define HDIM   64
#define MTOT   (BATCH*TLEN)      // 8192

#define QSCALE (0.125f * 1.44269504089f)   // 1/sqrt(64) * log2(e), folded into q

// ---------------------------------------------------------------------------
// Global scratch, all fp16 stored as uint32 half2-words.
// ---------------------------------------------------------------------------
__device__ uint32_t g_qw  [4194304];   // flash A-frag order
__device__ uint32_t g_kw  [4194304];   // flash B-frag order
__device__ uint32_t g_vw  [4194304];   // row-major [bh][t][hd>>1]
__device__ uint32_t g_vt  [4194304];   // flash B-frag order (per 64-row window)
__device__ uint32_t g_aow [4194304];   // GEMM A-frag order
__device__ uint32_t g_xrw [4194304];   // GEMM A-frag order
__device__ uint32_t g_wqkvw[1572864];  // GEMM B-frag order
__device__ uint32_t g_woutw[524288];

// ---------------------------------------------------------------------------
// Helpers
// ---------------------------------------------------------------------------
__device__ __forceinline__ uint32_t smem_u32(const void* p) {
    uint32_t a;
    asm("{ .reg .u64 t; cvta.to.shared.u64 t, %1; cvt.u32.u64 %0, t; }"
        : "=r"(a) : "l"(p));
    return a;
}

__device__ __forceinline__ uint32_t f2h2(float lo, float hi) {
    __half2 h = __floats2half2_rn(lo, hi);
    return *reinterpret_cast<uint32_t*>(&h);
}

__device__ __forceinline__ uint32_t h2exp2(float a, float b) {
    uint32_t h = f2h2(a, b), r;
    asm("ex2.approx.f16x2 %0, %1;" : "=r"(r) : "r"(h));
    return r;
}

__device__ __forceinline__ void cp16(uint32_t dst, const void* src) {
    asm volatile("cp.async.cg.shared.global [%0], [%1], 16;"
                 :: "r"(dst), "l"(src) : "memory");
}
#define CP_COMMIT() asm volatile("cp.async.commit_group;" ::: "memory")
#define CP_WAIT1()  asm volatile("cp.async.wait_group 1;" ::: "memory")
#define CP_WAIT0()  asm volatile("cp.async.wait_group 0;" ::: "memory")

// m16n8k16 row.col fp16 MMA, fp32 accumulate
__device__ __forceinline__ void mma_f16(float* c, const uint32_t* a,
                                        uint32_t b0, uint32_t b1) {
    asm volatile(
        "mma.sync.aligned.m16n8k16.row.col.f32.f16.f16.f32 "
        "{%0,%1,%2,%3}, {%4,%5,%6,%7}, {%8,%9}, {%0,%1,%2,%3};"
        : "+f"(c[0]), "+f"(c[1]), "+f"(c[2]), "+f"(c[3])
        : "r"(a[0]), "r"(a[1]), "r"(a[2]), "r"(a[3]), "r"(b0), "r"(b1));
}

// ---------------------------------------------------------------------------
// Fused prepass: x -> A-frag fp16, W_qkv/W_out -> B-frag fp16.
// ---------------------------------------------------------------------------
__device__ __forceinline__ void perm_a_body(const float4* __restrict__ src,
                                            uint4* __restrict__ dst, int t) {
    int g = t & 7, c = (t >> 3) & 63, Mtile = t >> 9;
    int m0 = Mtile * 16 + g;
    float f0[16], f1[16];
#pragma unroll
    for (int j = 0; j < 4; j++) {
        float4 v0 = src[m0 * 256 + c * 4 + j];
        float4 v1 = src[(m0 + 8) * 256 + c * 4 + j];
        f0[4*j+0]=v0.x; f0[4*j+1]=v0.y; f0[4*j+2]=v0.z; f0[4*j+3]=v0.w;
        f1[4*j+0]=v1.x; f1[4*j+1]=v1.y; f1[4*j+2]=v1.z; f1[4*j+3]=v1.w;
    }
    int base = (Mtile * 64 + c) * 32 + g * 4;
#pragma unroll
    for (int tig = 0; tig < 4; tig++) {
        uint4 w;
        w.x = f2h2(f0[2*tig],   f0[2*tig+1]);
        w.y = f2h2(f1[2*tig],   f1[2*tig+1]);
        w.z = f2h2(f0[2*tig+8], f0[2*tig+9]);
        w.w = f2h2(f1[2*tig+8], f1[2*tig+9]);
        dst[base + tig] = w;
    }
}

__device__ __forceinline__ void perm_b_body(const float4* __restrict__ src,
                                            uint32_t* __restrict__ dst, int N, int t) {
    int Kblk = t & 127, Ntile = t >> 7;
    float w[8][8];
#pragma unroll
    for (int kk = 0; kk < 8; kk++) {
        int k = Kblk * 8 + kk;
        float4 wa = src[(size_t)k * (N / 4) + Ntile * 2];
        float4 wb = src[(size_t)k * (N / 4) + Ntile * 2 + 1];
        w[kk][0]=wa.x; w[kk][1]=wa.y; w[kk][2]=wa.z; w[kk][3]=wa.w;
        w[kk][4]=wb.x; w[kk][5]=wb.y; w[kk][6]=wb.z; w[kk][7]=wb.w;
    }
    int c = Kblk >> 1, kb = Kblk & 1;
    int base = (Ntile * 64 + c) * 64 + kb;
#pragma unroll
    for (int l = 0; l < 32; l++) {
        int g = l >> 2, tig = l & 3;
        dst[base + l * 2] = f2h2(w[2*tig][g], w[2*tig+1][g]);
    }
}

__global__ __launch_bounds__(256) void perm_all(const float4* __restrict__ x,
                                                const float4* __restrict__ wqkv,
                                                const float4* __restrict__ wout) {
    int b = blockIdx.x;
    if (b < 1024) {
        perm_a_body(x, (uint4*)g_xrw, b * 256 + threadIdx.x);
    } else if (b < 1216) {
        perm_b_body(wqkv, g_wqkvw, 3 * DMODEL, (b - 1024) * 256 + threadIdx.x);
    } else {
        perm_b_body(wout, g_woutw, DMODEL, (b - 1216) * 256 + threadIdx.x);
    }
}

// ---------------------------------------------------------------------------
// Prepass: g_vw (row-major) -> g_vt in flash B-frag order per 64-row window:
// g_vt[(bh*32+win)*2048 + ((nt*4+ksc)*32 + lane)*2 + b]
//   b=0: (V[K+2tig][n], V[K+2tig+1][n]),  b=1: (V[K+8+2tig][n], V[K+9+2tig][n])
//   K = win*64 + ksc*16, n = nt*8 + g.
// ---------------------------------------------------------------------------
__global__ __launch_bounds__(256) void perm_v_f16() {
    int t = blockIdx.x * 256 + threadIdx.x;   // 2,097,152 threads
    int lane = t & 31;
    int fr   = (t >> 5) & 31;
    int win  = (t >> 10) & 31;
    int bh   = t >> 15;
    int g = lane >> 2, tig = lane & 3;
    int nt = fr >> 2, ksc = fr & 3;
    int n = nt * 8 + g;
    int j = n >> 1;
    uint32_t sel = (n & 1) ? 0x7632u : 0x5410u;
    int K = win * 64 + ksc * 16 + 2 * tig;
    const uint32_t* src = g_vw + (size_t)bh * 65536;
    uint32_t w0 = src[(K + 0) * 32 + j];
    uint32_t w1 = src[(K + 1) * 32 + j];
    uint32_t w8 = src[(K + 8) * 32 + j];
    uint32_t w9 = src[(K + 9) * 32 + j];
    uint2 o;
    o.x = __byte_perm(w0, w1, sel);
    o.y = __byte_perm(w8, w9, sel);
    *(uint2*)&g_vt[(size_t)(bh * 32 + win) * 2048 + (fr * 32 + lane) * 2] = o;
}

// ---------------------------------------------------------------------------
// fp16 m16n8k16 GEMM, 3-stage cp.async pipeline, one barrier per K-iteration.
// ---------------------------------------------------------------------------
#define STAGE_BYTES 32768
#define GEMM_SMEM   (3 * STAGE_BYTES)      // 98304

template<int MODE>
__global__ __launch_bounds__(256) void gemm_f16(const float* __restrict__ bias,
                                                float* __restrict__ out, int Ntot) {
    extern __shared__ char smem[];
    const uint32_t sb = smem_u32(smem);
    const int tid  = threadIdx.x;
    const int lane = tid & 31;
    const int warp = tid >> 5;
    const int mw = warp & 1;
    const int nw = warp >> 1;
    const int g   = lane >> 2;
    const int tig = lane & 3;
    const int brow = blockIdx.y * 128;
    const int bcol = blockIdx.x * 128;
    const int Mtile0 = blockIdx.y * 8;
    const int Ntile0 = blockIdx.x * 16;

    const uint4* __restrict__ A4 = (const uint4*)(MODE ? g_aow : g_xrw);
    const uint4* __restrict__ B4 = (const uint4*)(MODE ? g_woutw : g_wqkvw);

    float acc[4][4][4];
#pragma unroll
    for (int i = 0; i < 4; i++)
#pragma unroll
        for (int j = 0; j < 4; j++)
#pragma unroll
            for (int q = 0; q < 4; q++) acc[i][j][q] = 0.f;

    auto issue = [&](int ic, int s) {
        const int Kc0 = ic * 4;
        const uint32_t As = sb + (uint32_t)s * STAGE_BYTES;
        const uint32_t Bs = As + 16384u;
#pragma unroll
        for (int r = 0; r < 4; r++) {
            int idx = tid + r * 256;
            int ml = idx >> 7, c = (idx >> 5) & 3, l = idx & 31;
            cp16(As + (uint32_t)idx * 16,
                 &A4[(size_t)((Mtile0 + ml) * 64 + Kc0 + c) * 32 + l]);
        }
#pragma unroll
        for (int r = 0; r < 4; r++) {
            int idx = tid + r * 256;
            int nl = idx >> 6, c = (idx >> 4) & 3, l = idx & 15;
            cp16(Bs + (uint32_t)idx * 16,
                 &B4[(size_t)((Ntile0 + nl) * 64 + Kc0 + c) * 16 + l]);
        }
    };

    issue(0, 0); CP_COMMIT();
    issue(1, 1); CP_COMMIT();

    for (int ic = 0; ic < 16; ic++) {
        if (ic + 1 < 16) { CP_WAIT1(); } else { CP_WAIT0(); }
        __syncthreads();

        const int s = ic % 3;
        const uint4* As4 = (const uint4*)(smem + (size_t)s * STAGE_BYTES);
        const uint2* Bs2 = (const uint2*)(smem + (size_t)s * STAGE_BYTES + 16384);

#pragma unroll
        for (int c = 0; c < 4; c++) {
            uint4 af[4];
            uint2 bf[4];
#pragma unroll
            for (int mt = 0; mt < 4; mt++)
                af[mt] = As4[((mw * 4 + mt) * 4 + c) * 32 + lane];
#pragma unroll
            for (int nt = 0; nt < 4; nt++)
                bf[nt] = Bs2[((nw * 4 + nt) * 4 + c) * 32 + lane];
#pragma unroll
            for (int mt = 0; mt < 4; mt++)
#pragma unroll
                for (int nt = 0; nt < 4; nt++)
                    mma_f16(acc[mt][nt], (const uint32_t*)&af[mt], bf[nt].x, bf[nt].y);
        }

        if (ic + 2 < 16) { issue(ic + 2, (ic + 2) % 3); CP_COMMIT(); }
    }

#pragma unroll
    for (int mt = 0; mt < 4; mt++) {
#pragma unroll
        for (int half = 0; half < 2; half++) {
            const int m = brow + mw * 64 + mt * 16 + g + half * 8;
            const int b = m >> 11, t = m & 2047;
#pragma unroll
            for (int nt = 0; nt < 4; nt++) {
                const int col = bcol + nw * 32 + nt * 8 + 2 * tig;
                float vx = acc[mt][nt][half * 2 + 0] + bias[col];
                float vy = acc[mt][nt][half * 2 + 1] + bias[col + 1];
                if (MODE == 0) {
                    const int seg = col >> 10;
                    const int dc  = col & 1023;
                    const int h = dc >> 6, hd = dc & 63;
                    const int bh = b * NHEAD + h;
                    if (seg == 0) {
                        uint32_t w = f2h2(vx * QSCALE, vy * QSCALE);
                        int idx = (((bh * 128 + (t >> 4)) * 4 + (hd >> 4)) * 32
                                   + g * 4 + tig) * 4 + half + 2 * ((hd >> 3) & 1);
                        g_qw[idx] = w;
                    } else if (seg == 1) {
                        uint32_t w = f2h2(vx, vy);
                        int idx = (((bh * 256 + (t >> 3)) * 4 + (hd >> 4)) * 32
                                   + g * 4 + tig) * 2 + ((hd >> 3) & 1);
                        g_kw[idx] = w;
                    } else {
                        g_vw[(size_t)(bh * TLEN + t) * 32 + (hd >> 1)] = f2h2(vx, vy);
                    }
                } else {
                    *(float2*)&out[(size_t)m * DMODEL + col] = make_float2(vx, vy);
                }
            }
        }
    }
}

// ---------------------------------------------------------------------------
// Flash attention, causal, fp16 m16n8k16. 3-stage KV pipeline, one barrier
// per KV tile. K and V both in B-frag order: fills are contiguous copies,
// all fragment loads are coalesced LDS.64.
// ---------------------------------------------------------------------------
#define STAGE_W 4096                        // 2048 K words + 2048 V words
#define FLASH_SMEM (3 * STAGE_W * 4)        // 49152 B

__global__ __launch_bounds__(256, 2) void flash_attn_f16() {
    extern __shared__ uint32_t smw[];

    const int tid  = threadIdx.x;
    const int lane = tid & 31;
    const int warp = tid >> 5;
    const int g    = lane >> 2;
    const int tig  = lane & 3;
    const int qt = (int)gridDim.x - 1 - (int)blockIdx.x;
    const int bh = blockIdx.y;
    const int q0 = qt * 128;
    const int Mt = qt * 8 + warp;

    uint32_t aq[4][4];
#pragma unroll
    for (int ksc = 0; ksc < 4; ksc++) {
        uint4 w = *(const uint4*)&g_qw[(((bh * 128 + Mt) * 4 + ksc) * 32 + lane) * 4];
        aq[ksc][0] = w.x; aq[ksc][1] = w.y; aq[ksc][2] = w.z; aq[ksc][3] = w.w;
    }

    const int qrow_w = q0 + warp * 16;
    float m0 = -1e30f, m1 = -1e30f, l0 = 0.f, l1 = 0.f;
    float o[8][4];
#pragma unroll
    for (int nt = 0; nt < 8; nt++)
#pragma unroll
        for (int q = 0; q < 4; q++) o[nt][q] = 0.f;

    const uint32_t sb = smem_u32(smw);
    const int njt = 2 * qt + 2;
    const uint32_t ONES = 0x3C003C00u;

    auto issue_kv = [&](int jt, int s) {
        const uint32_t base = sb + (uint32_t)s * STAGE_W * 4;
        const uint4* srcK = (const uint4*)&g_kw[(size_t)(bh * 256 + jt * 8) * 256];
#pragma unroll
        for (int r = 0; r < 2; r++) {
            int idx = tid + r * 256;
            cp16(base + (uint32_t)idx * 16, &srcK[idx]);
        }
        const uint4* srcV = (const uint4*)&g_vt[(size_t)(bh * 32 + jt) * 2048];
#pragma unroll
        for (int r = 0; r < 2; r++) {
            int idx = tid + r * 256;
            cp16(base + 8192u + (uint32_t)idx * 16, &srcV[idx]);
        }
    };

    issue_kv(0, 0); CP_COMMIT();
    issue_kv(1, 1); CP_COMMIT();

    for (int jt = 0; jt < njt; jt++) {
        if (jt + 1 < njt) { CP_WAIT1(); } else { CP_WAIT0(); }
        __syncthreads();

        const int s = jt % 3;
        const int k0 = jt * 64;

        if (qrow_w + 15 >= k0) {
            const uint2* Kb = (const uint2*)(smw + (size_t)s * STAGE_W);
            const uint2* Vb = (const uint2*)(smw + (size_t)s * STAGE_W + 2048);

            float sc[8][4];
#pragma unroll
            for (int nt = 0; nt < 8; nt++)
#pragma unroll
                for (int q = 0; q < 4; q++) sc[nt][q] = 0.f;
#pragma unroll
            for (int ksc = 0; ksc < 4; ksc++) {
#pragma unroll
                for (int nt = 0; nt < 8; nt++) {
                    uint2 bb = Kb[(nt * 4 + ksc) * 32 + lane];
                    mma_f16(sc[nt], aq[ksc], bb.x, bb.y);
                }
            }

            if (k0 + 63 > qrow_w) {
                const int row0 = qrow_w + g, row1 = row0 + 8;
#pragma unroll
                for (int nt = 0; nt < 8; nt++) {
                    const int col = k0 + nt * 8 + 2 * tig;
                    if (col     > row0) sc[nt][0] = -1e30f;
                    if (col + 1 > row0) sc[nt][1] = -1e30f;
                    if (col     > row1) sc[nt][2] = -1e30f;
                    if (col + 1 > row1) sc[nt][3] = -1e30f;
                }
            }

            float rm0 = -1e30f, rm1 = -1e30f;
#pragma unroll
            for (int nt = 0; nt < 8; nt++) {
                rm0 = fmaxf(rm0, fmaxf(sc[nt][0], sc[nt][1]));
                rm1 = fmaxf(rm1, fmaxf(sc[nt][2], sc[nt][3]));
            }
            rm0 = fmaxf(rm0, __shfl_xor_sync(0xffffffffu, rm0, 1));
            rm0 = fmaxf(rm0, __shfl_xor_sync(0xffffffffu, rm0, 2));
            rm1 = fmaxf(rm1, __shfl_xor_sync(0xffffffffu, rm1, 1));
            rm1 = fmaxf(rm1, __shfl_xor_sync(0xffffffffu, rm1, 2));
            const float mn0 = fmaxf(m0, rm0), mn1 = fmaxf(m1, rm1);
            const float c0 = exp2f(m0 - mn0), c1 = exp2f(m1 - mn1);
            uint32_t pa[4][4];
#pragma unroll
            for (int nt = 0; nt < 8; nt++) {
                pa[nt >> 1][(nt & 1) * 2 + 0] = h2exp2(sc[nt][0] - mn0, sc[nt][1] - mn0);
                pa[nt >> 1][(nt & 1) * 2 + 1] = h2exp2(sc[nt][2] - mn1, sc[nt][3] - mn1);
                o[nt][0] *= c0; o[nt][1] *= c0;
                o[nt][2] *= c1; o[nt][3] *= c1;
            }
            float rsum[4] = {0.f, 0.f, 0.f, 0.f};
#pragma unroll
            for (int ksc = 0; ksc < 4; ksc++)
                mma_f16(rsum, pa[ksc], ONES, ONES);
            l0 = l0 * c0 + rsum[0]; m0 = mn0;
            l1 = l1 * c1 + rsum[2]; m1 = mn1;

#pragma unroll
            for (int ksc = 0; ksc < 4; ksc++) {
#pragma unroll
                for (int nt = 0; nt < 8; nt++) {
                    uint2 bb = Vb[(nt * 4 + ksc) * 32 + lane];
                    mma_f16(o[nt], pa[ksc], bb.x, bb.y);
                }
            }
        }

        if (jt + 2 < njt) { issue_kv(jt + 2, (jt + 2) % 3); CP_COMMIT(); }
    }

    // ----- normalize + write g_aow in fp16 A-frag order -----
    const int b = bh >> 4;
    const int h = bh & 15;
    const float inv0 = 1.0f / l0, inv1 = 1.0f / l1;
    const int MtO = b * 128 + (q0 >> 4) + warp;
#pragma unroll
    for (int nt = 0; nt < 8; nt++) {
        const int chunk = h * 4 + (nt >> 1);
        const int base = ((MtO * 64 + chunk) * 32 + lane) * 4 + 2 * (nt & 1);
        g_aow[base]     = f2h2(o[nt][0] * inv0, o[nt][1] * inv0);
        g_aow[base + 1] = f2h2(o[nt][2] * inv1, o[nt][3] * inv1);
    }
}

// ---------------------------------------------------------------------------
extern "C" void kernel_launch(void* const* d_in, const int* in_sizes, int n_in,
                              void* d_out, int out_size) {
    const float* x     = (const float*)d_in[0];
    const float* W_qkv = (const float*)d_in[1];
    const float* b_qkv = (const float*)d_in[2];
    const float* W_out = (const float*)d_in[3];
    const float* b_out = (const float*)d_in[4];
    float* out = (float*)d_out;

    cudaFuncSetAttribute(gemm_f16<0>, cudaFuncAttributeMaxDynamicSharedMemorySize, GEMM_SMEM);
    cudaFuncSetAttribute(gemm_f16<1>, cudaFuncAttributeMaxDynamicSharedMemorySize, GEMM_SMEM);
    cudaFuncSetAttribute(flash_attn_f16, cudaFuncAttributeMaxDynamicSharedMemorySize, FLASH_SMEM);

    perm_all<<<1280, 256>>>((const float4*)x, (const float4*)W_qkv, (const float4*)W_out);

    gemm_f16<0><<<dim3(3 * DMODEL / 128, MTOT / 128), 256, GEMM_SMEM>>>(b_qkv, nullptr, 3 * DMODEL);
    perm_v_f16<<<8192, 256>>>();
    flash_attn_f16<<<dim3(TLEN / 128, BATCH * NHEAD), 256, FLASH_SMEM>>>();
    gemm_f16<1><<<dim3(DMODEL / 128, MTOT / 128), 256, GEMM_SMEM>>>(b_out, out, DMODEL);
}

// round 14
// speedup vs baseline: 2.5943x; 1.0171x over previous
#include <cuda_runtime.h>
#include <cuda_fp16.h>
#include <cstdint>
#include <math.h>

// Problem constants
#define DMODEL 1024
#define TLEN   2048
#define BATCH  4
#define NHEAD  16
#define HDIM   64
#define MTOT   (BATCH*TLEN)      // 8192

#define QSCALE (0.125f * 1.44269504089f)   // 1/sqrt(64) * log2(e), folded into q

// ---------------------------------------------------------------------------
// Global scratch, all fp16 stored as uint32 half2-words.
// ---------------------------------------------------------------------------
__device__ uint32_t g_qw  [4194304];   // flash A-frag order
__device__ uint32_t g_kw  [4194304];   // flash B-frag order
__device__ uint32_t g_vw  [4194304];   // row-major [bh][t][hd>>1]
__device__ uint32_t g_vt  [4194304];   // flash B-frag order (per 64-row window)
__device__ uint32_t g_aow [4194304];   // GEMM A-frag order
__device__ uint32_t g_xrw [4194304];   // GEMM A-frag order
__device__ uint32_t g_wqkvw[1572864];  // GEMM B-frag order
__device__ uint32_t g_woutw[524288];

// ---------------------------------------------------------------------------
// Helpers
// ---------------------------------------------------------------------------
__device__ __forceinline__ uint32_t smem_u32(const void* p) {
    uint32_t a;
    asm("{ .reg .u64 t; cvta.to.shared.u64 t, %1; cvt.u32.u64 %0, t; }"
        : "=r"(a) : "l"(p));
    return a;
}

__device__ __forceinline__ uint32_t f2h2(float lo, float hi) {
    __half2 h = __floats2half2_rn(lo, hi);
    return *reinterpret_cast<uint32_t*>(&h);
}

__device__ __forceinline__ uint32_t h2exp2(float a, float b) {
    uint32_t h = f2h2(a, b), r;
    asm("ex2.approx.f16x2 %0, %1;" : "=r"(r) : "r"(h));
    return r;
}

__device__ __forceinline__ void cp16(uint32_t dst, const void* src) {
    asm volatile("cp.async.cg.shared.global [%0], [%1], 16;"
                 :: "r"(dst), "l"(src) : "memory");
}
#define CP_COMMIT() asm volatile("cp.async.commit_group;" ::: "memory")
#define CP_WAIT1()  asm volatile("cp.async.wait_group 1;" ::: "memory")
#define CP_WAIT0()  asm volatile("cp.async.wait_group 0;" ::: "memory")

// m16n8k16 row.col fp16 MMA, fp32 accumulate
__device__ __forceinline__ void mma_f16(float* c, const uint32_t* a,
                                        uint32_t b0, uint32_t b1) {
    asm volatile(
        "mma.sync.aligned.m16n8k16.row.col.f32.f16.f16.f32 "
        "{%0,%1,%2,%3}, {%4,%5,%6,%7}, {%8,%9}, {%0,%1,%2,%3};"
        : "+f"(c[0]), "+f"(c[1]), "+f"(c[2]), "+f"(c[3])
        : "r"(a[0]), "r"(a[1]), "r"(a[2]), "r"(a[3]), "r"(b0), "r"(b1));
}

// ---------------------------------------------------------------------------
// Fused prepass: x -> A-frag fp16, W_qkv/W_out -> B-frag fp16.
// ---------------------------------------------------------------------------
__device__ __forceinline__ void perm_a_body(const float4* __restrict__ src,
                                            uint4* __restrict__ dst, int t) {
    int g = t & 7, c = (t >> 3) & 63, Mtile = t >> 9;
    int m0 = Mtile * 16 + g;
    float f0[16], f1[16];
#pragma unroll
    for (int j = 0; j < 4; j++) {
        float4 v0 = src[m0 * 256 + c * 4 + j];
        float4 v1 = src[(m0 + 8) * 256 + c * 4 + j];
        f0[4*j+0]=v0.x; f0[4*j+1]=v0.y; f0[4*j+2]=v0.z; f0[4*j+3]=v0.w;
        f1[4*j+0]=v1.x; f1[4*j+1]=v1.y; f1[4*j+2]=v1.z; f1[4*j+3]=v1.w;
    }
    int base = (Mtile * 64 + c) * 32 + g * 4;
#pragma unroll
    for (int tig = 0; tig < 4; tig++) {
        uint4 w;
        w.x = f2h2(f0[2*tig],   f0[2*tig+1]);
        w.y = f2h2(f1[2*tig],   f1[2*tig+1]);
        w.z = f2h2(f0[2*tig+8], f0[2*tig+9]);
        w.w = f2h2(f1[2*tig+8], f1[2*tig+9]);
        dst[base + tig] = w;
    }
}

__device__ __forceinline__ void perm_b_body(const float4* __restrict__ src,
                                            uint32_t* __restrict__ dst, int N, int t) {
    int Kblk = t & 127, Ntile = t >> 7;
    float w[8][8];
#pragma unroll
    for (int kk = 0; kk < 8; kk++) {
        int k = Kblk * 8 + kk;
        float4 wa = src[(size_t)k * (N / 4) + Ntile * 2];
        float4 wb = src[(size_t)k * (N / 4) + Ntile * 2 + 1];
        w[kk][0]=wa.x; w[kk][1]=wa.y; w[kk][2]=wa.z; w[kk][3]=wa.w;
        w[kk][4]=wb.x; w[kk][5]=wb.y; w[kk][6]=wb.z; w[kk][7]=wb.w;
    }
    int c = Kblk >> 1, kb = Kblk & 1;
    int base = (Ntile * 64 + c) * 64 + kb;
#pragma unroll
    for (int l = 0; l < 32; l++) {
        int g = l >> 2, tig = l & 3;
        dst[base + l * 2] = f2h2(w[2*tig][g], w[2*tig+1][g]);
    }
}

__global__ __launch_bounds__(256) void perm_all(const float4* __restrict__ x,
                                                const float4* __restrict__ wqkv,
                                                const float4* __restrict__ wout) {
    int b = blockIdx.x;
    if (b < 1024) {
        perm_a_body(x, (uint4*)g_xrw, b * 256 + threadIdx.x);
    } else if (b < 1216) {
        perm_b_body(wqkv, g_wqkvw, 3 * DMODEL, (b - 1024) * 256 + threadIdx.x);
    } else {
        perm_b_body(wout, g_woutw, DMODEL, (b - 1216) * 256 + threadIdx.x);
    }
}

// ---------------------------------------------------------------------------
// Prepass: g_vw (row-major) -> g_vt in flash B-frag order per 64-row window.
// ---------------------------------------------------------------------------
__global__ __launch_bounds__(256) void perm_v_f16() {
    int t = blockIdx.x * 256 + threadIdx.x;
    int lane = t & 31;
    int fr   = (t >> 5) & 31;
    int win  = (t >> 10) & 31;
    int bh   = t >> 15;
    int g = lane >> 2, tig = lane & 3;
    int nt = fr >> 2, ksc = fr & 3;
    int n = nt * 8 + g;
    int j = n >> 1;
    uint32_t sel = (n & 1) ? 0x7632u : 0x5410u;
    int K = win * 64 + ksc * 16 + 2 * tig;
    const uint32_t* src = g_vw + (size_t)bh * 65536;
    uint32_t w0 = src[(K + 0) * 32 + j];
    uint32_t w1 = src[(K + 1) * 32 + j];
    uint32_t w8 = src[(K + 8) * 32 + j];
    uint32_t w9 = src[(K + 9) * 32 + j];
    uint2 o;
    o.x = __byte_perm(w0, w1, sel);
    o.y = __byte_perm(w8, w9, sel);
    *(uint2*)&g_vt[(size_t)(bh * 32 + win) * 2048 + (fr * 32 + lane) * 2] = o;
}

// ---------------------------------------------------------------------------
// fp16 m16n8k16 GEMM, 3-stage cp.async pipeline (unchanged from R13).
// ---------------------------------------------------------------------------
#define STAGE_BYTES 32768
#define GEMM_SMEM   (3 * STAGE_BYTES)      // 98304

template<int MODE>
__global__ __launch_bounds__(256) void gemm_f16(const float* __restrict__ bias,
                                                float* __restrict__ out, int Ntot) {
    extern __shared__ char smem[];
    const uint32_t sb = smem_u32(smem);
    const int tid  = threadIdx.x;
    const int lane = tid & 31;
    const int warp = tid >> 5;
    const int mw = warp & 1;
    const int nw = warp >> 1;
    const int g   = lane >> 2;
    const int tig = lane & 3;
    const int brow = blockIdx.y * 128;
    const int bcol = blockIdx.x * 128;
    const int Mtile0 = blockIdx.y * 8;
    const int Ntile0 = blockIdx.x * 16;

    const uint4* __restrict__ A4 = (const uint4*)(MODE ? g_aow : g_xrw);
    const uint4* __restrict__ B4 = (const uint4*)(MODE ? g_woutw : g_wqkvw);

    float acc[4][4][4];
#pragma unroll
    for (int i = 0; i < 4; i++)
#pragma unroll
        for (int j = 0; j < 4; j++)
#pragma unroll
            for (int q = 0; q < 4; q++) acc[i][j][q] = 0.f;

    auto issue = [&](int ic, int s) {
        const int Kc0 = ic * 4;
        const uint32_t As = sb + (uint32_t)s * STAGE_BYTES;
        const uint32_t Bs = As + 16384u;
#pragma unroll
        for (int r = 0; r < 4; r++) {
            int idx = tid + r * 256;
            int ml = idx >> 7, c = (idx >> 5) & 3, l = idx & 31;
            cp16(As + (uint32_t)idx * 16,
                 &A4[(size_t)((Mtile0 + ml) * 64 + Kc0 + c) * 32 + l]);
        }
#pragma unroll
        for (int r = 0; r < 4; r++) {
            int idx = tid + r * 256;
            int nl = idx >> 6, c = (idx >> 4) & 3, l = idx & 15;
            cp16(Bs + (uint32_t)idx * 16,
                 &B4[(size_t)((Ntile0 + nl) * 64 + Kc0 + c) * 16 + l]);
        }
    };

    issue(0, 0); CP_COMMIT();
    issue(1, 1); CP_COMMIT();

    for (int ic = 0; ic < 16; ic++) {
        if (ic + 1 < 16) { CP_WAIT1(); } else { CP_WAIT0(); }
        __syncthreads();

        const int s = ic % 3;
        const uint4* As4 = (const uint4*)(smem + (size_t)s * STAGE_BYTES);
        const uint2* Bs2 = (const uint2*)(smem + (size_t)s * STAGE_BYTES + 16384);

#pragma unroll
        for (int c = 0; c < 4; c++) {
            uint4 af[4];
            uint2 bf[4];
#pragma unroll
            for (int mt = 0; mt < 4; mt++)
                af[mt] = As4[((mw * 4 + mt) * 4 + c) * 32 + lane];
#pragma unroll
            for (int nt = 0; nt < 4; nt++)
                bf[nt] = Bs2[((nw * 4 + nt) * 4 + c) * 32 + lane];
#pragma unroll
            for (int mt = 0; mt < 4; mt++)
#pragma unroll
                for (int nt = 0; nt < 4; nt++)
                    mma_f16(acc[mt][nt], (const uint32_t*)&af[mt], bf[nt].x, bf[nt].y);
        }

        if (ic + 2 < 16) { issue(ic + 2, (ic + 2) % 3); CP_COMMIT(); }
    }

#pragma unroll
    for (int mt = 0; mt < 4; mt++) {
#pragma unroll
        for (int half = 0; half < 2; half++) {
            const int m = brow + mw * 64 + mt * 16 + g + half * 8;
            const int b = m >> 11, t = m & 2047;
#pragma unroll
            for (int nt = 0; nt < 4; nt++) {
                const int col = bcol + nw * 32 + nt * 8 + 2 * tig;
                float vx = acc[mt][nt][half * 2 + 0] + bias[col];
                float vy = acc[mt][nt][half * 2 + 1] + bias[col + 1];
                if (MODE == 0) {
                    const int seg = col >> 10;
                    const int dc  = col & 1023;
                    const int h = dc >> 6, hd = dc & 63;
                    const int bh = b * NHEAD + h;
                    if (seg == 0) {
                        uint32_t w = f2h2(vx * QSCALE, vy * QSCALE);
                        int idx = (((bh * 128 + (t >> 4)) * 4 + (hd >> 4)) * 32
                                   + g * 4 + tig) * 4 + half + 2 * ((hd >> 3) & 1);
                        g_qw[idx] = w;
                    } else if (seg == 1) {
                        uint32_t w = f2h2(vx, vy);
                        int idx = (((bh * 256 + (t >> 3)) * 4 + (hd >> 4)) * 32
                                   + g * 4 + tig) * 2 + ((hd >> 3) & 1);
                        g_kw[idx] = w;
                    } else {
                        g_vw[(size_t)(bh * TLEN + t) * 32 + (hd >> 1)] = f2h2(vx, vy);
                    }
                } else {
                    *(float2*)&out[(size_t)m * DMODEL + col] = make_float2(vx, vy);
                }
            }
        }
    }
}

// ---------------------------------------------------------------------------
// Flash attention, causal, fp16 m16n8k16.
// 4 warps x 32 q-rows (two m16 sub-tiles/warp): each K/V b-frag LDS feeds
// TWO MMAs. 3-stage KV pipeline, one barrier per tile. 128 threads.
// ---------------------------------------------------------------------------
#define STAGE_W 4096                        // 2048 K words + 2048 V words
#define FLASH_SMEM (3 * STAGE_W * 4)        // 49152 B

__global__ __launch_bounds__(128, 2) void flash_attn_f16() {
    extern __shared__ uint32_t smw[];

    const int tid  = threadIdx.x;
    const int lane = tid & 31;
    const int warp = tid >> 5;               // 0..3
    const int g    = lane >> 2;
    const int tig  = lane & 3;
    const int qt = (int)gridDim.x - 1 - (int)blockIdx.x;
    const int bh = blockIdx.y;
    const int q0 = qt * 128;

    // Q a-fragments for both sub-tiles (rows warp*32 .. warp*32+31)
    uint32_t aq[2][4][4];
#pragma unroll
    for (int sub = 0; sub < 2; sub++) {
        const int Mt = qt * 8 + warp * 2 + sub;
#pragma unroll
        for (int ksc = 0; ksc < 4; ksc++) {
            uint4 w = *(const uint4*)&g_qw[(((bh * 128 + Mt) * 4 + ksc) * 32 + lane) * 4];
            aq[sub][ksc][0] = w.x; aq[sub][ksc][1] = w.y;
            aq[sub][ksc][2] = w.z; aq[sub][ksc][3] = w.w;
        }
    }

    const int qrow_w = q0 + warp * 32;        // warp's first q row
    float mx[2][2], lv[2][2];
#pragma unroll
    for (int s2 = 0; s2 < 2; s2++) {
        mx[s2][0] = -1e30f; mx[s2][1] = -1e30f;
        lv[s2][0] = 0.f;    lv[s2][1] = 0.f;
    }
    float o[2][8][4];
#pragma unroll
    for (int sub = 0; sub < 2; sub++)
#pragma unroll
        for (int nt = 0; nt < 8; nt++)
#pragma unroll
            for (int q = 0; q < 4; q++) o[sub][nt][q] = 0.f;

    const uint32_t sb = smem_u32(smw);
    const int njt = 2 * qt + 2;
    const uint32_t ONES = 0x3C003C00u;

    auto issue_kv = [&](int jt, int s) {
        const uint32_t base = sb + (uint32_t)s * STAGE_W * 4;
        const uint4* srcK = (const uint4*)&g_kw[(size_t)(bh * 256 + jt * 8) * 256];
#pragma unroll
        for (int r = 0; r < 4; r++) {
            int idx = tid + r * 128;
            cp16(base + (uint32_t)idx * 16, &srcK[idx]);
        }
        const uint4* srcV = (const uint4*)&g_vt[(size_t)(bh * 32 + jt) * 2048];
#pragma unroll
        for (int r = 0; r < 4; r++) {
            int idx = tid + r * 128;
            cp16(base + 8192u + (uint32_t)idx * 16, &srcV[idx]);
        }
    };

    issue_kv(0, 0); CP_COMMIT();
    issue_kv(1, 1); CP_COMMIT();

    for (int jt = 0; jt < njt; jt++) {
        if (jt + 1 < njt) { CP_WAIT1(); } else { CP_WAIT0(); }
        __syncthreads();

        const int s = jt % 3;
        const int k0 = jt * 64;

        if (qrow_w + 31 >= k0) {
            const uint2* Kb = (const uint2*)(smw + (size_t)s * STAGE_W);
            const uint2* Vb = (const uint2*)(smw + (size_t)s * STAGE_W + 2048);

            // ----- S = Q @ K^T : one b-frag LDS feeds both sub-tiles -----
            float sc[2][8][4];
#pragma unroll
            for (int sub = 0; sub < 2; sub++)
#pragma unroll
                for (int nt = 0; nt < 8; nt++)
#pragma unroll
                    for (int q = 0; q < 4; q++) sc[sub][nt][q] = 0.f;
#pragma unroll
            for (int ksc = 0; ksc < 4; ksc++) {
#pragma unroll
                for (int nt = 0; nt < 8; nt++) {
                    uint2 bb = Kb[(nt * 4 + ksc) * 32 + lane];
                    mma_f16(sc[0][nt], aq[0][ksc], bb.x, bb.y);
                    mma_f16(sc[1][nt], aq[1][ksc], bb.x, bb.y);
                }
            }

            // ----- causal mask per sub-tile -----
#pragma unroll
            for (int sub = 0; sub < 2; sub++) {
                const int base_row = qrow_w + sub * 16;
                if (k0 + 63 > base_row) {
                    const int row0 = base_row + g, row1 = row0 + 8;
#pragma unroll
                    for (int nt = 0; nt < 8; nt++) {
                        const int col = k0 + nt * 8 + 2 * tig;
                        if (col     > row0) sc[sub][nt][0] = -1e30f;
                        if (col + 1 > row0) sc[sub][nt][1] = -1e30f;
                        if (col     > row1) sc[sub][nt][2] = -1e30f;
                        if (col + 1 > row1) sc[sub][nt][3] = -1e30f;
                    }
                }
            }

            // ----- online softmax per sub-tile (log2 domain) -----
            uint32_t pa[2][4][4];
#pragma unroll
            for (int sub = 0; sub < 2; sub++) {
                float rm0 = -1e30f, rm1 = -1e30f;
#pragma unroll
                for (int nt = 0; nt < 8; nt++) {
                    rm0 = fmaxf(rm0, fmaxf(sc[sub][nt][0], sc[sub][nt][1]));
                    rm1 = fmaxf(rm1, fmaxf(sc[sub][nt][2], sc[sub][nt][3]));
                }
                rm0 = fmaxf(rm0, __shfl_xor_sync(0xffffffffu, rm0, 1));
                rm0 = fmaxf(rm0, __shfl_xor_sync(0xffffffffu, rm0, 2));
                rm1 = fmaxf(rm1, __shfl_xor_sync(0xffffffffu, rm1, 1));
                rm1 = fmaxf(rm1, __shfl_xor_sync(0xffffffffu, rm1, 2));
                const float mn0 = fmaxf(mx[sub][0], rm0);
                const float mn1 = fmaxf(mx[sub][1], rm1);
                const float c0 = exp2f(mx[sub][0] - mn0);
                const float c1 = exp2f(mx[sub][1] - mn1);
#pragma unroll
                for (int nt = 0; nt < 8; nt++) {
                    pa[sub][nt >> 1][(nt & 1) * 2 + 0] =
                        h2exp2(sc[sub][nt][0] - mn0, sc[sub][nt][1] - mn0);
                    pa[sub][nt >> 1][(nt & 1) * 2 + 1] =
                        h2exp2(sc[sub][nt][2] - mn1, sc[sub][nt][3] - mn1);
                    o[sub][nt][0] *= c0; o[sub][nt][1] *= c0;
                    o[sub][nt][2] *= c1; o[sub][nt][3] *= c1;
                }
                float rsum[4] = {0.f, 0.f, 0.f, 0.f};
#pragma unroll
                for (int ksc = 0; ksc < 4; ksc++)
                    mma_f16(rsum, pa[sub][ksc], ONES, ONES);
                lv[sub][0] = lv[sub][0] * c0 + rsum[0]; mx[sub][0] = mn0;
                lv[sub][1] = lv[sub][1] * c1 + rsum[2]; mx[sub][1] = mn1;
            }

            // ----- O += P @ V : one b-frag LDS feeds both sub-tiles -----
#pragma unroll
            for (int ksc = 0; ksc < 4; ksc++) {
#pragma unroll
                for (int nt = 0; nt < 8; nt++) {
                    uint2 bb = Vb[(nt * 4 + ksc) * 32 + lane];
                    mma_f16(o[0][nt], pa[0][ksc], bb.x, bb.y);
                    mma_f16(o[1][nt], pa[1][ksc], bb.x, bb.y);
                }
            }
        }

        if (jt + 2 < njt) { issue_kv(jt + 2, (jt + 2) % 3); CP_COMMIT(); }
    }

    // ----- normalize + write g_aow in fp16 A-frag order -----
    const int b = bh >> 4;
    const int h = bh & 15;
#pragma unroll
    for (int sub = 0; sub < 2; sub++) {
        const float inv0 = 1.0f / lv[sub][0], inv1 = 1.0f / lv[sub][1];
        const int MtO = b * 128 + qt * 8 + warp * 2 + sub;
#pragma unroll
        for (int nt = 0; nt < 8; nt++) {
            const int chunk = h * 4 + (nt >> 1);
            const int base = ((MtO * 64 + chunk) * 32 + lane) * 4 + 2 * (nt & 1);
            g_aow[base]     = f2h2(o[sub][nt][0] * inv0, o[sub][nt][1] * inv0);
            g_aow[base + 1] = f2h2(o[sub][nt][2] * inv1, o[sub][nt][3] * inv1);
        }
    }
}

// ---------------------------------------------------------------------------
extern "C" void kernel_launch(void* const* d_in, const int* in_sizes, int n_in,
                              void* d_out, int out_size) {
    const float* x     = (const float*)d_in[0];
    const float* W_qkv = (const float*)d_in[1];
    const float* b_qkv = (const float*)d_in[2];
    const float* W_out = (const float*)d_in[3];
    const float* b_out = (const float*)d_in[4];
    float* out = (float*)d_out;

    cudaFuncSetAttribute(gemm_f16<0>, cudaFuncAttributeMaxDynamicSharedMemorySize, GEMM_SMEM);
    cudaFuncSetAttribute(gemm_f16<1>, cudaFuncAttributeMaxDynamicSharedMemorySize, GEMM_SMEM);
    cudaFuncSetAttribute(flash_attn_f16, cudaFuncAttributeMaxDynamicSharedMemorySize, FLASH_SMEM);

    perm_all<<<1280, 256>>>((const float4*)x, (const float4*)W_qkv, (const float4*)W_out);

    gemm_f16<0><<<dim3(3 * DMODEL / 128, MTOT / 128), 256, GEMM_SMEM>>>(b_qkv, nullptr, 3 * DMODEL);
    perm_v_f16<<<8192, 256>>>();
    flash_attn_f16<<<dim3(TLEN / 128, BATCH * NHEAD), 128, FLASH_SMEM>>>();
    gemm_f16<1><<<dim3(DMODEL / 128, MTOT / 128), 256, GEMM_SMEM>>>(b_out, out, DMODEL);
}

// round 15
// speedup vs baseline: 2.6734x; 1.0305x over previous
#include <cuda_runtime.h>
#include <cuda_fp16.h>
#include <cstdint>
#include <math.h>

// Problem constants
#define DMODEL 1024
#define TLEN   2048
#define BATCH  4
#define NHEAD  16
#define HDIM   64
#define MTOT   (BATCH*TLEN)      // 8192

#define QSCALE (0.125f * 1.44269504089f)   // 1/sqrt(64) * log2(e), folded into q

// ---------------------------------------------------------------------------
// Global scratch, all fp16 stored as uint32 half2-words.
// ---------------------------------------------------------------------------
__device__ uint32_t g_qw  [4194304];   // flash A-frag order
__device__ uint32_t g_kw  [4194304];   // flash B-frag order
__device__ uint32_t g_vt  [4194304];   // flash B-frag order (per 64-row window)
__device__ uint32_t g_aow [4194304];   // GEMM A-frag order
__device__ uint32_t g_xrw [4194304];   // GEMM A-frag order
__device__ uint32_t g_wqkvw[1572864];  // GEMM B-frag order
__device__ uint32_t g_woutw[524288];

// ---------------------------------------------------------------------------
// Helpers
// ---------------------------------------------------------------------------
__device__ __forceinline__ uint32_t smem_u32(const void* p) {
    uint32_t a;
    asm("{ .reg .u64 t; cvta.to.shared.u64 t, %1; cvt.u32.u64 %0, t; }"
        : "=r"(a) : "l"(p));
    return a;
}

__device__ __forceinline__ uint32_t f2h2(float lo, float hi) {
    __half2 h = __floats2half2_rn(lo, hi);
    return *reinterpret_cast<uint32_t*>(&h);
}

__device__ __forceinline__ uint32_t h2exp2(float a, float b) {
    uint32_t h = f2h2(a, b), r;
    asm("ex2.approx.f16x2 %0, %1;" : "=r"(r) : "r"(h));
    return r;
}

__device__ __forceinline__ void cp16(uint32_t dst, const void* src) {
    asm volatile("cp.async.cg.shared.global [%0], [%1], 16;"
                 :: "r"(dst), "l"(src) : "memory");
}
#define CP_COMMIT() asm volatile("cp.async.commit_group;" ::: "memory")
#define CP_WAIT1()  asm volatile("cp.async.wait_group 1;" ::: "memory")
#define CP_WAIT0()  asm volatile("cp.async.wait_group 0;" ::: "memory")

// m16n8k16 row.col fp16 MMA, fp32 accumulate
__device__ __forceinline__ void mma_f16(float* c, const uint32_t* a,
                                        uint32_t b0, uint32_t b1) {
    asm volatile(
        "mma.sync.aligned.m16n8k16.row.col.f32.f16.f16.f32 "
        "{%0,%1,%2,%3}, {%4,%5,%6,%7}, {%8,%9}, {%0,%1,%2,%3};"
        : "+f"(c[0]), "+f"(c[1]), "+f"(c[2]), "+f"(c[3])
        : "r"(a[0]), "r"(a[1]), "r"(a[2]), "r"(a[3]), "r"(b0), "r"(b1));
}

// ---------------------------------------------------------------------------
// Fused prepass: x -> A-frag fp16, W_qkv/W_out -> B-frag fp16.
// ---------------------------------------------------------------------------
__device__ __forceinline__ void perm_a_body(const float4* __restrict__ src,
                                            uint4* __restrict__ dst, int t) {
    int g = t & 7, c = (t >> 3) & 63, Mtile = t >> 9;
    int m0 = Mtile * 16 + g;
    float f0[16], f1[16];
#pragma unroll
    for (int j = 0; j < 4; j++) {
        float4 v0 = src[m0 * 256 + c * 4 + j];
        float4 v1 = src[(m0 + 8) * 256 + c * 4 + j];
        f0[4*j+0]=v0.x; f0[4*j+1]=v0.y; f0[4*j+2]=v0.z; f0[4*j+3]=v0.w;
        f1[4*j+0]=v1.x; f1[4*j+1]=v1.y; f1[4*j+2]=v1.z; f1[4*j+3]=v1.w;
    }
    int base = (Mtile * 64 + c) * 32 + g * 4;
#pragma unroll
    for (int tig = 0; tig < 4; tig++) {
        uint4 w;
        w.x = f2h2(f0[2*tig],   f0[2*tig+1]);
        w.y = f2h2(f1[2*tig],   f1[2*tig+1]);
        w.z = f2h2(f0[2*tig+8], f0[2*tig+9]);
        w.w = f2h2(f1[2*tig+8], f1[2*tig+9]);
        dst[base + tig] = w;
    }
}

__device__ __forceinline__ void perm_b_body(const float4* __restrict__ src,
                                            uint32_t* __restrict__ dst, int N, int t) {
    int Kblk = t & 127, Ntile = t >> 7;
    float w[8][8];
#pragma unroll
    for (int kk = 0; kk < 8; kk++) {
        int k = Kblk * 8 + kk;
        float4 wa = src[(size_t)k * (N / 4) + Ntile * 2];
        float4 wb = src[(size_t)k * (N / 4) + Ntile * 2 + 1];
        w[kk][0]=wa.x; w[kk][1]=wa.y; w[kk][2]=wa.z; w[kk][3]=wa.w;
        w[kk][4]=wb.x; w[kk][5]=wb.y; w[kk][6]=wb.z; w[kk][7]=wb.w;
    }
    int c = Kblk >> 1, kb = Kblk & 1;
    int base = (Ntile * 64 + c) * 64 + kb;
#pragma unroll
    for (int l = 0; l < 32; l++) {
        int g = l >> 2, tig = l & 3;
        dst[base + l * 2] = f2h2(w[2*tig][g], w[2*tig+1][g]);
    }
}

__global__ __launch_bounds__(256) void perm_all(const float4* __restrict__ x,
                                                const float4* __restrict__ wqkv,
                                                const float4* __restrict__ wout) {
    int b = blockIdx.x;
    if (b < 1024) {
        perm_a_body(x, (uint4*)g_xrw, b * 256 + threadIdx.x);
    } else if (b < 1216) {
        perm_b_body(wqkv, g_wqkvw, 3 * DMODEL, (b - 1024) * 256 + threadIdx.x);
    } else {
        perm_b_body(wout, g_woutw, DMODEL, (b - 1216) * 256 + threadIdx.x);
    }
}

// ---------------------------------------------------------------------------
// fp16 m16n8k16 GEMM, 3-stage cp.async pipeline. MODE 0 epilogue scatters
// q (flash A-frag), k (flash B-frag), and V DIRECTLY in flash B-frag order
// (fused transpose via warp shuffles — no perm_v pass, no g_vw).
// ---------------------------------------------------------------------------
#define STAGE_BYTES 32768
#define GEMM_SMEM   (3 * STAGE_BYTES)      // 98304

template<int MODE>
__global__ __launch_bounds__(256) void gemm_f16(const float* __restrict__ bias,
                                                float* __restrict__ out, int Ntot) {
    extern __shared__ char smem[];
    const uint32_t sb = smem_u32(smem);
    const int tid  = threadIdx.x;
    const int lane = tid & 31;
    const int warp = tid >> 5;
    const int mw = warp & 1;
    const int nw = warp >> 1;
    const int g   = lane >> 2;
    const int tig = lane & 3;
    const int brow = blockIdx.y * 128;
    const int bcol = blockIdx.x * 128;
    const int Mtile0 = blockIdx.y * 8;
    const int Ntile0 = blockIdx.x * 16;

    const uint4* __restrict__ A4 = (const uint4*)(MODE ? g_aow : g_xrw);
    const uint4* __restrict__ B4 = (const uint4*)(MODE ? g_woutw : g_wqkvw);

    float acc[4][4][4];
#pragma unroll
    for (int i = 0; i < 4; i++)
#pragma unroll
        for (int j = 0; j < 4; j++)
#pragma unroll
            for (int q = 0; q < 4; q++) acc[i][j][q] = 0.f;

    auto issue = [&](int ic, int s) {
        const int Kc0 = ic * 4;
        const uint32_t As = sb + (uint32_t)s * STAGE_BYTES;
        const uint32_t Bs = As + 16384u;
#pragma unroll
        for (int r = 0; r < 4; r++) {
            int idx = tid + r * 256;
            int ml = idx >> 7, c = (idx >> 5) & 3, l = idx & 31;
            cp16(As + (uint32_t)idx * 16,
                 &A4[(size_t)((Mtile0 + ml) * 64 + Kc0 + c) * 32 + l]);
        }
#pragma unroll
        for (int r = 0; r < 4; r++) {
            int idx = tid + r * 256;
            int nl = idx >> 6, c = (idx >> 4) & 3, l = idx & 15;
            cp16(Bs + (uint32_t)idx * 16,
                 &B4[(size_t)((Ntile0 + nl) * 64 + Kc0 + c) * 16 + l]);
        }
    };

    issue(0, 0); CP_COMMIT();
    issue(1, 1); CP_COMMIT();

    for (int ic = 0; ic < 16; ic++) {
        if (ic + 1 < 16) { CP_WAIT1(); } else { CP_WAIT0(); }
        __syncthreads();

        const int s = ic % 3;
        const uint4* As4 = (const uint4*)(smem + (size_t)s * STAGE_BYTES);
        const uint2* Bs2 = (const uint2*)(smem + (size_t)s * STAGE_BYTES + 16384);

#pragma unroll
        for (int c = 0; c < 4; c++) {
            uint4 af[4];
            uint2 bf[4];
#pragma unroll
            for (int mt = 0; mt < 4; mt++)
                af[mt] = As4[((mw * 4 + mt) * 4 + c) * 32 + lane];
#pragma unroll
            for (int nt = 0; nt < 4; nt++)
                bf[nt] = Bs2[((nw * 4 + nt) * 4 + c) * 32 + lane];
#pragma unroll
            for (int mt = 0; mt < 4; mt++)
#pragma unroll
                for (int nt = 0; nt < 4; nt++)
                    mma_f16(acc[mt][nt], (const uint32_t*)&af[mt], bf[nt].x, bf[nt].y);
        }

        if (ic + 2 < 16) { issue(ic + 2, (ic + 2) % 3); CP_COMMIT(); }
    }

    // ----- epilogue -----
#pragma unroll
    for (int mt = 0; mt < 4; mt++) {
        // rows for half 0/1 of this mt
        const int m0r = brow + mw * 64 + mt * 16 + g;        // half 0 (t mod 16 = g)
        const int b0 = m0r >> 11, t0 = m0r & 2047;
#pragma unroll
        for (int nt = 0; nt < 4; nt++) {
            const int col = bcol + nw * 32 + nt * 8 + 2 * tig;
            float vx0 = acc[mt][nt][0] + bias[col];
            float vy0 = acc[mt][nt][1] + bias[col + 1];
            float vx1 = acc[mt][nt][2] + bias[col];
            float vy1 = acc[mt][nt][3] + bias[col + 1];
            if (MODE == 1) {
                *(float2*)&out[(size_t)m0r * DMODEL + col] = make_float2(vx0, vy0);
                *(float2*)&out[(size_t)(m0r + 8) * DMODEL + col] = make_float2(vx1, vy1);
                continue;
            }
            const int seg = col >> 10;
            const int dc  = col & 1023;
            const int h = dc >> 6, hd = dc & 63;
            const int bh = b0 * NHEAD + h;
            if (seg == 0) {          // q: flash A-frag order, pre-scaled
                uint32_t w0 = f2h2(vx0 * QSCALE, vy0 * QSCALE);
                uint32_t w1 = f2h2(vx1 * QSCALE, vy1 * QSCALE);
                int ibase = (((bh * 128 + (t0 >> 4)) * 4 + (hd >> 4)) * 32
                             + g * 4 + tig) * 4 + 2 * ((hd >> 3) & 1);
                g_qw[ibase]     = w0;
                g_qw[ibase + 1] = w1;
            } else if (seg == 1) {   // k: flash B-frag order
                uint32_t w0 = f2h2(vx0, vy0);
                uint32_t w1 = f2h2(vx1, vy1);
                int i0 = (((bh * 256 + (t0 >> 3)) * 4 + (hd >> 4)) * 32
                          + g * 4 + tig) * 2 + ((hd >> 3) & 1);
                int i1 = (((bh * 256 + ((t0 + 8) >> 3)) * 4 + (hd >> 4)) * 32
                          + g * 4 + tig) * 2 + ((hd >> 3) & 1);
                g_kw[i0] = w0;
                g_kw[i1] = w1;
            } else {                 // v: DIRECT flash B-frag order via shuffles
                // pairs (t, t+1): peer = lane+4 (g+1, same tig)
                float px0 = __shfl_down_sync(0xffffffffu, vx0, 4);
                float py0 = __shfl_down_sync(0xffffffffu, vy0, 4);
                float px1 = __shfl_down_sync(0xffffffffu, vx1, 4);
                float py1 = __shfl_down_sync(0xffffffffu, vy1, 4);
                if ((g & 1) == 0) {
                    const int win = t0 >> 6, ksc = (t0 >> 4) & 3;
                    const int tv = g >> 1;     // t0 mod 16 == g (even)
                    // n = col: word b0 = (V[t0],V[t0+1]), b1 = (V[t0+8],V[t0+9])
                    uint2 wa, wb;
                    wa.x = f2h2(vx0, px0); wa.y = f2h2(vx1, px1);
                    wb.x = f2h2(vy0, py0); wb.y = f2h2(vy1, py1);
                    uint2* dst = (uint2*)g_vt;
                    const int na = hd, nb = hd + 1;
                    dst[(size_t)(bh * 32 + win) * 1024
                        + ((na >> 3) * 4 + ksc) * 32 + (na & 7) * 4 + tv] = wa;
                    dst[(size_t)(bh * 32 + win) * 1024
                        + ((nb >> 3) * 4 + ksc) * 32 + (nb & 7) * 4 + tv] = wb;
                }
            }
        }
    }
}

// ---------------------------------------------------------------------------
// Flash attention, causal, fp16 m16n8k16 (unchanged from R14).
// 4 warps x 32 q-rows; each K/V b-frag LDS feeds two MMAs. 3-stage pipeline.
// ---------------------------------------------------------------------------
#define STAGE_W 4096                        // 2048 K words + 2048 V words
#define FLASH_SMEM (3 * STAGE_W * 4)        // 49152 B

__global__ __launch_bounds__(128, 2) void flash_attn_f16() {
    extern __shared__ uint32_t smw[];

    const int tid  = threadIdx.x;
    const int lane = tid & 31;
    const int warp = tid >> 5;               // 0..3
    const int g    = lane >> 2;
    const int tig  = lane & 3;
    const int qt = (int)gridDim.x - 1 - (int)blockIdx.x;
    const int bh = blockIdx.y;
    const int q0 = qt * 128;

    uint32_t aq[2][4][4];
#pragma unroll
    for (int sub = 0; sub < 2; sub++) {
        const int Mt = qt * 8 + warp * 2 + sub;
#pragma unroll
        for (int ksc = 0; ksc < 4; ksc++) {
            uint4 w = *(const uint4*)&g_qw[(((bh * 128 + Mt) * 4 + ksc) * 32 + lane) * 4];
            aq[sub][ksc][0] = w.x; aq[sub][ksc][1] = w.y;
            aq[sub][ksc][2] = w.z; aq[sub][ksc][3] = w.w;
        }
    }

    const int qrow_w = q0 + warp * 32;
    float mx[2][2], lv[2][2];
#pragma unroll
    for (int s2 = 0; s2 < 2; s2++) {
        mx[s2][0] = -1e30f; mx[s2][1] = -1e30f;
        lv[s2][0] = 0.f;    lv[s2][1] = 0.f;
    }
    float o[2][8][4];
#pragma unroll
    for (int sub = 0; sub < 2; sub++)
#pragma unroll
        for (int nt = 0; nt < 8; nt++)
#pragma unroll
            for (int q = 0; q < 4; q++) o[sub][nt][q] = 0.f;

    const uint32_t sb = smem_u32(smw);
    const int njt = 2 * qt + 2;
    const uint32_t ONES = 0x3C003C00u;

    auto issue_kv = [&](int jt, int s) {
        const uint32_t base = sb + (uint32_t)s * STAGE_W * 4;
        const uint4* srcK = (const uint4*)&g_kw[(size_t)(bh * 256 + jt * 8) * 256];
#pragma unroll
        for (int r = 0; r < 4; r++) {
            int idx = tid + r * 128;
            cp16(base + (uint32_t)idx * 16, &srcK[idx]);
        }
        const uint4* srcV = (const uint4*)&g_vt[(size_t)(bh * 32 + jt) * 2048];
#pragma unroll
        for (int r = 0; r < 4; r++) {
            int idx = tid + r * 128;
            cp16(base + 8192u + (uint32_t)idx * 16, &srcV[idx]);
        }
    };

    issue_kv(0, 0); CP_COMMIT();
    issue_kv(1, 1); CP_COMMIT();

    for (int jt = 0; jt < njt; jt++) {
        if (jt + 1 < njt) { CP_WAIT1(); } else { CP_WAIT0(); }
        __syncthreads();

        const int s = jt % 3;
        const int k0 = jt * 64;

        if (qrow_w + 31 >= k0) {
            const uint2* Kb = (const uint2*)(smw + (size_t)s * STAGE_W);
            const uint2* Vb = (const uint2*)(smw + (size_t)s * STAGE_W + 2048);

            float sc[2][8][4];
#pragma unroll
            for (int sub = 0; sub < 2; sub++)
#pragma unroll
                for (int nt = 0; nt < 8; nt++)
#pragma unroll
                    for (int q = 0; q < 4; q++) sc[sub][nt][q] = 0.f;
#pragma unroll
            for (int ksc = 0; ksc < 4; ksc++) {
#pragma unroll
                for (int nt = 0; nt < 8; nt++) {
                    uint2 bb = Kb[(nt * 4 + ksc) * 32 + lane];
                    mma_f16(sc[0][nt], aq[0][ksc], bb.x, bb.y);
                    mma_f16(sc[1][nt], aq[1][ksc], bb.x, bb.y);
                }
            }

#pragma unroll
            for (int sub = 0; sub < 2; sub++) {
                const int base_row = qrow_w + sub * 16;
                if (k0 + 63 > base_row) {
                    const int row0 = base_row + g, row1 = row0 + 8;
#pragma unroll
                    for (int nt = 0; nt < 8; nt++) {
                        const int col = k0 + nt * 8 + 2 * tig;
                        if (col     > row0) sc[sub][nt][0] = -1e30f;
                        if (col + 1 > row0) sc[sub][nt][1] = -1e30f;
                        if (col     > row1) sc[sub][nt][2] = -1e30f;
                        if (col + 1 > row1) sc[sub][nt][3] = -1e30f;
                    }
                }
            }

            uint32_t pa[2][4][4];
#pragma unroll
            for (int sub = 0; sub < 2; sub++) {
                float rm0 = -1e30f, rm1 = -1e30f;
#pragma unroll
                for (int nt = 0; nt < 8; nt++) {
                    rm0 = fmaxf(rm0, fmaxf(sc[sub][nt][0], sc[sub][nt][1]));
                    rm1 = fmaxf(rm1, fmaxf(sc[sub][nt][2], sc[sub][nt][3]));
                }
                rm0 = fmaxf(rm0, __shfl_xor_sync(0xffffffffu, rm0, 1));
                rm0 = fmaxf(rm0, __shfl_xor_sync(0xffffffffu, rm0, 2));
                rm1 = fmaxf(rm1, __shfl_xor_sync(0xffffffffu, rm1, 1));
                rm1 = fmaxf(rm1, __shfl_xor_sync(0xffffffffu, rm1, 2));
                const float mn0 = fmaxf(mx[sub][0], rm0);
                const float mn1 = fmaxf(mx[sub][1], rm1);
                const float c0 = exp2f(mx[sub][0] - mn0);
                const float c1 = exp2f(mx[sub][1] - mn1);
#pragma unroll
                for (int nt = 0; nt < 8; nt++) {
                    pa[sub][nt >> 1][(nt & 1) * 2 + 0] =
                        h2exp2(sc[sub][nt][0] - mn0, sc[sub][nt][1] - mn0);
                    pa[sub][nt >> 1][(nt & 1) * 2 + 1] =
                        h2exp2(sc[sub][nt][2] - mn1, sc[sub][nt][3] - mn1);
                    o[sub][nt][0] *= c0; o[sub][nt][1] *= c0;
                    o[sub][nt][2] *= c1; o[sub][nt][3] *= c1;
                }
                float rsum[4] = {0.f, 0.f, 0.f, 0.f};
#pragma unroll
                for (int ksc = 0; ksc < 4; ksc++)
                    mma_f16(rsum, pa[sub][ksc], ONES, ONES);
                lv[sub][0] = lv[sub][0] * c0 + rsum[0]; mx[sub][0] = mn0;
                lv[sub][1] = lv[sub][1] * c1 + rsum[2]; mx[sub][1] = mn1;
            }

#pragma unroll
            for (int ksc = 0; ksc < 4; ksc++) {
#pragma unroll
                for (int nt = 0; nt < 8; nt++) {
                    uint2 bb = Vb[(nt * 4 + ksc) * 32 + lane];
                    mma_f16(o[0][nt], pa[0][ksc], bb.x, bb.y);
                    mma_f16(o[1][nt], pa[1][ksc], bb.x, bb.y);
                }
            }
        }

        if (jt + 2 < njt) { issue_kv(jt + 2, (jt + 2) % 3); CP_COMMIT(); }
    }

    const int b = bh >> 4;
    const int h = bh & 15;
#pragma unroll
    for (int sub = 0; sub < 2; sub++) {
        const float inv0 = 1.0f / lv[sub][0], inv1 = 1.0f / lv[sub][1];
        const int MtO = b * 128 + qt * 8 + warp * 2 + sub;
#pragma unroll
        for (int nt = 0; nt < 8; nt++) {
            const int chunk = h * 4 + (nt >> 1);
            const int base = ((MtO * 64 + chunk) * 32 + lane) * 4 + 2 * (nt & 1);
            g_aow[base]     = f2h2(o[sub][nt][0] * inv0, o[sub][nt][1] * inv0);
            g_aow[base + 1] = f2h2(o[sub][nt][2] * inv1, o[sub][nt][3] * inv1);
        }
    }
}

// ---------------------------------------------------------------------------
extern "C" void kernel_launch(void* const* d_in, const int* in_sizes, int n_in,
                              void* d_out, int out_size) {
    const float* x     = (const float*)d_in[0];
    const float* W_qkv = (const float*)d_in[1];
    const float* b_qkv = (const float*)d_in[2];
    const float* W_out = (const float*)d_in[3];
    const float* b_out = (const float*)d_in[4];
    float* out = (float*)d_out;

    cudaFuncSetAttribute(gemm_f16<0>, cudaFuncAttributeMaxDynamicSharedMemorySize, GEMM_SMEM);
    cudaFuncSetAttribute(gemm_f16<1>, cudaFuncAttributeMaxDynamicSharedMemorySize, GEMM_SMEM);
    cudaFuncSetAttribute(flash_attn_f16, cudaFuncAttributeMaxDynamicSharedMemorySize, FLASH_SMEM);

    perm_all<<<1280, 256>>>((const float4*)x, (const float4*)W_qkv, (const float4*)W_out);

    gemm_f16<0><<<dim3(3 * DMODEL / 128, MTOT / 128), 256, GEMM_SMEM>>>(b_qkv, nullptr, 3 * DMODEL);
    flash_attn_f16<<<dim3(TLEN / 128, BATCH * NHEAD), 128, FLASH_SMEM>>>();
    gemm_f16<1><<<dim3(DMODEL / 128, MTOT / 128), 256, GEMM_SMEM>>>(b_out, out, DMODEL);
}